// round 3
// baseline (speedup 1.0000x reference)
#include <cuda_runtime.h>
#include <mma.h>
#include <cstdint>
#include <math.h>

using namespace nvcuda;

// Problem constants (fixed shapes from setup_inputs)
#define BB   16
#define DIM  384
#define NHKD 256
#define DHV  1024
#define NTOK 1024
#define NH   8
#define KDIM 32
#define DV   128

// Scratch (device globals — no allocations allowed)
__device__ float g_q [BB * NHKD * NTOK];
__device__ float g_k [BB * NHKD * NTOK];
__device__ float g_v [BB * DHV  * NTOK];
__device__ float g_xx[BB * DHV  * NTOK];

// tf32 round-to-nearest (RNA); result is exactly representable in tf32
__device__ __forceinline__ float tf32r(float x) {
    uint32_t u;
    asm("cvt.rna.tf32.f32 %0, %1;" : "=r"(u) : "f"(x));
    return __uint_as_float(u);
}

typedef wmma::fragment<wmma::matrix_a, 16, 16, 8, wmma::precision::tf32, wmma::row_major> FragAR;
typedef wmma::fragment<wmma::matrix_a, 16, 16, 8, wmma::precision::tf32, wmma::col_major> FragAC;
typedef wmma::fragment<wmma::matrix_b, 16, 16, 8, wmma::precision::tf32, wmma::row_major> FragBR;
typedef wmma::fragment<wmma::matrix_b, 16, 16, 8, wmma::precision::tf32, wmma::col_major> FragBC;
typedef wmma::fragment<wmma::accumulator, 16, 16, 8, float> FragC;

// Split a raw-f32 fragment into hi/lo tf32 fragments (in registers)
template <typename F>
__device__ __forceinline__ void split_frag(const F& raw, F& hi, F& lo) {
#pragma unroll
    for (int i = 0; i < raw.num_elements; i++) {
        float h = tf32r(raw.x[i]);
        hi.x[i] = h;
        lo.x[i] = tf32r(raw.x[i] - h);
    }
}

// 3xTF32 mma: C += Ahi*Bhi + Ahi*Blo + Alo*Bhi
template <typename FA, typename FB>
__device__ __forceinline__ void mma3(FragC& c, const FA& ah, const FA& al,
                                     const FB& bh, const FB& bl) {
    wmma::mma_sync(c, ah, bh, c);
    wmma::mma_sync(c, ah, bl, c);
    wmma::mma_sync(c, al, bh, c);
}

// ---------------------------------------------------------------------------
// GEMM + BN (wmma tf32, 3x split):
//   Y[b][m][n] = (sum_k W[m][k] * X[b][k][n]) * s[m] + t[m]
// Block: 256 thr (8 warps), tile 128(M) x 64(N), K-chunks of 32.
// Warp grid 4(M) x 2(N); warp tile 32x32 = 2x2 wmma(16x16x8) frags.
// smem: Ws[128][36] + Xs[32][68]; epilogue reuses as Out[128][68].
// ---------------------------------------------------------------------------
#define GEMM_SMEM_F32 (128 * 68)   // 8704 floats = 34816 B (covers stage too)

__global__ __launch_bounds__(256) void gemm_bn_tc(
    const float* __restrict__ W, const float* __restrict__ bn,
    const float* __restrict__ X, float* __restrict__ Y,
    int M, int K, long xStride, long yStride)
{
    extern __shared__ float sm[];
    float* Ws = sm;            // [128][36]
    float* Xs = sm + 128 * 36; // [32][68]

    const int t = threadIdx.x;
    const int w = t >> 5;
    const int wm = (w >> 1) * 32;   // warp m offset (0,32,64,96)
    const int wn = (w & 1) * 32;    // warp n offset (0,32)
    const int n0 = blockIdx.x * 64;
    const int m0 = blockIdx.y * 128;
    const float* Xb = X + (long)blockIdx.z * xStride;
    float*       Yb = Y + (long)blockIdx.z * yStride;

    FragC c[2][2];
#pragma unroll
    for (int i = 0; i < 2; i++)
#pragma unroll
        for (int j = 0; j < 2; j++) wmma::fill_fragment(c[i][j], 0.0f);

    const int nc = K >> 5;
    for (int kc = 0; kc < nc; kc++) {
        // gmem -> regs
        float4 wv[4], xv[2];
#pragma unroll
        for (int i = 0; i < 4; i++) {
            int idx = t + i * 256;
            int m = idx >> 3, kq = idx & 7;
            wv[i] = *(const float4*)(W + (long)(m0 + m) * K + kc * 32 + kq * 4);
        }
#pragma unroll
        for (int i = 0; i < 2; i++) {
            int idx = t + i * 256;
            int k = idx >> 4, nq = idx & 15;
            xv[i] = *(const float4*)(Xb + (long)(kc * 32 + k) * NTOK + n0 + nq * 4);
        }
        __syncthreads();   // prev iter's fragment loads complete
#pragma unroll
        for (int i = 0; i < 4; i++) {
            int idx = t + i * 256;
            int m = idx >> 3, kq = idx & 7;
            *(float4*)(Ws + m * 36 + kq * 4) = wv[i];
        }
#pragma unroll
        for (int i = 0; i < 2; i++) {
            int idx = t + i * 256;
            int k = idx >> 4, nq = idx & 15;
            *(float4*)(Xs + k * 68 + nq * 4) = xv[i];
        }
        __syncthreads();

#pragma unroll
        for (int ks = 0; ks < 4; ks++) {
            FragAR ar, ah[2], al[2];
            FragBR br, bh[2], bl[2];
#pragma unroll
            for (int i = 0; i < 2; i++) {
                wmma::load_matrix_sync(ar, Ws + (wm + 16 * i) * 36 + ks * 8, 36);
                split_frag(ar, ah[i], al[i]);
            }
#pragma unroll
            for (int j = 0; j < 2; j++) {
                wmma::load_matrix_sync(br, Xs + (ks * 8) * 68 + wn + 16 * j, 68);
                split_frag(br, bh[j], bl[j]);
            }
#pragma unroll
            for (int i = 0; i < 2; i++)
#pragma unroll
                for (int j = 0; j < 2; j++)
                    mma3(c[i][j], ah[i], al[i], bh[j], bl[j]);
        }
    }

    // Epilogue: frags -> smem, BN, store
    __syncthreads();
    float* Out = sm;   // [128][68]
#pragma unroll
    for (int i = 0; i < 2; i++)
#pragma unroll
        for (int j = 0; j < 2; j++)
            wmma::store_matrix_sync(Out + (wm + 16 * i) * 68 + wn + 16 * j,
                                    c[i][j], 68, wmma::mem_row_major);
    __syncthreads();
    {
        int row = t >> 1, half = t & 1;
        int m = m0 + row;
        float g  = bn[m];
        float be = bn[M + m];
        float mu = bn[2 * M + m];
        float va = bn[3 * M + m];
        float sc = g * rsqrtf(va + 1e-5f);
        float tt = be - mu * sc;
        const float* src = Out + row * 68 + half * 32;
        float* dst = Yb + (long)m * NTOK + n0 + half * 32;
#pragma unroll
        for (int q = 0; q < 8; q++) {
            float4 v = *(const float4*)(src + q * 4);
            v.x = v.x * sc + tt; v.y = v.y * sc + tt;
            v.z = v.z * sc + tt; v.w = v.w * sc + tt;
            *(float4*)(dst + q * 4) = v;
        }
    }
}

// ---------------------------------------------------------------------------
// Attention (wmma tf32 3x): one CTA per (b, h, 32-query tile), 128 threads.
//   Phase 1: S[32][1024] = (Qt K) * sqrt(32)  (full row block in smem)
//   Phase 2: exact softmax (max / exp / sum / scale by 1/l)
//   Phase 3: O[32][128] = P V^T, V tiles staged through smem
// smem (f32): S[32][1032] | Qs[32][36] | Ks[32][68] | Vs[128][36]
// ---------------------------------------------------------------------------
#define ATTN_SMEM_F32 (32 * 1032 + 32 * 36 + 32 * 68 + 128 * 36)  // 40960

__global__ __launch_bounds__(128) void attn_tc()
{
    extern __shared__ float sm[];
    float* Ss = sm;                       // [32][1032]
    float* Qs = Ss + 32 * 1032;           // [32 kd][36] (tok-major rows of kd)
    float* Ks = Qs + 32 * 36;             // [32 kd][68]
    float* Vs = Ks + 32 * 68;             // [128 d][36]

    const int t = threadIdx.x;
    const int w = t >> 5;
    const int q0 = blockIdx.x * 32;
    const int bh = blockIdx.y;
    const int b = bh >> 3, h = bh & 7;

    const float* qp = g_q + (long)b * NHKD * NTOK + (long)h * KDIM * NTOK;
    const float* kp = g_k + (long)b * NHKD * NTOK + (long)h * KDIM * NTOK;
    const float* vp = g_v + (long)b * DHV  * NTOK + (long)h * DV   * NTOK;

    const float scale = 5.656854249492380f;  // sqrt(32)

    // Load Q tile [kd=32][tok=32] * scale  (1024 f32, 2 float4/thread)
#pragma unroll
    for (int i = 0; i < 2; i++) {
        int idx = t + i * 128;
        int kd = idx >> 3, c4 = (idx & 7) * 4;
        float4 v = *(const float4*)(qp + (long)kd * NTOK + q0 + c4);
        float* dst = Qs + kd * 36 + c4;
        dst[0] = v.x * scale; dst[1] = v.y * scale;
        dst[2] = v.z * scale; dst[3] = v.w * scale;
    }

    // ---- Phase 1: S = Qt K (3xTF32). Warp w covers n-cols [w*16, w*16+16).
    for (int jt = 0; jt < 16; jt++) {
        // Load K tile [32][64]  (2048 f32, 4 float4/thread)
        __syncthreads();   // prev jt fragment loads complete
#pragma unroll
        for (int i = 0; i < 4; i++) {
            int idx = t + i * 128;
            int kd = idx >> 4, c4 = (idx & 15) * 4;
            *(float4*)(Ks + kd * 68 + c4) =
                *(const float4*)(kp + (long)kd * NTOK + jt * 64 + c4);
        }
        __syncthreads();

        FragC s2[2];
        wmma::fill_fragment(s2[0], 0.0f);
        wmma::fill_fragment(s2[1], 0.0f);
#pragma unroll
        for (int ks = 0; ks < 4; ks++) {
            FragAC ar, ah[2], al[2];
            FragBR br, bh, bl;
#pragma unroll
            for (int i = 0; i < 2; i++) {
                // A = Qt (col_major): elem (m=tok, k=kd) at Qs[kd][tok]
                wmma::load_matrix_sync(ar, Qs + (ks * 8) * 36 + 16 * i, 36);
                split_frag(ar, ah[i], al[i]);
            }
            wmma::load_matrix_sync(br, Ks + (ks * 8) * 68 + w * 16, 68);
            split_frag(br, bh, bl);
#pragma unroll
            for (int i = 0; i < 2; i++)
                mma3(s2[i], ah[i], al[i], bh, bl);
        }
#pragma unroll
        for (int i = 0; i < 2; i++)
            wmma::store_matrix_sync(Ss + (16 * i) * 1032 + jt * 64 + w * 16,
                                    s2[i], 1032, wmma::mem_row_major);
    }

    // ---- Phase 2: exact softmax per row (4 threads per row)
    __syncthreads();
    {
        int row = t >> 2, g = t & 3;
        float* Sr = Ss + row * 1032;
        float mx = -1e30f;
        for (int j = g; j < 1024; j += 4) mx = fmaxf(mx, Sr[j]);
        mx = fmaxf(mx, __shfl_xor_sync(0xffffffffu, mx, 1));
        mx = fmaxf(mx, __shfl_xor_sync(0xffffffffu, mx, 2));
        float sum = 0.f;
        for (int j = g; j < 1024; j += 4) {
            float e = __expf(Sr[j] - mx);
            Sr[j] = e;
            sum += e;
        }
        sum += __shfl_xor_sync(0xffffffffu, sum, 1);
        sum += __shfl_xor_sync(0xffffffffu, sum, 2);
        float inv = 1.0f / sum;
        for (int j = g; j < 1024; j += 4) Sr[j] *= inv;
    }

    // ---- Phase 3: O = P V^T (3xTF32). Warp w covers d-cols [w*32, w*32+32).
    FragC oc[2][2];
#pragma unroll
    for (int i = 0; i < 2; i++)
#pragma unroll
        for (int j = 0; j < 2; j++) wmma::fill_fragment(oc[i][j], 0.0f);

    for (int vt = 0; vt < 32; vt++) {
        __syncthreads();   // prev vt fragment loads complete (or softmax done)
        // Stage V tile: Vs[d][kt] for kt in [vt*32, vt*32+32)  (8 float4/thread)
        {
            const float* vsrc = vp + (long)t * NTOK + vt * 32;
            float* vdst = Vs + t * 36;
#pragma unroll
            for (int q = 0; q < 8; q++)
                *(float4*)(vdst + q * 4) = *(const float4*)(vsrc + q * 4);
        }
        __syncthreads();

#pragma unroll
        for (int ks = 0; ks < 4; ks++) {
            FragAR ar, ah[2], al[2];
            FragBC br, bh[2], bl[2];
#pragma unroll
            for (int i = 0; i < 2; i++) {
                wmma::load_matrix_sync(ar, Ss + (16 * i) * 1032 + vt * 32 + ks * 8, 1032);
                split_frag(ar, ah[i], al[i]);
            }
#pragma unroll
            for (int j = 0; j < 2; j++) {
                // B = Vt (col_major): elem (k=kt, n=d) at Vs[d][kt]
                wmma::load_matrix_sync(br, Vs + (w * 32 + 16 * j) * 36 + ks * 8, 36);
                split_frag(br, bh[j], bl[j]);
            }
#pragma unroll
            for (int i = 0; i < 2; i++)
#pragma unroll
                for (int j = 0; j < 2; j++)
                    mma3(oc[i][j], ah[i], al[i], bh[j], bl[j]);
        }
    }

    // ---- Epilogue: O frags -> smem [32][132], transpose-write to g_xx[d][n]
    __syncthreads();
    float* Os = Ss;   // reuse
#pragma unroll
    for (int i = 0; i < 2; i++)
#pragma unroll
        for (int j = 0; j < 2; j++)
            wmma::store_matrix_sync(Os + (16 * i) * 132 + w * 32 + 16 * j,
                                    oc[i][j], 132, wmma::mem_row_major);
    __syncthreads();
    {
        float* xxp = g_xx + (long)b * DHV * NTOK + (long)h * DV * NTOK
                   + (long)t * NTOK + q0;
#pragma unroll
        for (int t4 = 0; t4 < 8; t4++) {
            float4 v;
            v.x = Os[(t4 * 4 + 0) * 132 + t];
            v.y = Os[(t4 * 4 + 1) * 132 + t];
            v.z = Os[(t4 * 4 + 2) * 132 + t];
            v.w = Os[(t4 * 4 + 3) * 132 + t];
            *(float4*)(xxp + t4 * 4) = v;
        }
    }
}

// ---------------------------------------------------------------------------
extern "C" void kernel_launch(void* const* d_in, const int* in_sizes, int n_in,
                              void* d_out, int out_size)
{
    const float* x   = (const float*)d_in[0];
    const float* wq  = (const float*)d_in[1];
    const float* bnq = (const float*)d_in[2];
    const float* wk  = (const float*)d_in[3];
    const float* bnk = (const float*)d_in[4];
    const float* wv  = (const float*)d_in[5];
    const float* bnv = (const float*)d_in[6];
    const float* wp  = (const float*)d_in[7];
    const float* bnp = (const float*)d_in[8];
    float* out = (float*)d_out;

    float *qs, *ks, *vs, *xxs;
    cudaGetSymbolAddress((void**)&qs,  g_q);
    cudaGetSymbolAddress((void**)&ks,  g_k);
    cudaGetSymbolAddress((void**)&vs,  g_v);
    cudaGetSymbolAddress((void**)&xxs, g_xx);

    const int smem_gemm = GEMM_SMEM_F32 * 4;   // 34816 B
    const int smem_attn = ATTN_SMEM_F32 * 4;   // 163840 B
    cudaFuncSetAttribute(attn_tc, cudaFuncAttributeMaxDynamicSharedMemorySize,
                         smem_attn);

    // QKV projections
    gemm_bn_tc<<<dim3(16, NHKD / 128, BB), 256, smem_gemm>>>(
        wq, bnq, x, qs, NHKD, DIM, (long)DIM * NTOK, (long)NHKD * NTOK);
    gemm_bn_tc<<<dim3(16, NHKD / 128, BB), 256, smem_gemm>>>(
        wk, bnk, x, ks, NHKD, DIM, (long)DIM * NTOK, (long)NHKD * NTOK);
    gemm_bn_tc<<<dim3(16, DHV / 128, BB), 256, smem_gemm>>>(
        wv, bnv, x, vs, DHV, DIM, (long)DIM * NTOK, (long)DHV * NTOK);

    // Attention
    attn_tc<<<dim3(NTOK / 32, BB * NH), 128, smem_attn>>>();

    // Output projection
    gemm_bn_tc<<<dim3(16, DIM / 128, BB), 256, smem_gemm>>>(
        wp, bnp, xxs, out, DIM, DHV, (long)DHV * NTOK, (long)DIM * NTOK);
}

// round 4
// speedup vs baseline: 1.3194x; 1.3194x over previous
#include <cuda_runtime.h>
#include <mma.h>
#include <cstdint>
#include <math.h>

using namespace nvcuda;

// Problem constants (fixed shapes from setup_inputs)
#define BB   16
#define DIM  384
#define NHKD 256
#define DHV  1024
#define NTOK 1024
#define NH   8
#define KDIM 32
#define DV   128

// Scratch (device globals — no allocations allowed)
__device__ float g_q [BB * NHKD * NTOK];
__device__ float g_k [BB * NHKD * NTOK];
__device__ float g_v [BB * DHV  * NTOK];
__device__ float g_xx[BB * DHV  * NTOK];

// tf32 round-to-nearest (RNA)
__device__ __forceinline__ float tf32r(float x) {
    uint32_t u;
    asm("cvt.rna.tf32.f32 %0, %1;" : "=r"(u) : "f"(x));
    return __uint_as_float(u);
}

typedef wmma::fragment<wmma::matrix_a, 16, 16, 8, wmma::precision::tf32, wmma::row_major> FragAR;
typedef wmma::fragment<wmma::matrix_a, 16, 16, 8, wmma::precision::tf32, wmma::col_major> FragAC;
typedef wmma::fragment<wmma::matrix_b, 16, 16, 8, wmma::precision::tf32, wmma::row_major> FragBR;
typedef wmma::fragment<wmma::matrix_b, 16, 16, 8, wmma::precision::tf32, wmma::col_major> FragBC;
typedef wmma::fragment<wmma::accumulator, 16, 16, 8, float> FragC;

template <typename F>
__device__ __forceinline__ void split_frag(const F& raw, F& hi, F& lo) {
#pragma unroll
    for (int i = 0; i < raw.num_elements; i++) {
        float h = tf32r(raw.x[i]);
        hi.x[i] = h;
        lo.x[i] = tf32r(raw.x[i] - h);
    }
}
template <typename F>
__device__ __forceinline__ void round_frag(F& f) {
#pragma unroll
    for (int i = 0; i < f.num_elements; i++) f.x[i] = tf32r(f.x[i]);
}
template <typename FA, typename FB>
__device__ __forceinline__ void mma3(FragC& c, const FA& ah, const FA& al,
                                     const FB& bh, const FB& bl) {
    wmma::mma_sync(c, ah, bh, c);
    wmma::mma_sync(c, ah, bl, c);
    wmma::mma_sync(c, al, bh, c);
}

// ---------------------------------------------------------------------------
// GEMM + BN (FFMA, exact — R1 kernel):
//   Y[b][m][n] = (sum_k W[m][k] * X[b][k][n]) * s[m] + t[m]
// ---------------------------------------------------------------------------
__global__ __launch_bounds__(256) void gemm_bn_kernel(
    const float* __restrict__ W, const float* __restrict__ bn,
    const float* __restrict__ X, float* __restrict__ Y,
    int M, int K, long xStride, long yStride)
{
    __shared__ float As[16 * 65];   // [k][m], padded
    __shared__ float Bs[16 * 64];   // [k][n]

    const int t  = threadIdx.x;
    const int tx = t & 15, ty = t >> 4;
    const int n0 = blockIdx.x * 64;
    const int m0 = blockIdx.y * 64;
    const float* Xb = X + (long)blockIdx.z * xStride;
    float*       Yb = Y + (long)blockIdx.z * yStride;

    const int ar = t >> 2, ak = (t & 3) * 4;
    const int bk = t >> 4, bnn = (t & 15) * 4;

    float c[4][4];
#pragma unroll
    for (int i = 0; i < 4; i++)
#pragma unroll
        for (int j = 0; j < 4; j++) c[i][j] = 0.f;

    for (int kt = 0; kt < K; kt += 16) {
        float4 wv4 = *(const float4*)(W + (long)(m0 + ar) * K + kt + ak);
        float4 xv4 = *(const float4*)(Xb + (long)(kt + bk) * NTOK + n0 + bnn);
        __syncthreads();
        As[(ak + 0) * 65 + ar] = wv4.x;
        As[(ak + 1) * 65 + ar] = wv4.y;
        As[(ak + 2) * 65 + ar] = wv4.z;
        As[(ak + 3) * 65 + ar] = wv4.w;
        *(float4*)(Bs + bk * 64 + bnn) = xv4;
        __syncthreads();
#pragma unroll
        for (int kk = 0; kk < 16; kk++) {
            float a0 = As[kk * 65 + ty * 4 + 0];
            float a1 = As[kk * 65 + ty * 4 + 1];
            float a2 = As[kk * 65 + ty * 4 + 2];
            float a3 = As[kk * 65 + ty * 4 + 3];
            float4 b4 = *(float4*)(Bs + kk * 64 + tx * 4);
            c[0][0] += a0 * b4.x; c[0][1] += a0 * b4.y; c[0][2] += a0 * b4.z; c[0][3] += a0 * b4.w;
            c[1][0] += a1 * b4.x; c[1][1] += a1 * b4.y; c[1][2] += a1 * b4.z; c[1][3] += a1 * b4.w;
            c[2][0] += a2 * b4.x; c[2][1] += a2 * b4.y; c[2][2] += a2 * b4.z; c[2][3] += a2 * b4.w;
            c[3][0] += a3 * b4.x; c[3][1] += a3 * b4.y; c[3][2] += a3 * b4.z; c[3][3] += a3 * b4.w;
        }
    }

#pragma unroll
    for (int i = 0; i < 4; i++) {
        int m = m0 + ty * 4 + i;
        float g  = bn[0 * M + m];
        float be = bn[1 * M + m];
        float mu = bn[2 * M + m];
        float va = bn[3 * M + m];
        float sc = g * rsqrtf(va + 1e-5f);
        float tt = be - mu * sc;
        float4 r;
        r.x = c[i][0] * sc + tt;
        r.y = c[i][1] * sc + tt;
        r.z = c[i][2] * sc + tt;
        r.w = c[i][3] * sc + tt;
        *(float4*)(Yb + (long)m * NTOK + n0 + tx * 4) = r;
    }
}

// ---------------------------------------------------------------------------
// Attention (wmma tf32): one CTA per (b, h, 32-query tile), 256 threads.
//   Phase 1: S[32][1024] = (Qt K)*sqrt(32), 3xTF32, Q frags pre-split in regs
//   Phase 2: exact softmax, 8 threads/row
//   Phase 3: O[32][128] = P V^T, 2xTF32 (P rounded single, V hi/lo)
// smem (f32): Ss[32][1032] | Ks[32][68] | Vs[128][36]   = 159232 B
// warp grid both phases: 2(m) x 4(n)
// ---------------------------------------------------------------------------
#define ATTN_SMEM_F32 (32 * 1032 + 32 * 68 + 128 * 36)

__global__ __launch_bounds__(256) void attn_tc()
{
    extern __shared__ float sm[];
    float* Ss = sm;                    // [32][1032]
    float* Ks = Ss + 32 * 1032;        // [32 kd][68]
    float* Vs = Ks + 32 * 68;          // [128 d][36]  (also Q staging)

    const int t = threadIdx.x;
    const int w = t >> 5;
    const int mi = w >> 2;             // 0..1  (16-row half)
    const int nq = w & 3;              // 0..3
    const int q0 = blockIdx.x * 32;
    const int b = blockIdx.y >> 3, h = blockIdx.y & 7;

    const float* qp = g_q + (long)b * NHKD * NTOK + (long)h * KDIM * NTOK;
    const float* kp = g_k + (long)b * NHKD * NTOK + (long)h * KDIM * NTOK;
    const float* vp = g_v + (long)b * DHV  * NTOK + (long)h * DV   * NTOK;

    const float scale = 5.656854249492380f;  // sqrt(32)

    // ---- Stage Q [kd=32][tok=32]*scale into Vs region, build frags once
    {
        int kd = t >> 3, c4 = (t & 7) * 4;
        float4 v = *(const float4*)(qp + (long)kd * NTOK + q0 + c4);
        float* dst = Vs + kd * 36 + c4;
        dst[0] = v.x * scale; dst[1] = v.y * scale;
        dst[2] = v.z * scale; dst[3] = v.w * scale;
    }
    __syncthreads();
    FragAC qh[4], ql[4];               // this warp's m-half only
#pragma unroll
    for (int ks = 0; ks < 4; ks++) {
        FragAC raw;
        wmma::load_matrix_sync(raw, Vs + (ks * 8) * 36 + mi * 16, 36);
        split_frag(raw, qh[ks], ql[ks]);
    }
    __syncthreads();

    // ---- Phase 1: S = Qt K  (3xTF32)
    for (int jt = 0; jt < 16; jt++) {
        if (jt) __syncthreads();       // prev iter frag loads from Ks done
#pragma unroll
        for (int i = 0; i < 2; i++) {
            int idx = t + i * 256;
            int kd = idx >> 4, c4 = (idx & 15) * 4;
            *(float4*)(Ks + kd * 68 + c4) =
                *(const float4*)(kp + (long)kd * NTOK + jt * 64 + c4);
        }
        __syncthreads();

        FragC s;
        wmma::fill_fragment(s, 0.0f);
#pragma unroll
        for (int ks = 0; ks < 4; ks++) {
            FragBR br, bh, bl;
            wmma::load_matrix_sync(br, Ks + (ks * 8) * 68 + nq * 16, 68);
            split_frag(br, bh, bl);
            mma3(s, qh[ks], ql[ks], bh, bl);
        }
        wmma::store_matrix_sync(Ss + (mi * 16) * 1032 + jt * 64 + nq * 16,
                                s, 1032, wmma::mem_row_major);
    }

    // ---- Phase 2: exact softmax (8 threads per row)
    __syncthreads();
    {
        int row = t >> 3, g = t & 7;
        float* Sr = Ss + row * 1032;
        float mx = -1e30f;
        for (int j = g; j < 1024; j += 8) mx = fmaxf(mx, Sr[j]);
        mx = fmaxf(mx, __shfl_xor_sync(0xffffffffu, mx, 1));
        mx = fmaxf(mx, __shfl_xor_sync(0xffffffffu, mx, 2));
        mx = fmaxf(mx, __shfl_xor_sync(0xffffffffu, mx, 4));
        float sum = 0.f;
        for (int j = g; j < 1024; j += 8) {
            float e = __expf(Sr[j] - mx);
            Sr[j] = e;
            sum += e;
        }
        sum += __shfl_xor_sync(0xffffffffu, sum, 1);
        sum += __shfl_xor_sync(0xffffffffu, sum, 2);
        sum += __shfl_xor_sync(0xffffffffu, sum, 4);
        float inv = 1.0f / sum;
        for (int j = g; j < 1024; j += 8) Sr[j] *= inv;
    }

    // ---- Phase 3: O = P V^T  (2xTF32: P rounded, V split). Warp: 16m x 32d.
    FragC oc[2];
    wmma::fill_fragment(oc[0], 0.0f);
    wmma::fill_fragment(oc[1], 0.0f);

    for (int vt = 0; vt < 32; vt++) {
        __syncthreads();               // softmax done / prev frag loads done
#pragma unroll
        for (int i = 0; i < 4; i++) {
            int idx = t + i * 256;
            int d = idx >> 3, c4 = (idx & 7) * 4;
            *(float4*)(Vs + d * 36 + c4) =
                *(const float4*)(vp + (long)d * NTOK + vt * 32 + c4);
        }
        __syncthreads();

#pragma unroll
        for (int ks = 0; ks < 4; ks++) {
            FragAR pa;
            wmma::load_matrix_sync(pa, Ss + (mi * 16) * 1032 + vt * 32 + ks * 8, 1032);
            round_frag(pa);
#pragma unroll
            for (int nf = 0; nf < 2; nf++) {
                FragBC vr, vh, vl;
                wmma::load_matrix_sync(vr, Vs + (nq * 32 + nf * 16) * 36 + ks * 8, 36);
                split_frag(vr, vh, vl);
                wmma::mma_sync(oc[nf], pa, vh, oc[nf]);
                wmma::mma_sync(oc[nf], pa, vl, oc[nf]);
            }
        }
    }

    // ---- Epilogue: O[32 q][128 d] -> g_xx[d][q] (transposed, coalesced)
    __syncthreads();
    float* Os = Ss;   // reuse [32][132]
#pragma unroll
    for (int nf = 0; nf < 2; nf++)
        wmma::store_matrix_sync(Os + (mi * 16) * 132 + nq * 32 + nf * 16,
                                oc[nf], 132, wmma::mem_row_major);
    __syncthreads();
    {
        int d = t >> 1, half = t & 1;
        float* xxp = g_xx + (long)b * DHV * NTOK + (long)h * DV * NTOK
                   + (long)d * NTOK + q0 + half * 16;
#pragma unroll
        for (int t4 = 0; t4 < 4; t4++) {
            float4 v;
            v.x = Os[(half * 16 + t4 * 4 + 0) * 132 + d];
            v.y = Os[(half * 16 + t4 * 4 + 1) * 132 + d];
            v.z = Os[(half * 16 + t4 * 4 + 2) * 132 + d];
            v.w = Os[(half * 16 + t4 * 4 + 3) * 132 + d];
            *(float4*)(xxp + t4 * 4) = v;
        }
    }
}

// ---------------------------------------------------------------------------
extern "C" void kernel_launch(void* const* d_in, const int* in_sizes, int n_in,
                              void* d_out, int out_size)
{
    const float* x   = (const float*)d_in[0];
    const float* wq  = (const float*)d_in[1];
    const float* bnq = (const float*)d_in[2];
    const float* wk  = (const float*)d_in[3];
    const float* bnk = (const float*)d_in[4];
    const float* wv  = (const float*)d_in[5];
    const float* bnv = (const float*)d_in[6];
    const float* wp  = (const float*)d_in[7];
    const float* bnp = (const float*)d_in[8];
    float* out = (float*)d_out;

    float *qs, *ks, *vs, *xxs;
    cudaGetSymbolAddress((void**)&qs,  g_q);
    cudaGetSymbolAddress((void**)&ks,  g_k);
    cudaGetSymbolAddress((void**)&vs,  g_v);
    cudaGetSymbolAddress((void**)&xxs, g_xx);

    const int smem_attn = ATTN_SMEM_F32 * 4;   // 159232 B
    cudaFuncSetAttribute(attn_tc, cudaFuncAttributeMaxDynamicSharedMemorySize,
                         smem_attn);

    dim3 blk(256);

    // QKV projections (exact FFMA)
    gemm_bn_kernel<<<dim3(16, NHKD / 64, BB), blk>>>(
        wq, bnq, x, qs, NHKD, DIM, (long)DIM * NTOK, (long)NHKD * NTOK);
    gemm_bn_kernel<<<dim3(16, NHKD / 64, BB), blk>>>(
        wk, bnk, x, ks, NHKD, DIM, (long)DIM * NTOK, (long)NHKD * NTOK);
    gemm_bn_kernel<<<dim3(16, DHV / 64, BB), blk>>>(
        wv, bnv, x, vs, DHV, DIM, (long)DIM * NTOK, (long)DHV * NTOK);

    // Attention (wmma tf32)
    attn_tc<<<dim3(NTOK / 32, BB * NH), blk, smem_attn>>>();

    // Output projection (exact FFMA)
    gemm_bn_kernel<<<dim3(16, DIM / 64, BB), blk>>>(
        wp, bnp, xxs, out, DIM, DHV, (long)DHV * NTOK, (long)DIM * NTOK);
}

// round 5
// speedup vs baseline: 1.3239x; 1.0034x over previous
#include <cuda_runtime.h>
#include <mma.h>
#include <cstdint>
#include <math.h>

using namespace nvcuda;

// Problem constants (fixed shapes from setup_inputs)
#define BB   16
#define DIM  384
#define NHKD 256
#define DHV  1024
#define NTOK 1024
#define NH   8
#define KDIM 32
#define DV   128

// Scratch (device globals — no allocations allowed)
__device__ float g_q [BB * NHKD * NTOK];
__device__ float g_k [BB * NHKD * NTOK];
__device__ float g_v [BB * DHV  * NTOK];
__device__ float g_xx[BB * DHV  * NTOK];

// tf32 round-to-nearest (RNA)
__device__ __forceinline__ float tf32r(float x) {
    uint32_t u;
    asm("cvt.rna.tf32.f32 %0, %1;" : "=r"(u) : "f"(x));
    return __uint_as_float(u);
}

typedef wmma::fragment<wmma::matrix_a, 16, 16, 8, wmma::precision::tf32, wmma::row_major> FragAR;
typedef wmma::fragment<wmma::matrix_a, 16, 16, 8, wmma::precision::tf32, wmma::col_major> FragAC;
typedef wmma::fragment<wmma::matrix_b, 16, 16, 8, wmma::precision::tf32, wmma::row_major> FragBR;
typedef wmma::fragment<wmma::matrix_b, 16, 16, 8, wmma::precision::tf32, wmma::col_major> FragBC;
typedef wmma::fragment<wmma::accumulator, 16, 16, 8, float> FragC;

template <typename F>
__device__ __forceinline__ void split_frag(const F& raw, F& hi, F& lo) {
#pragma unroll
    for (int i = 0; i < raw.num_elements; i++) {
        float h = tf32r(raw.x[i]);
        hi.x[i] = h;
        lo.x[i] = tf32r(raw.x[i] - h);
    }
}
template <typename F>
__device__ __forceinline__ void round_frag(F& f) {
#pragma unroll
    for (int i = 0; i < f.num_elements; i++) f.x[i] = tf32r(f.x[i]);
}
template <typename FA, typename FB>
__device__ __forceinline__ void mma3(FragC& c, const FA& ah, const FA& al,
                                     const FB& bh, const FB& bl) {
    wmma::mma_sync(c, ah, bh, c);
    wmma::mma_sync(c, ah, bl, c);
    wmma::mma_sync(c, al, bh, c);
}

// ---------------------------------------------------------------------------
// GEMM + BN (FFMA, exact — R1 kernel):
//   Y[b][m][n] = (sum_k W[m][k] * X[b][k][n]) * s[m] + t[m]
// ---------------------------------------------------------------------------
__global__ __launch_bounds__(256) void gemm_bn_kernel(
    const float* __restrict__ W, const float* __restrict__ bn,
    const float* __restrict__ X, float* __restrict__ Y,
    int M, int K, long xStride, long yStride)
{
    __shared__ float As[16 * 65];   // [k][m], padded
    __shared__ float Bs[16 * 64];   // [k][n]

    const int t  = threadIdx.x;
    const int tx = t & 15, ty = t >> 4;
    const int n0 = blockIdx.x * 64;
    const int m0 = blockIdx.y * 64;
    const float* Xb = X + (long)blockIdx.z * xStride;
    float*       Yb = Y + (long)blockIdx.z * yStride;

    const int ar = t >> 2, ak = (t & 3) * 4;
    const int bk = t >> 4, bnn = (t & 15) * 4;

    float c[4][4];
#pragma unroll
    for (int i = 0; i < 4; i++)
#pragma unroll
        for (int j = 0; j < 4; j++) c[i][j] = 0.f;

    for (int kt = 0; kt < K; kt += 16) {
        float4 wv4 = *(const float4*)(W + (long)(m0 + ar) * K + kt + ak);
        float4 xv4 = *(const float4*)(Xb + (long)(kt + bk) * NTOK + n0 + bnn);
        __syncthreads();
        As[(ak + 0) * 65 + ar] = wv4.x;
        As[(ak + 1) * 65 + ar] = wv4.y;
        As[(ak + 2) * 65 + ar] = wv4.z;
        As[(ak + 3) * 65 + ar] = wv4.w;
        *(float4*)(Bs + bk * 64 + bnn) = xv4;
        __syncthreads();
#pragma unroll
        for (int kk = 0; kk < 16; kk++) {
            float a0 = As[kk * 65 + ty * 4 + 0];
            float a1 = As[kk * 65 + ty * 4 + 1];
            float a2 = As[kk * 65 + ty * 4 + 2];
            float a3 = As[kk * 65 + ty * 4 + 3];
            float4 b4 = *(float4*)(Bs + kk * 64 + tx * 4);
            c[0][0] += a0 * b4.x; c[0][1] += a0 * b4.y; c[0][2] += a0 * b4.z; c[0][3] += a0 * b4.w;
            c[1][0] += a1 * b4.x; c[1][1] += a1 * b4.y; c[1][2] += a1 * b4.z; c[1][3] += a1 * b4.w;
            c[2][0] += a2 * b4.x; c[2][1] += a2 * b4.y; c[2][2] += a2 * b4.z; c[2][3] += a2 * b4.w;
            c[3][0] += a3 * b4.x; c[3][1] += a3 * b4.y; c[3][2] += a3 * b4.z; c[3][3] += a3 * b4.w;
        }
    }

#pragma unroll
    for (int i = 0; i < 4; i++) {
        int m = m0 + ty * 4 + i;
        float g  = bn[0 * M + m];
        float be = bn[1 * M + m];
        float mu = bn[2 * M + m];
        float va = bn[3 * M + m];
        float sc = g * rsqrtf(va + 1e-5f);
        float tt = be - mu * sc;
        float4 r;
        r.x = c[i][0] * sc + tt;
        r.y = c[i][1] * sc + tt;
        r.z = c[i][2] * sc + tt;
        r.w = c[i][3] * sc + tt;
        *(float4*)(Yb + (long)m * NTOK + n0 + tx * 4) = r;
    }
}

// ---------------------------------------------------------------------------
// Attention (wmma tf32): one CTA per (b, h, 32-query tile), 256 threads.
//   Phase 1: S[32][1024] = (Qt K)*sqrt(32), 3xTF32, Q frags pre-split in regs
//   Phase 2: exact softmax, 8 threads/row
//   Phase 3: O[32][128] = P V^T, 2xTF32 (P rounded single, V hi/lo)
// smem (f32): Ss[32][1032] | Ks[32][68] | Vs[128][36]   = 159232 B
// warp grid both phases: 2(m) x 4(n)
// ---------------------------------------------------------------------------
#define ATTN_SMEM_F32 (32 * 1032 + 32 * 68 + 128 * 36)

__global__ __launch_bounds__(256) void attn_tc()
{
    extern __shared__ float sm[];
    float* Ss = sm;                    // [32][1032]
    float* Ks = Ss + 32 * 1032;        // [32 kd][68]
    float* Vs = Ks + 32 * 68;          // [128 d][36]  (also Q staging)

    const int t = threadIdx.x;
    const int w = t >> 5;
    const int mi = w >> 2;             // 0..1  (16-row half)
    const int nq = w & 3;              // 0..3
    const int q0 = blockIdx.x * 32;
    const int b = blockIdx.y >> 3, h = blockIdx.y & 7;

    const float* qp = g_q + (long)b * NHKD * NTOK + (long)h * KDIM * NTOK;
    const float* kp = g_k + (long)b * NHKD * NTOK + (long)h * KDIM * NTOK;
    const float* vp = g_v + (long)b * DHV  * NTOK + (long)h * DV   * NTOK;

    const float scale = 5.656854249492380f;  // sqrt(32)

    // ---- Stage Q [kd=32][tok=32]*scale into Vs region, build frags once
    {
        int kd = t >> 3, c4 = (t & 7) * 4;
        float4 v = *(const float4*)(qp + (long)kd * NTOK + q0 + c4);
        float* dst = Vs + kd * 36 + c4;
        dst[0] = v.x * scale; dst[1] = v.y * scale;
        dst[2] = v.z * scale; dst[3] = v.w * scale;
    }
    __syncthreads();
    FragAC qh[4], ql[4];               // this warp's m-half only
#pragma unroll
    for (int ks = 0; ks < 4; ks++) {
        FragAC raw;
        wmma::load_matrix_sync(raw, Vs + (ks * 8) * 36 + mi * 16, 36);
        split_frag(raw, qh[ks], ql[ks]);
    }
    __syncthreads();

    // ---- Phase 1: S = Qt K  (3xTF32)
    for (int jt = 0; jt < 16; jt++) {
        if (jt) __syncthreads();       // prev iter frag loads from Ks done
#pragma unroll
        for (int i = 0; i < 2; i++) {
            int idx = t + i * 256;
            int kd = idx >> 4, c4 = (idx & 15) * 4;
            *(float4*)(Ks + kd * 68 + c4) =
                *(const float4*)(kp + (long)kd * NTOK + jt * 64 + c4);
        }
        __syncthreads();

        FragC s;
        wmma::fill_fragment(s, 0.0f);
#pragma unroll
        for (int ks = 0; ks < 4; ks++) {
            FragBR br, bh, bl;
            wmma::load_matrix_sync(br, Ks + (ks * 8) * 68 + nq * 16, 68);
            split_frag(br, bh, bl);
            mma3(s, qh[ks], ql[ks], bh, bl);
        }
        wmma::store_matrix_sync(Ss + (mi * 16) * 1032 + jt * 64 + nq * 16,
                                s, 1032, wmma::mem_row_major);
    }

    // ---- Phase 2: exact softmax (8 threads per row)
    __syncthreads();
    {
        int row = t >> 3, g = t & 7;
        float* Sr = Ss + row * 1032;
        float mx = -1e30f;
        for (int j = g; j < 1024; j += 8) mx = fmaxf(mx, Sr[j]);
        mx = fmaxf(mx, __shfl_xor_sync(0xffffffffu, mx, 1));
        mx = fmaxf(mx, __shfl_xor_sync(0xffffffffu, mx, 2));
        mx = fmaxf(mx, __shfl_xor_sync(0xffffffffu, mx, 4));
        float sum = 0.f;
        for (int j = g; j < 1024; j += 8) {
            float e = __expf(Sr[j] - mx);
            Sr[j] = e;
            sum += e;
        }
        sum += __shfl_xor_sync(0xffffffffu, sum, 1);
        sum += __shfl_xor_sync(0xffffffffu, sum, 2);
        sum += __shfl_xor_sync(0xffffffffu, sum, 4);
        float inv = 1.0f / sum;
        for (int j = g; j < 1024; j += 8) Sr[j] *= inv;
    }

    // ---- Phase 3: O = P V^T  (2xTF32: P rounded, V split). Warp: 16m x 32d.
    FragC oc[2];
    wmma::fill_fragment(oc[0], 0.0f);
    wmma::fill_fragment(oc[1], 0.0f);

    for (int vt = 0; vt < 32; vt++) {
        __syncthreads();               // softmax done / prev frag loads done
#pragma unroll
        for (int i = 0; i < 4; i++) {
            int idx = t + i * 256;
            int d = idx >> 3, c4 = (idx & 7) * 4;
            *(float4*)(Vs + d * 36 + c4) =
                *(const float4*)(vp + (long)d * NTOK + vt * 32 + c4);
        }
        __syncthreads();

#pragma unroll
        for (int ks = 0; ks < 4; ks++) {
            FragAR pa;
            wmma::load_matrix_sync(pa, Ss + (mi * 16) * 1032 + vt * 32 + ks * 8, 1032);
            round_frag(pa);
#pragma unroll
            for (int nf = 0; nf < 2; nf++) {
                FragBC vr, vh, vl;
                wmma::load_matrix_sync(vr, Vs + (nq * 32 + nf * 16) * 36 + ks * 8, 36);
                split_frag(vr, vh, vl);
                wmma::mma_sync(oc[nf], pa, vh, oc[nf]);
                wmma::mma_sync(oc[nf], pa, vl, oc[nf]);
            }
        }
    }

    // ---- Epilogue: O[32 q][128 d] -> g_xx[d][q] (transposed, coalesced)
    __syncthreads();
    float* Os = Ss;   // reuse [32][132]
#pragma unroll
    for (int nf = 0; nf < 2; nf++)
        wmma::store_matrix_sync(Os + (mi * 16) * 132 + nq * 32 + nf * 16,
                                oc[nf], 132, wmma::mem_row_major);
    __syncthreads();
    {
        int d = t >> 1, half = t & 1;
        float* xxp = g_xx + (long)b * DHV * NTOK + (long)h * DV * NTOK
                   + (long)d * NTOK + q0 + half * 16;
#pragma unroll
        for (int t4 = 0; t4 < 4; t4++) {
            float4 v;
            v.x = Os[(half * 16 + t4 * 4 + 0) * 132 + d];
            v.y = Os[(half * 16 + t4 * 4 + 1) * 132 + d];
            v.z = Os[(half * 16 + t4 * 4 + 2) * 132 + d];
            v.w = Os[(half * 16 + t4 * 4 + 3) * 132 + d];
            *(float4*)(xxp + t4 * 4) = v;
        }
    }
}

// ---------------------------------------------------------------------------
extern "C" void kernel_launch(void* const* d_in, const int* in_sizes, int n_in,
                              void* d_out, int out_size)
{
    const float* x   = (const float*)d_in[0];
    const float* wq  = (const float*)d_in[1];
    const float* bnq = (const float*)d_in[2];
    const float* wk  = (const float*)d_in[3];
    const float* bnk = (const float*)d_in[4];
    const float* wv  = (const float*)d_in[5];
    const float* bnv = (const float*)d_in[6];
    const float* wp  = (const float*)d_in[7];
    const float* bnp = (const float*)d_in[8];
    float* out = (float*)d_out;

    float *qs, *ks, *vs, *xxs;
    cudaGetSymbolAddress((void**)&qs,  g_q);
    cudaGetSymbolAddress((void**)&ks,  g_k);
    cudaGetSymbolAddress((void**)&vs,  g_v);
    cudaGetSymbolAddress((void**)&xxs, g_xx);

    const int smem_attn = ATTN_SMEM_F32 * 4;   // 159232 B
    cudaFuncSetAttribute(attn_tc, cudaFuncAttributeMaxDynamicSharedMemorySize,
                         smem_attn);

    dim3 blk(256);

    // QKV projections (exact FFMA)
    gemm_bn_kernel<<<dim3(16, NHKD / 64, BB), blk>>>(
        wq, bnq, x, qs, NHKD, DIM, (long)DIM * NTOK, (long)NHKD * NTOK);
    gemm_bn_kernel<<<dim3(16, NHKD / 64, BB), blk>>>(
        wk, bnk, x, ks, NHKD, DIM, (long)DIM * NTOK, (long)NHKD * NTOK);
    gemm_bn_kernel<<<dim3(16, DHV / 64, BB), blk>>>(
        wv, bnv, x, vs, DHV, DIM, (long)DIM * NTOK, (long)DHV * NTOK);

    // Attention (wmma tf32)
    attn_tc<<<dim3(NTOK / 32, BB * NH), blk, smem_attn>>>();

    // Output projection (exact FFMA)
    gemm_bn_kernel<<<dim3(16, DIM / 64, BB), blk>>>(
        wp, bnp, xxs, out, DIM, DHV, (long)DHV * NTOK, (long)DIM * NTOK);
}

// round 6
// speedup vs baseline: 2.5440x; 1.9216x over previous
#include <cuda_runtime.h>
#include <cstdint>
#include <math.h>

#define BB   16
#define DIM  384
#define NHKD 256
#define DHV  1024
#define NTOK 1024
#define NH   8
#define KDIM 32
#define DV   128

__device__ float g_q [BB * NHKD * NTOK];
__device__ float g_k [BB * NHKD * NTOK];
__device__ float g_v [BB * DHV  * NTOK];
__device__ float g_xx[BB * DHV  * NTOK];

__device__ __forceinline__ float tf32r(float x) {
    uint32_t u;
    asm("cvt.rna.tf32.f32 %0, %1;" : "=r"(u) : "f"(x));
    return __uint_as_float(u);
}
__device__ __forceinline__ uint32_t fb(float x) { return __float_as_uint(x); }

__device__ __forceinline__ void mma8(float c[4], const uint32_t a[4],
                                     uint32_t b0, uint32_t b1) {
    asm volatile("mma.sync.aligned.m16n8k8.row.col.f32.tf32.tf32.f32 "
        "{%0,%1,%2,%3}, {%4,%5,%6,%7}, {%8,%9}, {%0,%1,%2,%3};"
        : "+f"(c[0]), "+f"(c[1]), "+f"(c[2]), "+f"(c[3])
        : "r"(a[0]), "r"(a[1]), "r"(a[2]), "r"(a[3]), "r"(b0), "r"(b1));
}

// 2^z on FMA pipe, z <= 0 (clamped at -100). deg-5 poly, rel err ~6e-6.
__device__ __forceinline__ float fexp2(float z) {
    z = fmaxf(z, -100.0f);
    float zi = z + 12582912.0f;
    int   n  = __float_as_int(zi) - 0x4B400000;
    float t  = z - (zi - 12582912.0f);
    float p = fmaf(0.0013333558f, t, 0.0096181291f);
    p = fmaf(p, t, 0.0555041087f);
    p = fmaf(p, t, 0.2402265069f);
    p = fmaf(p, t, 0.6931471806f);
    p = fmaf(p, t, 1.0f);
    return __int_as_float(__float_as_int(p) + (n << 23));
}

// ---------------- exact FFMA GEMM+BN (proven R1 kernel) --------------------
__global__ __launch_bounds__(256) void gemm_bn_kernel(
    const float* __restrict__ W, const float* __restrict__ bn,
    const float* __restrict__ X, float* __restrict__ Y,
    int M, int K, long xStride, long yStride)
{
    __shared__ float As[16 * 65];
    __shared__ float Bs[16 * 64];
    const int t = threadIdx.x, tx = t & 15, ty = t >> 4;
    const int n0 = blockIdx.x * 64, m0 = blockIdx.y * 64;
    const float* Xb = X + (long)blockIdx.z * xStride;
    float*       Yb = Y + (long)blockIdx.z * yStride;
    const int ar = t >> 2, ak = (t & 3) * 4;
    const int bk = t >> 4, bnn = (t & 15) * 4;
    float c[4][4];
#pragma unroll
    for (int i = 0; i < 4; i++)
#pragma unroll
        for (int j = 0; j < 4; j++) c[i][j] = 0.f;
    for (int kt = 0; kt < K; kt += 16) {
        float4 wv4 = *(const float4*)(W + (long)(m0 + ar) * K + kt + ak);
        float4 xv4 = *(const float4*)(Xb + (long)(kt + bk) * NTOK + n0 + bnn);
        __syncthreads();
        As[(ak + 0) * 65 + ar] = wv4.x;
        As[(ak + 1) * 65 + ar] = wv4.y;
        As[(ak + 2) * 65 + ar] = wv4.z;
        As[(ak + 3) * 65 + ar] = wv4.w;
        *(float4*)(Bs + bk * 64 + bnn) = xv4;
        __syncthreads();
#pragma unroll
        for (int kk = 0; kk < 16; kk++) {
            float a0 = As[kk * 65 + ty * 4 + 0];
            float a1 = As[kk * 65 + ty * 4 + 1];
            float a2 = As[kk * 65 + ty * 4 + 2];
            float a3 = As[kk * 65 + ty * 4 + 3];
            float4 b4 = *(float4*)(Bs + kk * 64 + tx * 4);
            c[0][0] += a0 * b4.x; c[0][1] += a0 * b4.y; c[0][2] += a0 * b4.z; c[0][3] += a0 * b4.w;
            c[1][0] += a1 * b4.x; c[1][1] += a1 * b4.y; c[1][2] += a1 * b4.z; c[1][3] += a1 * b4.w;
            c[2][0] += a2 * b4.x; c[2][1] += a2 * b4.y; c[2][2] += a2 * b4.z; c[2][3] += a2 * b4.w;
            c[3][0] += a3 * b4.x; c[3][1] += a3 * b4.y; c[3][2] += a3 * b4.z; c[3][3] += a3 * b4.w;
        }
    }
#pragma unroll
    for (int i = 0; i < 4; i++) {
        int m = m0 + ty * 4 + i;
        float sc = bn[m] * rsqrtf(bn[3 * M + m] + 1e-5f);
        float tt = bn[M + m] - bn[2 * M + m] * sc;
        float4 r;
        r.x = c[i][0] * sc + tt; r.y = c[i][1] * sc + tt;
        r.z = c[i][2] * sc + tt; r.w = c[i][3] * sc + tt;
        *(float4*)(Yb + (long)m * NTOK + n0 + tx * 4) = r;
    }
}

// ---------------- FA2 attention on mma.sync tf32 ---------------------------
// CTA = (64-query tile, b, h), 256 thr, 8 warps: mi=w>>1 (16 rows), ni=w&1.
// QK 3xTF32 (K split in smem, Q split in regs); AV 1xTF32 (P,V rounded).
// smem floats: KH[32*72] KL[32*72] V[128*68] P[64*68](=Q stage)
//              MP[2*64] SP[2*64] MR[2*64] LR[64]
#define SO_KH 0
#define SO_KL 2304
#define SO_V  4608
#define SO_P  13312
#define SO_MP 17664
#define SO_SP 17792
#define SO_MR 17920
#define SO_LR 18048
#define ATTN_SMEM_F 18112

__global__ __launch_bounds__(256) void attn_fa()
{
    extern __shared__ float sm[];
    const int t = threadIdx.x, lane = t & 31, w = t >> 5;
    const int mi = w >> 1, ni = w & 1;
    const int g = lane >> 2, q = lane & 3;
    const int q0 = blockIdx.x * 64;
    const int b = blockIdx.y >> 3, h = blockIdx.y & 7;
    const float* qp = g_q + ((long)b * NHKD + h * KDIM) * NTOK;
    const float* kp = g_k + ((long)b * NHKD + h * KDIM) * NTOK;
    const float* vp = g_v + ((long)b * DHV  + h * DV  ) * NTOK;
    const float SQ = 5.656854249492380f, L2E = 1.44269504088896f;

    // stage Q [32 kd][64 q]*SQ into P area (pad 72)
    {
        int kd = t >> 3, c8 = (t & 7) * 8;
        const float* s = qp + (long)kd * NTOK + q0 + c8;
        float4 u0 = *(const float4*)s, u1 = *(const float4*)(s + 4);
        u0.x *= SQ; u0.y *= SQ; u0.z *= SQ; u0.w *= SQ;
        u1.x *= SQ; u1.y *= SQ; u1.z *= SQ; u1.w *= SQ;
        *(float4*)(sm + SO_P + kd * 72 + c8) = u0;
        *(float4*)(sm + SO_P + kd * 72 + c8 + 4) = u1;
    }
    if (t < 64) { sm[SO_MR + t] = -1e30f; sm[SO_MR + 64 + t] = -1e30f; sm[SO_LR + t] = 0.f; }
    __syncthreads();

    const int r0 = mi * 16 + g;
    uint32_t qh[4][4], ql[4][4];
#pragma unroll
    for (int ks = 0; ks < 4; ks++) {
        float v0 = sm[SO_P + (ks * 8 + q) * 72 + r0];
        float v1 = sm[SO_P + (ks * 8 + q) * 72 + r0 + 8];
        float v2 = sm[SO_P + (ks * 8 + q + 4) * 72 + r0];
        float v3 = sm[SO_P + (ks * 8 + q + 4) * 72 + r0 + 8];
        float h0 = tf32r(v0), h1 = tf32r(v1), h2 = tf32r(v2), h3 = tf32r(v3);
        qh[ks][0] = fb(h0); ql[ks][0] = fb(tf32r(v0 - h0));
        qh[ks][1] = fb(h1); ql[ks][1] = fb(tf32r(v1 - h1));
        qh[ks][2] = fb(h2); ql[ks][2] = fb(tf32r(v2 - h2));
        qh[ks][3] = fb(h3); ql[ks][3] = fb(tf32r(v3 - h3));
    }
    __syncthreads();

    float o[8][4];
#pragma unroll
    for (int nf = 0; nf < 8; nf++)
#pragma unroll
        for (int j = 0; j < 4; j++) o[nf][j] = 0.f;

    const int skd = t >> 3, skv = (t & 7) * 8;   // K staging
    const int svd = t >> 1, svq = (t & 1) * 32;  // V staging

    for (int it = 0; it < 16; it++) {
        const int j0 = it * 64;
        __syncthreads();   // prev AV done with V/P
        {
            const float* ks_ = kp + (long)skd * NTOK + j0 + skv;
            float4 u0 = *(const float4*)ks_, u1 = *(const float4*)(ks_ + 4);
            float kr[8] = {u0.x, u0.y, u0.z, u0.w, u1.x, u1.y, u1.z, u1.w};
#pragma unroll
            for (int j = 0; j < 8; j++) {
                float hi = tf32r(kr[j]);
                sm[SO_KH + skd * 72 + skv + j] = hi;
                sm[SO_KL + skd * 72 + skv + j] = tf32r(kr[j] - hi);
            }
            const float* vs_ = vp + (long)svd * NTOK + j0 + svq;
#pragma unroll
            for (int p = 0; p < 8; p++) {
                float4 v = *(const float4*)(vs_ + p * 4);
                v.x = tf32r(v.x); v.y = tf32r(v.y); v.z = tf32r(v.z); v.w = tf32r(v.w);
                *(float4*)(sm + SO_V + svd * 68 + svq + p * 4) = v;
            }
        }
        __syncthreads();

        // QK 3xTF32: S[16][32] per warp
        float s4[4][4];
#pragma unroll
        for (int nf = 0; nf < 4; nf++)
#pragma unroll
            for (int j = 0; j < 4; j++) s4[nf][j] = 0.f;
#pragma unroll
        for (int ks = 0; ks < 4; ks++) {
            int kd0 = ks * 8 + q;
#pragma unroll
            for (int nf = 0; nf < 4; nf++) {
                int col = ni * 32 + nf * 8 + g;
                uint32_t bh0 = fb(sm[SO_KH + kd0 * 72 + col]);
                uint32_t bh1 = fb(sm[SO_KH + (kd0 + 4) * 72 + col]);
                uint32_t bl0 = fb(sm[SO_KL + kd0 * 72 + col]);
                uint32_t bl1 = fb(sm[SO_KL + (kd0 + 4) * 72 + col]);
                mma8(s4[nf], qh[ks], bh0, bh1);
                mma8(s4[nf], qh[ks], bl0, bl1);
                mma8(s4[nf], ql[ks], bh0, bh1);
            }
        }

        // warp-local row max -> MP
        {
            float m0 = fmaxf(fmaxf(s4[0][0], s4[0][1]), fmaxf(s4[1][0], s4[1][1]));
            m0 = fmaxf(m0, fmaxf(fmaxf(s4[2][0], s4[2][1]), fmaxf(s4[3][0], s4[3][1])));
            float m1 = fmaxf(fmaxf(s4[0][2], s4[0][3]), fmaxf(s4[1][2], s4[1][3]));
            m1 = fmaxf(m1, fmaxf(fmaxf(s4[2][2], s4[2][3]), fmaxf(s4[3][2], s4[3][3])));
            m0 = fmaxf(m0, __shfl_xor_sync(0xffffffffu, m0, 1));
            m0 = fmaxf(m0, __shfl_xor_sync(0xffffffffu, m0, 2));
            m1 = fmaxf(m1, __shfl_xor_sync(0xffffffffu, m1, 1));
            m1 = fmaxf(m1, __shfl_xor_sync(0xffffffffu, m1, 2));
            if (q == 0) {
                sm[SO_MP + ni * 64 + r0] = m0;
                sm[SO_MP + ni * 64 + r0 + 8] = m1;
            }
        }
        __syncthreads();

        // new max, alpha, P (rounded), partial sums, O rescale
        {
            float moA = sm[SO_MR + (it & 1) * 64 + r0];
            float moB = sm[SO_MR + (it & 1) * 64 + r0 + 8];
            float mn0 = fmaxf(moA, fmaxf(sm[SO_MP + r0], sm[SO_MP + 64 + r0]));
            float mn1 = fmaxf(moB, fmaxf(sm[SO_MP + r0 + 8], sm[SO_MP + 64 + r0 + 8]));
            if (ni == 0 && q == 0) {
                sm[SO_MR + ((it + 1) & 1) * 64 + r0] = mn0;
                sm[SO_MR + ((it + 1) & 1) * 64 + r0 + 8] = mn1;
            }
            float al0 = fexp2((moA - mn0) * L2E);
            float al1 = fexp2((moB - mn1) * L2E);
            float c0 = -mn0 * L2E, c1 = -mn1 * L2E;
            float rs0 = 0.f, rs1 = 0.f;
#pragma unroll
            for (int nf = 0; nf < 4; nf++) {
                int col = ni * 32 + nf * 8 + 2 * q;
                float e00 = tf32r(fexp2(fmaf(s4[nf][0], L2E, c0)));
                float e01 = tf32r(fexp2(fmaf(s4[nf][1], L2E, c0)));
                float e10 = tf32r(fexp2(fmaf(s4[nf][2], L2E, c1)));
                float e11 = tf32r(fexp2(fmaf(s4[nf][3], L2E, c1)));
                rs0 += e00 + e01; rs1 += e10 + e11;
                *(float2*)(sm + SO_P + r0 * 68 + col) = make_float2(e00, e01);
                *(float2*)(sm + SO_P + (r0 + 8) * 68 + col) = make_float2(e10, e11);
            }
            rs0 += __shfl_xor_sync(0xffffffffu, rs0, 1);
            rs0 += __shfl_xor_sync(0xffffffffu, rs0, 2);
            rs1 += __shfl_xor_sync(0xffffffffu, rs1, 1);
            rs1 += __shfl_xor_sync(0xffffffffu, rs1, 2);
            if (q == 0) {
                sm[SO_SP + ni * 64 + r0] = rs0;
                sm[SO_SP + ni * 64 + r0 + 8] = rs1;
            }
#pragma unroll
            for (int nf = 0; nf < 8; nf++) {
                o[nf][0] *= al0; o[nf][1] *= al0;
                o[nf][2] *= al1; o[nf][3] *= al1;
            }
        }
        __syncthreads();

        // l update (concurrent with AV)
        if (t < 64) {
            float mo = sm[SO_MR + (it & 1) * 64 + t];
            float mn = sm[SO_MR + ((it + 1) & 1) * 64 + t];
            sm[SO_LR + t] = sm[SO_LR + t] * fexp2((mo - mn) * L2E)
                          + sm[SO_SP + t] + sm[SO_SP + 64 + t];
        }

        // AV 1xTF32: O[16][64] per warp
#pragma unroll
        for (int ks = 0; ks < 8; ks++) {
            uint32_t a[4];
            a[0] = fb(sm[SO_P + r0 * 68 + ks * 8 + q]);
            a[1] = fb(sm[SO_P + (r0 + 8) * 68 + ks * 8 + q]);
            a[2] = fb(sm[SO_P + r0 * 68 + ks * 8 + q + 4]);
            a[3] = fb(sm[SO_P + (r0 + 8) * 68 + ks * 8 + q + 4]);
#pragma unroll
            for (int nf = 0; nf < 8; nf++) {
                int d = ni * 64 + nf * 8 + g;
                uint32_t b0 = fb(sm[SO_V + d * 68 + ks * 8 + q]);
                uint32_t b1 = fb(sm[SO_V + d * 68 + ks * 8 + q + 4]);
                mma8(o[nf], a, b0, b1);
            }
        }
    }

    // epilogue: normalize, transpose via smem (reuse V area), coalesced store
    __syncthreads();
    {
        float inv0 = 1.0f / sm[SO_LR + r0];
        float inv1 = 1.0f / sm[SO_LR + r0 + 8];
#pragma unroll
        for (int nf = 0; nf < 8; nf++) {
            int d = ni * 64 + nf * 8 + 2 * q;
            sm[SO_V + d * 68 + r0]           = o[nf][0] * inv0;
            sm[SO_V + (d + 1) * 68 + r0]     = o[nf][1] * inv0;
            sm[SO_V + d * 68 + r0 + 8]       = o[nf][2] * inv1;
            sm[SO_V + (d + 1) * 68 + r0 + 8] = o[nf][3] * inv1;
        }
    }
    __syncthreads();
    {
        int d = t >> 1, qq = (t & 1) * 32;
        float* dst = g_xx + ((long)b * DHV + h * DV + d) * NTOK + q0 + qq;
#pragma unroll
        for (int p = 0; p < 8; p++)
            *(float4*)(dst + p * 4) = *(const float4*)(sm + SO_V + d * 68 + qq + p * 4);
    }
}

// ---------------------------------------------------------------------------
extern "C" void kernel_launch(void* const* d_in, const int* in_sizes, int n_in,
                              void* d_out, int out_size)
{
    const float* x   = (const float*)d_in[0];
    const float* wq  = (const float*)d_in[1];
    const float* bnq = (const float*)d_in[2];
    const float* wk  = (const float*)d_in[3];
    const float* bnk = (const float*)d_in[4];
    const float* wv  = (const float*)d_in[5];
    const float* bnv = (const float*)d_in[6];
    const float* wp  = (const float*)d_in[7];
    const float* bnp = (const float*)d_in[8];
    float* out = (float*)d_out;

    float *qs, *ks, *vs, *xxs;
    cudaGetSymbolAddress((void**)&qs,  g_q);
    cudaGetSymbolAddress((void**)&ks,  g_k);
    cudaGetSymbolAddress((void**)&vs,  g_v);
    cudaGetSymbolAddress((void**)&xxs, g_xx);

    const int smem_attn = ATTN_SMEM_F * 4;   // 72448 B
    cudaFuncSetAttribute(attn_fa, cudaFuncAttributeMaxDynamicSharedMemorySize,
                         smem_attn);
    dim3 blk(256);

    gemm_bn_kernel<<<dim3(16, NHKD / 64, BB), blk>>>(
        wq, bnq, x, qs, NHKD, DIM, (long)DIM * NTOK, (long)NHKD * NTOK);
    gemm_bn_kernel<<<dim3(16, NHKD / 64, BB), blk>>>(
        wk, bnk, x, ks, NHKD, DIM, (long)DIM * NTOK, (long)NHKD * NTOK);
    gemm_bn_kernel<<<dim3(16, DHV / 64, BB), blk>>>(
        wv, bnv, x, vs, DHV, DIM, (long)DIM * NTOK, (long)DHV * NTOK);

    attn_fa<<<dim3(NTOK / 64, BB * NH), blk, smem_attn>>>();

    gemm_bn_kernel<<<dim3(16, DIM / 64, BB), blk>>>(
        wp, bnp, xxs, out, DIM, DHV, (long)DHV * NTOK, (long)DIM * NTOK);
}

// round 7
// speedup vs baseline: 2.7870x; 1.0955x over previous
#include <cuda_runtime.h>
#include <cstdint>
#include <math.h>

#define BB   16
#define DIM  384
#define NHKD 256
#define DHV  1024
#define NTOK 1024
#define NH   8
#define KDIM 32
#define DV   128

__device__ float g_q [BB * NHKD * NTOK];
__device__ float g_k [BB * NHKD * NTOK];
__device__ float g_v [BB * DHV  * NTOK];
__device__ float g_xx[BB * DHV  * NTOK];

__device__ __forceinline__ float tf32r(float x) {
    uint32_t u;
    asm("cvt.rna.tf32.f32 %0, %1;" : "=r"(u) : "f"(x));
    return __uint_as_float(u);
}
__device__ __forceinline__ uint32_t fb(float x) { return __float_as_uint(x); }

__device__ __forceinline__ void mma8(float c[4], const uint32_t a[4],
                                     uint32_t b0, uint32_t b1) {
    asm volatile("mma.sync.aligned.m16n8k8.row.col.f32.tf32.tf32.f32 "
        "{%0,%1,%2,%3}, {%4,%5,%6,%7}, {%8,%9}, {%0,%1,%2,%3};"
        : "+f"(c[0]), "+f"(c[1]), "+f"(c[2]), "+f"(c[3])
        : "r"(a[0]), "r"(a[1]), "r"(a[2]), "r"(a[3]), "r"(b0), "r"(b1));
}

// 2^z on FMA pipe, z <= 0 (clamped at -100). deg-5 poly.
__device__ __forceinline__ float fexp2(float z) {
    z = fmaxf(z, -100.0f);
    float zi = z + 12582912.0f;
    int   n  = __float_as_int(zi) - 0x4B400000;
    float t  = z - (zi - 12582912.0f);
    float p = fmaf(0.0013333558f, t, 0.0096181291f);
    p = fmaf(p, t, 0.0555041087f);
    p = fmaf(p, t, 0.2402265069f);
    p = fmaf(p, t, 0.6931471806f);
    p = fmaf(p, t, 1.0f);
    return __int_as_float(__float_as_int(p) + (n << 23));
}

// ---------------- exact FFMA GEMM+BN, 128x128 tile, 8x8/thread -------------
__global__ __launch_bounds__(256) void gemm_bn128(
    const float* __restrict__ W, const float* __restrict__ bn,
    const float* __restrict__ X, float* __restrict__ Y,
    int M, int K, long xStride, long yStride)
{
    __shared__ float As[16 * 132];   // [k][m]
    __shared__ float Bs[16 * 128];   // [k][n]
    const int t = threadIdx.x, tx = t & 15, ty = t >> 4;
    const int n0 = blockIdx.x * 128, m0 = blockIdx.y * 128;
    const float* Xb = X + (long)blockIdx.z * xStride;
    float*       Yb = Y + (long)blockIdx.z * yStride;
    const int am = t & 127, akh = (t >> 7) * 8;   // A loader: row am, k akh..+8
    const int bk = t >> 4,  bn8 = (t & 15) * 8;   // B loader: k bk, n bn8..+8

    float c[8][8];
#pragma unroll
    for (int i = 0; i < 8; i++)
#pragma unroll
        for (int j = 0; j < 8; j++) c[i][j] = 0.f;

    for (int kt = 0; kt < K; kt += 16) {
        const float* wp_ = W + (long)(m0 + am) * K + kt + akh;
        float4 w0 = *(const float4*)wp_;
        float4 w1 = *(const float4*)(wp_ + 4);
        const float* xp_ = Xb + (long)(kt + bk) * NTOK + n0 + bn8;
        float4 x0 = *(const float4*)xp_;
        float4 x1 = *(const float4*)(xp_ + 4);
        __syncthreads();
        As[(akh + 0) * 132 + am] = w0.x;
        As[(akh + 1) * 132 + am] = w0.y;
        As[(akh + 2) * 132 + am] = w0.z;
        As[(akh + 3) * 132 + am] = w0.w;
        As[(akh + 4) * 132 + am] = w1.x;
        As[(akh + 5) * 132 + am] = w1.y;
        As[(akh + 6) * 132 + am] = w1.z;
        As[(akh + 7) * 132 + am] = w1.w;
        *(float4*)(Bs + bk * 128 + bn8)     = x0;
        *(float4*)(Bs + bk * 128 + bn8 + 4) = x1;
        __syncthreads();
#pragma unroll
        for (int k = 0; k < 16; k++) {
            float4 a0 = *(float4*)(As + k * 132 + ty * 4);
            float4 a1 = *(float4*)(As + k * 132 + 64 + ty * 4);
            float4 b0 = *(float4*)(Bs + k * 128 + tx * 4);
            float4 b1 = *(float4*)(Bs + k * 128 + 64 + tx * 4);
            float ar[8] = {a0.x, a0.y, a0.z, a0.w, a1.x, a1.y, a1.z, a1.w};
            float br[8] = {b0.x, b0.y, b0.z, b0.w, b1.x, b1.y, b1.z, b1.w};
#pragma unroll
            for (int i = 0; i < 8; i++)
#pragma unroll
                for (int j = 0; j < 8; j++) c[i][j] += ar[i] * br[j];
        }
    }

#pragma unroll
    for (int i = 0; i < 8; i++) {
        int m = m0 + ((i < 4) ? (ty * 4 + i) : (64 + ty * 4 + i - 4));
        float sc = bn[m] * rsqrtf(bn[3 * M + m] + 1e-5f);
        float tt = bn[M + m] - bn[2 * M + m] * sc;
        float4 r0, r1;
        r0.x = c[i][0] * sc + tt; r0.y = c[i][1] * sc + tt;
        r0.z = c[i][2] * sc + tt; r0.w = c[i][3] * sc + tt;
        r1.x = c[i][4] * sc + tt; r1.y = c[i][5] * sc + tt;
        r1.z = c[i][6] * sc + tt; r1.w = c[i][7] * sc + tt;
        float* yp = Yb + (long)m * NTOK + n0;
        *(float4*)(yp + tx * 4)      = r0;
        *(float4*)(yp + 64 + tx * 4) = r1;
    }
}

// ---------------- FA2 attention on mma.sync tf32 ---------------------------
// CTA = (64-query tile, b, h), 256 thr, 8 warps: mi=w>>1 (16 rows), ni=w&1.
// QK 3xTF32; AV 1xTF32 with pair-packed (k, k+4)->adjacent float2 layouts
// for P and V (permutation s(j) = 2*(j&3) + (j>>2), stride 72).
#define SO_KH 0
#define SO_KL 2304
#define SO_V  4608
#define SO_P  13824
#define SO_MP 18432
#define SO_SP 18560
#define SO_MR 18688
#define SO_LR 18816
#define ATTN_SMEM_F 18880

__global__ __launch_bounds__(256) void attn_fa()
{
    extern __shared__ float sm[];
    const int t = threadIdx.x, lane = t & 31, w = t >> 5;
    const int mi = w >> 1, ni = w & 1;
    const int g = lane >> 2, q = lane & 3;
    const int q0 = blockIdx.x * 64;
    const int b = blockIdx.y >> 3, h = blockIdx.y & 7;
    const float* qp = g_q + ((long)b * NHKD + h * KDIM) * NTOK;
    const float* kp = g_k + ((long)b * NHKD + h * KDIM) * NTOK;
    const float* vp = g_v + ((long)b * DHV  + h * DV  ) * NTOK;
    const float SQ = 5.656854249492380f, L2E = 1.44269504088896f;

    // stage Q [32 kd][64 q]*SQ into P area (stride 72)
    {
        int kd = t >> 3, c8 = (t & 7) * 8;
        const float* s = qp + (long)kd * NTOK + q0 + c8;
        float4 u0 = *(const float4*)s, u1 = *(const float4*)(s + 4);
        u0.x *= SQ; u0.y *= SQ; u0.z *= SQ; u0.w *= SQ;
        u1.x *= SQ; u1.y *= SQ; u1.z *= SQ; u1.w *= SQ;
        *(float4*)(sm + SO_P + kd * 72 + c8) = u0;
        *(float4*)(sm + SO_P + kd * 72 + c8 + 4) = u1;
    }
    if (t < 64) { sm[SO_MR + t] = -1e30f; sm[SO_MR + 64 + t] = -1e30f; sm[SO_LR + t] = 0.f; }
    __syncthreads();

    const int r0 = mi * 16 + g;
    uint32_t qh[4][4], ql[4][4];
#pragma unroll
    for (int ks = 0; ks < 4; ks++) {
        float v0 = sm[SO_P + (ks * 8 + q) * 72 + r0];
        float v1 = sm[SO_P + (ks * 8 + q) * 72 + r0 + 8];
        float v2 = sm[SO_P + (ks * 8 + q + 4) * 72 + r0];
        float v3 = sm[SO_P + (ks * 8 + q + 4) * 72 + r0 + 8];
        float h0 = tf32r(v0), h1 = tf32r(v1), h2 = tf32r(v2), h3 = tf32r(v3);
        qh[ks][0] = fb(h0); ql[ks][0] = fb(tf32r(v0 - h0));
        qh[ks][1] = fb(h1); ql[ks][1] = fb(tf32r(v1 - h1));
        qh[ks][2] = fb(h2); ql[ks][2] = fb(tf32r(v2 - h2));
        qh[ks][3] = fb(h3); ql[ks][3] = fb(tf32r(v3 - h3));
    }
    __syncthreads();

    float o[8][4];
#pragma unroll
    for (int nf = 0; nf < 8; nf++)
#pragma unroll
        for (int j = 0; j < 4; j++) o[nf][j] = 0.f;

    const int skd = t >> 3, skv = (t & 7) * 8;   // K staging
    const int svd = t >> 1, svq = (t & 1) * 32;  // V staging
    const int su  = (q & 1) * 4 + (q >> 1);      // P slot for token 2q

    for (int it = 0; it < 16; it++) {
        const int j0 = it * 64;
        __syncthreads();   // prev AV done with V/P
        {
            const float* ks_ = kp + (long)skd * NTOK + j0 + skv;
            float4 u0 = *(const float4*)ks_, u1 = *(const float4*)(ks_ + 4);
            float kr[8] = {u0.x, u0.y, u0.z, u0.w, u1.x, u1.y, u1.z, u1.w};
#pragma unroll
            for (int j = 0; j < 8; j++) {
                float hi = tf32r(kr[j]);
                sm[SO_KH + skd * 72 + skv + j] = hi;
                sm[SO_KL + skd * 72 + skv + j] = tf32r(kr[j] - hi);
            }
            // V: permuted-k pack: slots [0..7] = tokens [0,4,1,5,2,6,3,7]
            const float* vs_ = vp + (long)svd * NTOK + j0 + svq;
#pragma unroll
            for (int grp = 0; grp < 4; grp++) {
                float4 u = *(const float4*)(vs_ + grp * 8);
                float4 v = *(const float4*)(vs_ + grp * 8 + 4);
                u.x = tf32r(u.x); u.y = tf32r(u.y); u.z = tf32r(u.z); u.w = tf32r(u.w);
                v.x = tf32r(v.x); v.y = tf32r(v.y); v.z = tf32r(v.z); v.w = tf32r(v.w);
                float4 A = make_float4(u.x, v.x, u.y, v.y);
                float4 B2 = make_float4(u.z, v.z, u.w, v.w);
                *(float4*)(sm + SO_V + svd * 72 + svq + grp * 8)     = A;
                *(float4*)(sm + SO_V + svd * 72 + svq + grp * 8 + 4) = B2;
            }
        }
        __syncthreads();

        // QK 3xTF32: S[16][32] per warp
        float s4[4][4];
#pragma unroll
        for (int nf = 0; nf < 4; nf++)
#pragma unroll
            for (int j = 0; j < 4; j++) s4[nf][j] = 0.f;
#pragma unroll
        for (int ks = 0; ks < 4; ks++) {
            int kd0 = ks * 8 + q;
#pragma unroll
            for (int nf = 0; nf < 4; nf++) {
                int col = ni * 32 + nf * 8 + g;
                uint32_t bh0 = fb(sm[SO_KH + kd0 * 72 + col]);
                uint32_t bh1 = fb(sm[SO_KH + (kd0 + 4) * 72 + col]);
                uint32_t bl0 = fb(sm[SO_KL + kd0 * 72 + col]);
                uint32_t bl1 = fb(sm[SO_KL + (kd0 + 4) * 72 + col]);
                mma8(s4[nf], qh[ks], bh0, bh1);
                mma8(s4[nf], qh[ks], bl0, bl1);
                mma8(s4[nf], ql[ks], bh0, bh1);
            }
        }

        // warp-local row max -> MP
        {
            float m0 = fmaxf(fmaxf(s4[0][0], s4[0][1]), fmaxf(s4[1][0], s4[1][1]));
            m0 = fmaxf(m0, fmaxf(fmaxf(s4[2][0], s4[2][1]), fmaxf(s4[3][0], s4[3][1])));
            float m1 = fmaxf(fmaxf(s4[0][2], s4[0][3]), fmaxf(s4[1][2], s4[1][3]));
            m1 = fmaxf(m1, fmaxf(fmaxf(s4[2][2], s4[2][3]), fmaxf(s4[3][2], s4[3][3])));
            m0 = fmaxf(m0, __shfl_xor_sync(0xffffffffu, m0, 1));
            m0 = fmaxf(m0, __shfl_xor_sync(0xffffffffu, m0, 2));
            m1 = fmaxf(m1, __shfl_xor_sync(0xffffffffu, m1, 1));
            m1 = fmaxf(m1, __shfl_xor_sync(0xffffffffu, m1, 2));
            if (q == 0) {
                sm[SO_MP + ni * 64 + r0] = m0;
                sm[SO_MP + ni * 64 + r0 + 8] = m1;
            }
        }
        __syncthreads();

        // new max, alpha, P (rounded, permuted store), partial sums, O rescale
        {
            float moA = sm[SO_MR + (it & 1) * 64 + r0];
            float moB = sm[SO_MR + (it & 1) * 64 + r0 + 8];
            float mn0 = fmaxf(moA, fmaxf(sm[SO_MP + r0], sm[SO_MP + 64 + r0]));
            float mn1 = fmaxf(moB, fmaxf(sm[SO_MP + r0 + 8], sm[SO_MP + 64 + r0 + 8]));
            if (ni == 0 && q == 0) {
                sm[SO_MR + ((it + 1) & 1) * 64 + r0] = mn0;
                sm[SO_MR + ((it + 1) & 1) * 64 + r0 + 8] = mn1;
            }
            float al0 = fexp2((moA - mn0) * L2E);
            float al1 = fexp2((moB - mn1) * L2E);
            float c0 = -mn0 * L2E, c1 = -mn1 * L2E;
            float rs0 = 0.f, rs1 = 0.f;
#pragma unroll
            for (int nf = 0; nf < 4; nf++) {
                int colu = ni * 32 + nf * 8 + su;
                float e00 = tf32r(fexp2(fmaf(s4[nf][0], L2E, c0)));
                float e01 = tf32r(fexp2(fmaf(s4[nf][1], L2E, c0)));
                float e10 = tf32r(fexp2(fmaf(s4[nf][2], L2E, c1)));
                float e11 = tf32r(fexp2(fmaf(s4[nf][3], L2E, c1)));
                rs0 += e00 + e01; rs1 += e10 + e11;
                sm[SO_P + r0 * 72 + colu]           = e00;
                sm[SO_P + r0 * 72 + colu + 2]       = e01;
                sm[SO_P + (r0 + 8) * 72 + colu]     = e10;
                sm[SO_P + (r0 + 8) * 72 + colu + 2] = e11;
            }
            rs0 += __shfl_xor_sync(0xffffffffu, rs0, 1);
            rs0 += __shfl_xor_sync(0xffffffffu, rs0, 2);
            rs1 += __shfl_xor_sync(0xffffffffu, rs1, 1);
            rs1 += __shfl_xor_sync(0xffffffffu, rs1, 2);
            if (q == 0) {
                sm[SO_SP + ni * 64 + r0] = rs0;
                sm[SO_SP + ni * 64 + r0 + 8] = rs1;
            }
#pragma unroll
            for (int nf = 0; nf < 8; nf++) {
                o[nf][0] *= al0; o[nf][1] *= al0;
                o[nf][2] *= al1; o[nf][3] *= al1;
            }
        }
        __syncthreads();

        // l update (concurrent with AV)
        if (t < 64) {
            float mo = sm[SO_MR + (it & 1) * 64 + t];
            float mn = sm[SO_MR + ((it + 1) & 1) * 64 + t];
            sm[SO_LR + t] = sm[SO_LR + t] * fexp2((mo - mn) * L2E)
                          + sm[SO_SP + t] + sm[SO_SP + 64 + t];
        }

        // AV 1xTF32, pair-packed float2 loads
#pragma unroll
        for (int ks = 0; ks < 8; ks++) {
            float2 pa0 = *(float2*)(sm + SO_P + r0 * 72 + ks * 8 + 2 * q);
            float2 pa1 = *(float2*)(sm + SO_P + (r0 + 8) * 72 + ks * 8 + 2 * q);
            uint32_t a[4] = {fb(pa0.x), fb(pa1.x), fb(pa0.y), fb(pa1.y)};
#pragma unroll
            for (int nf = 0; nf < 8; nf++) {
                int d = ni * 64 + nf * 8 + g;
                float2 bv = *(float2*)(sm + SO_V + d * 72 + ks * 8 + 2 * q);
                mma8(o[nf], a, fb(bv.x), fb(bv.y));
            }
        }
    }

    // epilogue: normalize, transpose via smem (reuse V area), coalesced store
    __syncthreads();
    {
        float inv0 = 1.0f / sm[SO_LR + r0];
        float inv1 = 1.0f / sm[SO_LR + r0 + 8];
#pragma unroll
        for (int nf = 0; nf < 8; nf++) {
            int d = ni * 64 + nf * 8 + 2 * q;
            sm[SO_V + d * 72 + r0]           = o[nf][0] * inv0;
            sm[SO_V + (d + 1) * 72 + r0]     = o[nf][1] * inv0;
            sm[SO_V + d * 72 + r0 + 8]       = o[nf][2] * inv1;
            sm[SO_V + (d + 1) * 72 + r0 + 8] = o[nf][3] * inv1;
        }
    }
    __syncthreads();
    {
        int d = t >> 1, qq = (t & 1) * 32;
        float* dst = g_xx + ((long)b * DHV + h * DV + d) * NTOK + q0 + qq;
#pragma unroll
        for (int p = 0; p < 8; p++)
            *(float4*)(dst + p * 4) = *(const float4*)(sm + SO_V + d * 72 + qq + p * 4);
    }
}

// ---------------------------------------------------------------------------
extern "C" void kernel_launch(void* const* d_in, const int* in_sizes, int n_in,
                              void* d_out, int out_size)
{
    const float* x   = (const float*)d_in[0];
    const float* wq  = (const float*)d_in[1];
    const float* bnq = (const float*)d_in[2];
    const float* wk  = (const float*)d_in[3];
    const float* bnk = (const float*)d_in[4];
    const float* wv  = (const float*)d_in[5];
    const float* bnv = (const float*)d_in[6];
    const float* wp  = (const float*)d_in[7];
    const float* bnp = (const float*)d_in[8];
    float* out = (float*)d_out;

    float *qs, *ks, *vs, *xxs;
    cudaGetSymbolAddress((void**)&qs,  g_q);
    cudaGetSymbolAddress((void**)&ks,  g_k);
    cudaGetSymbolAddress((void**)&vs,  g_v);
    cudaGetSymbolAddress((void**)&xxs, g_xx);

    const int smem_attn = ATTN_SMEM_F * 4;   // 75520 B
    cudaFuncSetAttribute(attn_fa, cudaFuncAttributeMaxDynamicSharedMemorySize,
                         smem_attn);
    dim3 blk(256);

    gemm_bn128<<<dim3(8, NHKD / 128, BB), blk>>>(
        wq, bnq, x, qs, NHKD, DIM, (long)DIM * NTOK, (long)NHKD * NTOK);
    gemm_bn128<<<dim3(8, NHKD / 128, BB), blk>>>(
        wk, bnk, x, ks, NHKD, DIM, (long)DIM * NTOK, (long)NHKD * NTOK);
    gemm_bn128<<<dim3(8, DHV / 128, BB), blk>>>(
        wv, bnv, x, vs, DHV, DIM, (long)DIM * NTOK, (long)DHV * NTOK);

    attn_fa<<<dim3(NTOK / 64, BB * NH), blk, smem_attn>>>();

    gemm_bn128<<<dim3(8, DIM / 128, BB), blk>>>(
        wp, bnp, xxs, out, DIM, DHV, (long)DHV * NTOK, (long)DIM * NTOK);
}

// round 8
// speedup vs baseline: 3.0711x; 1.1019x over previous
#include <cuda_runtime.h>
#include <cuda_fp16.h>
#include <cstdint>
#include <math.h>

#define BB   16
#define DIM  384
#define NHKD 256
#define DHV  1024
#define NTOK 1024
#define NH   8
#define KDIM 32
#define DV   128

__device__ float g_q [BB * NHKD * NTOK];
__device__ float g_k [BB * NHKD * NTOK];
__device__ float g_v [BB * DHV  * NTOK];
__device__ float g_xx[BB * DHV  * NTOK];

__device__ __forceinline__ void mma16(float c[4], const uint32_t a[4],
                                      uint32_t b0, uint32_t b1) {
    asm volatile("mma.sync.aligned.m16n8k16.row.col.f32.f16.f16.f32 "
        "{%0,%1,%2,%3}, {%4,%5,%6,%7}, {%8,%9}, {%0,%1,%2,%3};"
        : "+f"(c[0]), "+f"(c[1]), "+f"(c[2]), "+f"(c[3])
        : "r"(a[0]), "r"(a[1]), "r"(a[2]), "r"(a[3]), "r"(b0), "r"(b1));
}

// pack two floats to half2 (x0 -> low, x1 -> high)
__device__ __forceinline__ uint32_t pack2(float x0, float x1) {
    __half2 h = __floats2half2_rn(x0, x1);
    return *(uint32_t*)&h;
}
// fp16 hi/lo split of a float pair
__device__ __forceinline__ void splitpack(float x0, float x1,
                                          uint32_t& h, uint32_t& l) {
    __half2 hh = __floats2half2_rn(x0, x1);
    float2 bk = __half22float2(hh);
    __half2 ll = __floats2half2_rn(x0 - bk.x, x1 - bk.y);
    h = *(uint32_t*)&hh;
    l = *(uint32_t*)&ll;
}

// 2^z on FMA pipe, z <= 0 (clamped at -100). deg-5 poly.
__device__ __forceinline__ float fexp2(float z) {
    z = fmaxf(z, -100.0f);
    float zi = z + 12582912.0f;
    int   n  = __float_as_int(zi) - 0x4B400000;
    float t  = z - (zi - 12582912.0f);
    float p = fmaf(0.0013333558f, t, 0.0096181291f);
    p = fmaf(p, t, 0.0555041087f);
    p = fmaf(p, t, 0.2402265069f);
    p = fmaf(p, t, 0.6931471806f);
    p = fmaf(p, t, 1.0f);
    return __int_as_float(__float_as_int(p) + (n << 23));
}

// ---------------- exact FFMA GEMM+BN, 128x128 tile, 8x8/thread -------------
__global__ __launch_bounds__(256) void gemm_bn128(
    const float* __restrict__ W, const float* __restrict__ bn,
    const float* __restrict__ X, float* __restrict__ Y,
    int M, int K, long xStride, long yStride)
{
    __shared__ float As[16 * 132];
    __shared__ float Bs[16 * 128];
    const int t = threadIdx.x, tx = t & 15, ty = t >> 4;
    const int n0 = blockIdx.x * 128, m0 = blockIdx.y * 128;
    const float* Xb = X + (long)blockIdx.z * xStride;
    float*       Yb = Y + (long)blockIdx.z * yStride;
    const int am = t & 127, akh = (t >> 7) * 8;
    const int bk = t >> 4,  bn8 = (t & 15) * 8;

    float c[8][8];
#pragma unroll
    for (int i = 0; i < 8; i++)
#pragma unroll
        for (int j = 0; j < 8; j++) c[i][j] = 0.f;

    for (int kt = 0; kt < K; kt += 16) {
        const float* wp_ = W + (long)(m0 + am) * K + kt + akh;
        float4 w0 = *(const float4*)wp_;
        float4 w1 = *(const float4*)(wp_ + 4);
        const float* xp_ = Xb + (long)(kt + bk) * NTOK + n0 + bn8;
        float4 x0 = *(const float4*)xp_;
        float4 x1 = *(const float4*)(xp_ + 4);
        __syncthreads();
        As[(akh + 0) * 132 + am] = w0.x;
        As[(akh + 1) * 132 + am] = w0.y;
        As[(akh + 2) * 132 + am] = w0.z;
        As[(akh + 3) * 132 + am] = w0.w;
        As[(akh + 4) * 132 + am] = w1.x;
        As[(akh + 5) * 132 + am] = w1.y;
        As[(akh + 6) * 132 + am] = w1.z;
        As[(akh + 7) * 132 + am] = w1.w;
        *(float4*)(Bs + bk * 128 + bn8)     = x0;
        *(float4*)(Bs + bk * 128 + bn8 + 4) = x1;
        __syncthreads();
#pragma unroll
        for (int k = 0; k < 16; k++) {
            float4 a0 = *(float4*)(As + k * 132 + ty * 4);
            float4 a1 = *(float4*)(As + k * 132 + 64 + ty * 4);
            float4 b0 = *(float4*)(Bs + k * 128 + tx * 4);
            float4 b1 = *(float4*)(Bs + k * 128 + 64 + tx * 4);
            float ar[8] = {a0.x, a0.y, a0.z, a0.w, a1.x, a1.y, a1.z, a1.w};
            float br[8] = {b0.x, b0.y, b0.z, b0.w, b1.x, b1.y, b1.z, b1.w};
#pragma unroll
            for (int i = 0; i < 8; i++)
#pragma unroll
                for (int j = 0; j < 8; j++) c[i][j] += ar[i] * br[j];
        }
    }

#pragma unroll
    for (int i = 0; i < 8; i++) {
        int m = m0 + ((i < 4) ? (ty * 4 + i) : (64 + ty * 4 + i - 4));
        float sc = bn[m] * rsqrtf(bn[3 * M + m] + 1e-5f);
        float tt = bn[M + m] - bn[2 * M + m] * sc;
        float4 r0, r1;
        r0.x = c[i][0] * sc + tt; r0.y = c[i][1] * sc + tt;
        r0.z = c[i][2] * sc + tt; r0.w = c[i][3] * sc + tt;
        r1.x = c[i][4] * sc + tt; r1.y = c[i][5] * sc + tt;
        r1.z = c[i][6] * sc + tt; r1.w = c[i][7] * sc + tt;
        float* yp = Yb + (long)m * NTOK + n0;
        *(float4*)(yp + tx * 4)      = r0;
        *(float4*)(yp + 64 + tx * 4) = r1;
    }
}

// ---------------- FA2 attention, fp16 m16n8k16 ------------------------------
// CTA = (64-query tile, b, h), 256 thr, 8 warps (mi = w>>1, ni = w&1).
// QK: 2x-split fp16 (QhKh + QhKl + QlKh) -> ~2^-21 logits.
// AV: P single fp16 (2^-11), V hi/lo fp16 split (~exact).
// smem (floats/uint32): KH[16*72] KL | VH[128*36] VL | P[64*36](=Qstage 32*72)
//                       MP[128] SP[128] MR[128] LR[64]
#define F_KH 0
#define F_KL 1152
#define F_VH 2304
#define F_VL 6912
#define F_P  11520
#define F_MP 13824
#define F_SP 13952
#define F_MR 14080
#define F_LR 14208
#define ATTN_SMEM_F 14272   // 57088 B

__global__ __launch_bounds__(256) void attn_fa()
{
    extern __shared__ float sm[];
    uint32_t* smu = (uint32_t*)sm;
    const int t = threadIdx.x, lane = t & 31, w = t >> 5;
    const int mi = w >> 1, ni = w & 1;
    const int g = lane >> 2, q = lane & 3;
    const int q0 = blockIdx.x * 64;
    const int b = blockIdx.y >> 3, h = blockIdx.y & 7;
    const float* qp = g_q + ((long)b * NHKD + h * KDIM) * NTOK;
    const float* kp = g_k + ((long)b * NHKD + h * KDIM) * NTOK;
    const float* vp = g_v + ((long)b * DHV  + h * DV  ) * NTOK;
    const float SQ = 5.656854249492380f, L2E = 1.44269504088896f;

    // stage Q [32 kd][64 q]*SQ into P area (float, stride 72)
    {
        int kd = t >> 3, c8 = (t & 7) * 8;
        const float* s = qp + (long)kd * NTOK + q0 + c8;
        float4 u0 = *(const float4*)s, u1 = *(const float4*)(s + 4);
        u0.x *= SQ; u0.y *= SQ; u0.z *= SQ; u0.w *= SQ;
        u1.x *= SQ; u1.y *= SQ; u1.z *= SQ; u1.w *= SQ;
        *(float4*)(sm + F_P + kd * 72 + c8)     = u0;
        *(float4*)(sm + F_P + kd * 72 + c8 + 4) = u1;
    }
    if (t < 64) { sm[F_MR + t] = -1e30f; sm[F_MR + 64 + t] = -1e30f; sm[F_LR + t] = 0.f; }
    __syncthreads();

    // Q fragments (A row-major m16n8k16), fp16 hi/lo, built once
    const int r0 = mi * 16 + g;
    uint32_t qh[2][4], ql[2][4];
#pragma unroll
    for (int s = 0; s < 2; s++) {
        int kd0 = 16 * s + 2 * q;
        const float* Q = sm + F_P;
        splitpack(Q[kd0 * 72 + r0],           Q[(kd0 + 1) * 72 + r0],     qh[s][0], ql[s][0]);
        splitpack(Q[kd0 * 72 + r0 + 8],       Q[(kd0 + 1) * 72 + r0 + 8], qh[s][1], ql[s][1]);
        splitpack(Q[(kd0 + 8) * 72 + r0],     Q[(kd0 + 9) * 72 + r0],     qh[s][2], ql[s][2]);
        splitpack(Q[(kd0 + 8) * 72 + r0 + 8], Q[(kd0 + 9) * 72 + r0 + 8], qh[s][3], ql[s][3]);
    }
    __syncthreads();   // P area free

    float o[8][4];
#pragma unroll
    for (int nf = 0; nf < 8; nf++)
#pragma unroll
        for (int j = 0; j < 4; j++) o[nf][j] = 0.f;

    const int kpair = t >> 4, ktok4 = (t & 15) * 4;   // K staging
    const int vd = t >> 1, vtb = (t & 1) * 32;        // V staging

    for (int it = 0; it < 16; it++) {
        const int j0 = it * 64;
        __syncthreads();   // prev AV done with V/P
        {
            // K: pairs of kd rows -> half2 per token, SW-free uint4 stores
            const float* k0 = kp + (long)(2 * kpair) * NTOK + j0 + ktok4;
            float4 a4 = *(const float4*)k0;
            float4 b4 = *(const float4*)(k0 + NTOK);
            uint32_t hh[4], ll[4];
            splitpack(a4.x, b4.x, hh[0], ll[0]);
            splitpack(a4.y, b4.y, hh[1], ll[1]);
            splitpack(a4.z, b4.z, hh[2], ll[2]);
            splitpack(a4.w, b4.w, hh[3], ll[3]);
            *(uint4*)(smu + F_KH + kpair * 72 + ktok4) = make_uint4(hh[0], hh[1], hh[2], hh[3]);
            *(uint4*)(smu + F_KL + kpair * 72 + ktok4) = make_uint4(ll[0], ll[1], ll[2], ll[3]);
            // V: [d][tok] -> half2 token pairs, hi/lo
            const float* vs_ = vp + (long)vd * NTOK + j0 + vtb;
#pragma unroll
            for (int jj = 0; jj < 4; jj++) {
                float4 u = *(const float4*)(vs_ + jj * 8);
                float4 v = *(const float4*)(vs_ + jj * 8 + 4);
                uint32_t h0, h1, h2, h3, l0, l1, l2, l3;
                splitpack(u.x, u.y, h0, l0);
                splitpack(u.z, u.w, h1, l1);
                splitpack(v.x, v.y, h2, l2);
                splitpack(v.z, v.w, h3, l3);
                *(uint4*)(smu + F_VH + vd * 36 + (t & 1) * 16 + jj * 4) = make_uint4(h0, h1, h2, h3);
                *(uint4*)(smu + F_VL + vd * 36 + (t & 1) * 16 + jj * 4) = make_uint4(l0, l1, l2, l3);
            }
        }
        __syncthreads();

        // QK (2x-split fp16): S[16][32] per warp
        float s4[4][4];
#pragma unroll
        for (int nf = 0; nf < 4; nf++)
#pragma unroll
            for (int j = 0; j < 4; j++) s4[nf][j] = 0.f;
#pragma unroll
        for (int s = 0; s < 2; s++) {
#pragma unroll
            for (int nf = 0; nf < 4; nf++) {
                int col = ni * 32 + nf * 8 + g;
                uint32_t bh0 = smu[F_KH + (8 * s + q) * 72 + col];
                uint32_t bh1 = smu[F_KH + (8 * s + q + 4) * 72 + col];
                uint32_t bl0 = smu[F_KL + (8 * s + q) * 72 + col];
                uint32_t bl1 = smu[F_KL + (8 * s + q + 4) * 72 + col];
                mma16(s4[nf], qh[s], bh0, bh1);
                mma16(s4[nf], qh[s], bl0, bl1);
                mma16(s4[nf], ql[s], bh0, bh1);
            }
        }

        // warp-local row max -> MP
        {
            float m0 = fmaxf(fmaxf(s4[0][0], s4[0][1]), fmaxf(s4[1][0], s4[1][1]));
            m0 = fmaxf(m0, fmaxf(fmaxf(s4[2][0], s4[2][1]), fmaxf(s4[3][0], s4[3][1])));
            float m1 = fmaxf(fmaxf(s4[0][2], s4[0][3]), fmaxf(s4[1][2], s4[1][3]));
            m1 = fmaxf(m1, fmaxf(fmaxf(s4[2][2], s4[2][3]), fmaxf(s4[3][2], s4[3][3])));
            m0 = fmaxf(m0, __shfl_xor_sync(0xffffffffu, m0, 1));
            m0 = fmaxf(m0, __shfl_xor_sync(0xffffffffu, m0, 2));
            m1 = fmaxf(m1, __shfl_xor_sync(0xffffffffu, m1, 1));
            m1 = fmaxf(m1, __shfl_xor_sync(0xffffffffu, m1, 2));
            if (q == 0) {
                sm[F_MP + ni * 64 + r0] = m0;
                sm[F_MP + ni * 64 + r0 + 8] = m1;
            }
        }
        __syncthreads();

        // new max, alpha, P (fp16 half2), partial sums, O rescale
        {
            float moA = sm[F_MR + (it & 1) * 64 + r0];
            float moB = sm[F_MR + (it & 1) * 64 + r0 + 8];
            float mn0 = fmaxf(moA, fmaxf(sm[F_MP + r0], sm[F_MP + 64 + r0]));
            float mn1 = fmaxf(moB, fmaxf(sm[F_MP + r0 + 8], sm[F_MP + 64 + r0 + 8]));
            if (ni == 0 && q == 0) {
                sm[F_MR + ((it + 1) & 1) * 64 + r0] = mn0;
                sm[F_MR + ((it + 1) & 1) * 64 + r0 + 8] = mn1;
            }
            float al0 = fexp2((moA - mn0) * L2E);
            float al1 = fexp2((moB - mn1) * L2E);
            float c0 = -mn0 * L2E, c1 = -mn1 * L2E;
            float rs0 = 0.f, rs1 = 0.f;
#pragma unroll
            for (int nf = 0; nf < 4; nf++) {
                int colp = ni * 16 + nf * 4 + q;
                float e00 = fexp2(fmaf(s4[nf][0], L2E, c0));
                float e01 = fexp2(fmaf(s4[nf][1], L2E, c0));
                float e10 = fexp2(fmaf(s4[nf][2], L2E, c1));
                float e11 = fexp2(fmaf(s4[nf][3], L2E, c1));
                rs0 += e00 + e01; rs1 += e10 + e11;
                smu[F_P + r0 * 36 + colp]       = pack2(e00, e01);
                smu[F_P + (r0 + 8) * 36 + colp] = pack2(e10, e11);
            }
            rs0 += __shfl_xor_sync(0xffffffffu, rs0, 1);
            rs0 += __shfl_xor_sync(0xffffffffu, rs0, 2);
            rs1 += __shfl_xor_sync(0xffffffffu, rs1, 1);
            rs1 += __shfl_xor_sync(0xffffffffu, rs1, 2);
            if (q == 0) {
                sm[F_SP + ni * 64 + r0] = rs0;
                sm[F_SP + ni * 64 + r0 + 8] = rs1;
            }
#pragma unroll
            for (int nf = 0; nf < 8; nf++) {
                o[nf][0] *= al0; o[nf][1] *= al0;
                o[nf][2] *= al1; o[nf][3] *= al1;
            }
        }
        __syncthreads();

        // l update (concurrent with AV)
        if (t < 64) {
            float mo = sm[F_MR + (it & 1) * 64 + t];
            float mn = sm[F_MR + ((it + 1) & 1) * 64 + t];
            sm[F_LR + t] = sm[F_LR + t] * fexp2((mo - mn) * L2E)
                         + sm[F_SP + t] + sm[F_SP + 64 + t];
        }

        // AV fp16: P single, V hi+lo
#pragma unroll
        for (int s = 0; s < 4; s++) {
            uint32_t a[4];
            a[0] = smu[F_P + r0 * 36 + 8 * s + q];
            a[1] = smu[F_P + (r0 + 8) * 36 + 8 * s + q];
            a[2] = smu[F_P + r0 * 36 + 8 * s + q + 4];
            a[3] = smu[F_P + (r0 + 8) * 36 + 8 * s + q + 4];
#pragma unroll
            for (int nf = 0; nf < 8; nf++) {
                int d = ni * 64 + nf * 8 + g;
                uint32_t bh0 = smu[F_VH + d * 36 + 8 * s + q];
                uint32_t bh1 = smu[F_VH + d * 36 + 8 * s + q + 4];
                uint32_t bl0 = smu[F_VL + d * 36 + 8 * s + q];
                uint32_t bl1 = smu[F_VL + d * 36 + 8 * s + q + 4];
                mma16(o[nf], a, bh0, bh1);
                mma16(o[nf], a, bl0, bl1);
            }
        }
    }

    // epilogue: normalize, transpose via smem (reuse VH+VL as [128][72] f32)
    __syncthreads();
    {
        float inv0 = 1.0f / sm[F_LR + r0];
        float inv1 = 1.0f / sm[F_LR + r0 + 8];
#pragma unroll
        for (int nf = 0; nf < 8; nf++) {
            int d = ni * 64 + nf * 8 + 2 * q;
            sm[F_VH + d * 72 + r0]           = o[nf][0] * inv0;
            sm[F_VH + (d + 1) * 72 + r0]     = o[nf][1] * inv0;
            sm[F_VH + d * 72 + r0 + 8]       = o[nf][2] * inv1;
            sm[F_VH + (d + 1) * 72 + r0 + 8] = o[nf][3] * inv1;
        }
    }
    __syncthreads();
    {
        int d = t >> 1, qq = (t & 1) * 32;
        float* dst = g_xx + ((long)b * DHV + h * DV + d) * NTOK + q0 + qq;
#pragma unroll
        for (int p = 0; p < 8; p++)
            *(float4*)(dst + p * 4) = *(const float4*)(sm + F_VH + d * 72 + qq + p * 4);
    }
}

// ---------------------------------------------------------------------------
extern "C" void kernel_launch(void* const* d_in, const int* in_sizes, int n_in,
                              void* d_out, int out_size)
{
    const float* x   = (const float*)d_in[0];
    const float* wq  = (const float*)d_in[1];
    const float* bnq = (const float*)d_in[2];
    const float* wk  = (const float*)d_in[3];
    const float* bnk = (const float*)d_in[4];
    const float* wv  = (const float*)d_in[5];
    const float* bnv = (const float*)d_in[6];
    const float* wp  = (const float*)d_in[7];
    const float* bnp = (const float*)d_in[8];
    float* out = (float*)d_out;

    float *qs, *ks, *vs, *xxs;
    cudaGetSymbolAddress((void**)&qs,  g_q);
    cudaGetSymbolAddress((void**)&ks,  g_k);
    cudaGetSymbolAddress((void**)&vs,  g_v);
    cudaGetSymbolAddress((void**)&xxs, g_xx);

    const int smem_attn = ATTN_SMEM_F * 4;   // 57088 B
    cudaFuncSetAttribute(attn_fa, cudaFuncAttributeMaxDynamicSharedMemorySize,
                         smem_attn);
    dim3 blk(256);

    gemm_bn128<<<dim3(8, NHKD / 128, BB), blk>>>(
        wq, bnq, x, qs, NHKD, DIM, (long)DIM * NTOK, (long)NHKD * NTOK);
    gemm_bn128<<<dim3(8, NHKD / 128, BB), blk>>>(
        wk, bnk, x, ks, NHKD, DIM, (long)DIM * NTOK, (long)NHKD * NTOK);
    gemm_bn128<<<dim3(8, DHV / 128, BB), blk>>>(
        wv, bnv, x, vs, DHV, DIM, (long)DIM * NTOK, (long)DHV * NTOK);

    attn_fa<<<dim3(NTOK / 64, BB * NH), blk, smem_attn>>>();

    gemm_bn128<<<dim3(8, DIM / 128, BB), blk>>>(
        wp, bnp, xxs, out, DIM, DHV, (long)DHV * NTOK, (long)DIM * NTOK);
}

// round 9
// speedup vs baseline: 3.3845x; 1.1020x over previous
#include <cuda_runtime.h>
#include <cuda_fp16.h>
#include <cstdint>
#include <math.h>

#define BB   16
#define DIM  384
#define NHKD 256
#define DHV  1024
#define NTOK 1024
#define NH   8
#define KDIM 32
#define DV   128

__device__ float g_q [BB * NHKD * NTOK];
__device__ float g_k [BB * NHKD * NTOK];
__device__ float g_v [BB * DHV  * NTOK];
__device__ float g_xx[BB * DHV  * NTOK];

__device__ __forceinline__ void mma16(float c[4], const uint32_t a[4],
                                      uint32_t b0, uint32_t b1) {
    asm volatile("mma.sync.aligned.m16n8k16.row.col.f32.f16.f16.f32 "
        "{%0,%1,%2,%3}, {%4,%5,%6,%7}, {%8,%9}, {%0,%1,%2,%3};"
        : "+f"(c[0]), "+f"(c[1]), "+f"(c[2]), "+f"(c[3])
        : "r"(a[0]), "r"(a[1]), "r"(a[2]), "r"(a[3]), "r"(b0), "r"(b1));
}

__device__ __forceinline__ uint32_t pack2(float x0, float x1) {
    __half2 h = __floats2half2_rn(x0, x1);
    return *(uint32_t*)&h;
}
__device__ __forceinline__ void splitpack(float x0, float x1,
                                          uint32_t& h, uint32_t& l) {
    __half2 hh = __floats2half2_rn(x0, x1);
    float2 bk = __half22float2(hh);
    __half2 ll = __floats2half2_rn(x0 - bk.x, x1 - bk.y);
    h = *(uint32_t*)&hh;
    l = *(uint32_t*)&ll;
}

// 2^z on FMA pipe, z <= 0 (clamped at -100). deg-5 poly.
__device__ __forceinline__ float fexp2(float z) {
    z = fmaxf(z, -100.0f);
    float zi = z + 12582912.0f;
    int   n  = __float_as_int(zi) - 0x4B400000;
    float t  = z - (zi - 12582912.0f);
    float p = fmaf(0.0013333558f, t, 0.0096181291f);
    p = fmaf(p, t, 0.0555041087f);
    p = fmaf(p, t, 0.2402265069f);
    p = fmaf(p, t, 0.6931471806f);
    p = fmaf(p, t, 1.0f);
    return __int_as_float(__float_as_int(p) + (n << 23));
}

// ================= exact FFMA GEMM+BN body (128x128, 8x8/thr) ==============
__device__ __forceinline__ void gemm_body(
    const float* __restrict__ W, const float* __restrict__ bn,
    const float* __restrict__ Xb, float* __restrict__ Yb,
    int M, int K, int m0, int n0, float* As, float* Bs)
{
    const int t = threadIdx.x, tx = t & 15, ty = t >> 4;
    const int am = t & 127, akh = (t >> 7) * 8;
    const int bk = t >> 4,  bn8 = (t & 15) * 8;

    float c[8][8];
#pragma unroll
    for (int i = 0; i < 8; i++)
#pragma unroll
        for (int j = 0; j < 8; j++) c[i][j] = 0.f;

    for (int kt = 0; kt < K; kt += 16) {
        const float* wp_ = W + (long)(m0 + am) * K + kt + akh;
        float4 w0 = *(const float4*)wp_;
        float4 w1 = *(const float4*)(wp_ + 4);
        const float* xp_ = Xb + (long)(kt + bk) * NTOK + n0 + bn8;
        float4 x0 = *(const float4*)xp_;
        float4 x1 = *(const float4*)(xp_ + 4);
        __syncthreads();
        As[(akh + 0) * 132 + am] = w0.x;
        As[(akh + 1) * 132 + am] = w0.y;
        As[(akh + 2) * 132 + am] = w0.z;
        As[(akh + 3) * 132 + am] = w0.w;
        As[(akh + 4) * 132 + am] = w1.x;
        As[(akh + 5) * 132 + am] = w1.y;
        As[(akh + 6) * 132 + am] = w1.z;
        As[(akh + 7) * 132 + am] = w1.w;
        *(float4*)(Bs + bk * 128 + bn8)     = x0;
        *(float4*)(Bs + bk * 128 + bn8 + 4) = x1;
        __syncthreads();
#pragma unroll
        for (int k = 0; k < 16; k++) {
            float4 a0 = *(float4*)(As + k * 132 + ty * 4);
            float4 a1 = *(float4*)(As + k * 132 + 64 + ty * 4);
            float4 b0 = *(float4*)(Bs + k * 128 + tx * 4);
            float4 b1 = *(float4*)(Bs + k * 128 + 64 + tx * 4);
            float ar[8] = {a0.x, a0.y, a0.z, a0.w, a1.x, a1.y, a1.z, a1.w};
            float br[8] = {b0.x, b0.y, b0.z, b0.w, b1.x, b1.y, b1.z, b1.w};
#pragma unroll
            for (int i = 0; i < 8; i++)
#pragma unroll
                for (int j = 0; j < 8; j++) c[i][j] += ar[i] * br[j];
        }
    }

#pragma unroll
    for (int i = 0; i < 8; i++) {
        int m = m0 + ((i < 4) ? (ty * 4 + i) : (64 + ty * 4 + i - 4));
        float sc = bn[m] * rsqrtf(bn[3 * M + m] + 1e-5f);
        float tt = bn[M + m] - bn[2 * M + m] * sc;
        float4 r0, r1;
        r0.x = c[i][0] * sc + tt; r0.y = c[i][1] * sc + tt;
        r0.z = c[i][2] * sc + tt; r0.w = c[i][3] * sc + tt;
        r1.x = c[i][4] * sc + tt; r1.y = c[i][5] * sc + tt;
        r1.z = c[i][6] * sc + tt; r1.w = c[i][7] * sc + tt;
        float* yp = Yb + (long)m * NTOK + n0;
        *(float4*)(yp + tx * 4)      = r0;
        *(float4*)(yp + 64 + tx * 4) = r1;
    }
}

// Fused QKV projection: blockIdx.y 0-1 -> Q, 2-3 -> K, 4-11 -> V
__global__ __launch_bounds__(256) void gemm_qkv(
    const float* __restrict__ x,
    const float* __restrict__ wq, const float* __restrict__ bnq,
    const float* __restrict__ wk, const float* __restrict__ bnk,
    const float* __restrict__ wv, const float* __restrict__ bnv,
    float* __restrict__ yq, float* __restrict__ yk, float* __restrict__ yv)
{
    __shared__ float As[16 * 132];
    __shared__ float Bs[16 * 128];
    const int y = blockIdx.y;
    const float *W, *bn;
    float* Y;
    int M, m0;
    if (y < 2)      { W = wq; bn = bnq; Y = yq; M = NHKD; m0 = y * 128; }
    else if (y < 4) { W = wk; bn = bnk; Y = yk; M = NHKD; m0 = (y - 2) * 128; }
    else            { W = wv; bn = bnv; Y = yv; M = DHV;  m0 = (y - 4) * 128; }
    gemm_body(W, bn, x + (long)blockIdx.z * DIM * NTOK,
              Y + (long)blockIdx.z * M * NTOK,
              M, DIM, m0, blockIdx.x * 128, As, Bs);
}

// Output projection
__global__ __launch_bounds__(256) void gemm_proj(
    const float* __restrict__ wp, const float* __restrict__ bnp,
    float* __restrict__ out)
{
    __shared__ float As[16 * 132];
    __shared__ float Bs[16 * 128];
    gemm_body(wp, bnp, g_xx + (long)blockIdx.z * DHV * NTOK,
              out + (long)blockIdx.z * DIM * NTOK,
              DIM, DHV, blockIdx.y * 128, blockIdx.x * 128, As, Bs);
}

// ---------------- FA2 attention, fp16 m16n8k16 ------------------------------
// QK: 2x-split fp16 (QhKh + QhKl + QlKh); AV: P single fp16, V single fp16.
#define F_KH 0
#define F_KL 1152
#define F_VH 2304
#define F_P  6912
#define F_MP 9216
#define F_SP 9344
#define F_MR 9472
#define F_LR 9600
#define ATTN_SMEM_F 9664   // 38656 B

__global__ __launch_bounds__(256) void attn_fa()
{
    extern __shared__ float sm[];
    uint32_t* smu = (uint32_t*)sm;
    const int t = threadIdx.x, lane = t & 31, w = t >> 5;
    const int mi = w >> 1, ni = w & 1;
    const int g = lane >> 2, q = lane & 3;
    const int q0 = blockIdx.x * 64;
    const int b = blockIdx.y >> 3, h = blockIdx.y & 7;
    const float* qp = g_q + ((long)b * NHKD + h * KDIM) * NTOK;
    const float* kp = g_k + ((long)b * NHKD + h * KDIM) * NTOK;
    const float* vp = g_v + ((long)b * DHV  + h * DV  ) * NTOK;
    const float SQ = 5.656854249492380f, L2E = 1.44269504088896f;

    // stage Q [32 kd][64 q]*SQ into P+VH area (float, stride 72)
    {
        int kd = t >> 3, c8 = (t & 7) * 8;
        const float* s = qp + (long)kd * NTOK + q0 + c8;
        float4 u0 = *(const float4*)s, u1 = *(const float4*)(s + 4);
        u0.x *= SQ; u0.y *= SQ; u0.z *= SQ; u0.w *= SQ;
        u1.x *= SQ; u1.y *= SQ; u1.z *= SQ; u1.w *= SQ;
        *(float4*)(sm + F_VH + kd * 72 + c8)     = u0;
        *(float4*)(sm + F_VH + kd * 72 + c8 + 4) = u1;
    }
    if (t < 64) { sm[F_MR + t] = -1e30f; sm[F_MR + 64 + t] = -1e30f; sm[F_LR + t] = 0.f; }
    __syncthreads();

    const int r0 = mi * 16 + g;
    uint32_t qh[2][4], ql[2][4];
#pragma unroll
    for (int s = 0; s < 2; s++) {
        int kd0 = 16 * s + 2 * q;
        const float* Q = sm + F_VH;
        splitpack(Q[kd0 * 72 + r0],           Q[(kd0 + 1) * 72 + r0],     qh[s][0], ql[s][0]);
        splitpack(Q[kd0 * 72 + r0 + 8],       Q[(kd0 + 1) * 72 + r0 + 8], qh[s][1], ql[s][1]);
        splitpack(Q[(kd0 + 8) * 72 + r0],     Q[(kd0 + 9) * 72 + r0],     qh[s][2], ql[s][2]);
        splitpack(Q[(kd0 + 8) * 72 + r0 + 8], Q[(kd0 + 9) * 72 + r0 + 8], qh[s][3], ql[s][3]);
    }
    __syncthreads();

    float o[8][4];
#pragma unroll
    for (int nf = 0; nf < 8; nf++)
#pragma unroll
        for (int j = 0; j < 4; j++) o[nf][j] = 0.f;

    const int kpair = t >> 4, ktok4 = (t & 15) * 4;   // K staging
    const int vd = t >> 1, vhalf = t & 1;             // V staging

    for (int it = 0; it < 16; it++) {
        const int j0 = it * 64;
        __syncthreads();   // prev AV done with V/P
        {
            // K: pairs of kd rows -> half2 per token, hi/lo split
            const float* k0 = kp + (long)(2 * kpair) * NTOK + j0 + ktok4;
            float4 a4 = *(const float4*)k0;
            float4 b4 = *(const float4*)(k0 + NTOK);
            uint32_t hh[4], ll[4];
            splitpack(a4.x, b4.x, hh[0], ll[0]);
            splitpack(a4.y, b4.y, hh[1], ll[1]);
            splitpack(a4.z, b4.z, hh[2], ll[2]);
            splitpack(a4.w, b4.w, hh[3], ll[3]);
            *(uint4*)(smu + F_KH + kpair * 72 + ktok4) = make_uint4(hh[0], hh[1], hh[2], hh[3]);
            *(uint4*)(smu + F_KL + kpair * 72 + ktok4) = make_uint4(ll[0], ll[1], ll[2], ll[3]);
            // V: [d][tok] -> half2 token pairs, single fp16
            const float* vs_ = vp + (long)vd * NTOK + j0 + vhalf * 32;
#pragma unroll
            for (int jj = 0; jj < 4; jj++) {
                float4 u = *(const float4*)(vs_ + jj * 8);
                float4 v = *(const float4*)(vs_ + jj * 8 + 4);
                *(uint4*)(smu + F_VH + vd * 36 + vhalf * 16 + jj * 4) =
                    make_uint4(pack2(u.x, u.y), pack2(u.z, u.w),
                               pack2(v.x, v.y), pack2(v.z, v.w));
            }
        }
        __syncthreads();

        // QK (2x-split fp16): S[16][32] per warp
        float s4[4][4];
#pragma unroll
        for (int nf = 0; nf < 4; nf++)
#pragma unroll
            for (int j = 0; j < 4; j++) s4[nf][j] = 0.f;
#pragma unroll
        for (int s = 0; s < 2; s++) {
#pragma unroll
            for (int nf = 0; nf < 4; nf++) {
                int col = ni * 32 + nf * 8 + g;
                uint32_t bh0 = smu[F_KH + (8 * s + q) * 72 + col];
                uint32_t bh1 = smu[F_KH + (8 * s + q + 4) * 72 + col];
                uint32_t bl0 = smu[F_KL + (8 * s + q) * 72 + col];
                uint32_t bl1 = smu[F_KL + (8 * s + q + 4) * 72 + col];
                mma16(s4[nf], qh[s], bh0, bh1);
                mma16(s4[nf], qh[s], bl0, bl1);
                mma16(s4[nf], ql[s], bh0, bh1);
            }
        }

        // warp-local row max -> MP
        {
            float m0 = fmaxf(fmaxf(s4[0][0], s4[0][1]), fmaxf(s4[1][0], s4[1][1]));
            m0 = fmaxf(m0, fmaxf(fmaxf(s4[2][0], s4[2][1]), fmaxf(s4[3][0], s4[3][1])));
            float m1 = fmaxf(fmaxf(s4[0][2], s4[0][3]), fmaxf(s4[1][2], s4[1][3]));
            m1 = fmaxf(m1, fmaxf(fmaxf(s4[2][2], s4[2][3]), fmaxf(s4[3][2], s4[3][3])));
            m0 = fmaxf(m0, __shfl_xor_sync(0xffffffffu, m0, 1));
            m0 = fmaxf(m0, __shfl_xor_sync(0xffffffffu, m0, 2));
            m1 = fmaxf(m1, __shfl_xor_sync(0xffffffffu, m1, 1));
            m1 = fmaxf(m1, __shfl_xor_sync(0xffffffffu, m1, 2));
            if (q == 0) {
                sm[F_MP + ni * 64 + r0] = m0;
                sm[F_MP + ni * 64 + r0 + 8] = m1;
            }
        }
        __syncthreads();

        // new max, alpha, P (fp16 half2), partial sums, O rescale
        {
            float moA = sm[F_MR + (it & 1) * 64 + r0];
            float moB = sm[F_MR + (it & 1) * 64 + r0 + 8];
            float mn0 = fmaxf(moA, fmaxf(sm[F_MP + r0], sm[F_MP + 64 + r0]));
            float mn1 = fmaxf(moB, fmaxf(sm[F_MP + r0 + 8], sm[F_MP + 64 + r0 + 8]));
            if (ni == 0 && q == 0) {
                sm[F_MR + ((it + 1) & 1) * 64 + r0] = mn0;
                sm[F_MR + ((it + 1) & 1) * 64 + r0 + 8] = mn1;
            }
            float al0 = fexp2((moA - mn0) * L2E);
            float al1 = fexp2((moB - mn1) * L2E);
            float c0 = -mn0 * L2E, c1 = -mn1 * L2E;
            float rs0 = 0.f, rs1 = 0.f;
#pragma unroll
            for (int nf = 0; nf < 4; nf++) {
                int colp = ni * 16 + nf * 4 + q;
                float e00 = fexp2(fmaf(s4[nf][0], L2E, c0));
                float e01 = fexp2(fmaf(s4[nf][1], L2E, c0));
                float e10 = fexp2(fmaf(s4[nf][2], L2E, c1));
                float e11 = fexp2(fmaf(s4[nf][3], L2E, c1));
                rs0 += e00 + e01; rs1 += e10 + e11;
                smu[F_P + r0 * 36 + colp]       = pack2(e00, e01);
                smu[F_P + (r0 + 8) * 36 + colp] = pack2(e10, e11);
            }
            rs0 += __shfl_xor_sync(0xffffffffu, rs0, 1);
            rs0 += __shfl_xor_sync(0xffffffffu, rs0, 2);
            rs1 += __shfl_xor_sync(0xffffffffu, rs1, 1);
            rs1 += __shfl_xor_sync(0xffffffffu, rs1, 2);
            if (q == 0) {
                sm[F_SP + ni * 64 + r0] = rs0;
                sm[F_SP + ni * 64 + r0 + 8] = rs1;
            }
#pragma unroll
            for (int nf = 0; nf < 8; nf++) {
                o[nf][0] *= al0; o[nf][1] *= al0;
                o[nf][2] *= al1; o[nf][3] *= al1;
            }
        }
        __syncthreads();

        // l update (concurrent with AV)
        if (t < 64) {
            float mo = sm[F_MR + (it & 1) * 64 + t];
            float mn = sm[F_MR + ((it + 1) & 1) * 64 + t];
            sm[F_LR + t] = sm[F_LR + t] * fexp2((mo - mn) * L2E)
                         + sm[F_SP + t] + sm[F_SP + 64 + t];
        }

        // AV fp16: P single, V single
#pragma unroll
        for (int s = 0; s < 4; s++) {
            uint32_t a[4];
            a[0] = smu[F_P + r0 * 36 + 8 * s + q];
            a[1] = smu[F_P + (r0 + 8) * 36 + 8 * s + q];
            a[2] = smu[F_P + r0 * 36 + 8 * s + q + 4];
            a[3] = smu[F_P + (r0 + 8) * 36 + 8 * s + q + 4];
#pragma unroll
            for (int nf = 0; nf < 8; nf++) {
                int d = ni * 64 + nf * 8 + g;
                uint32_t bh0 = smu[F_VH + d * 36 + 8 * s + q];
                uint32_t bh1 = smu[F_VH + d * 36 + 8 * s + q + 4];
                mma16(o[nf], a, bh0, bh1);
            }
        }
    }

    // epilogue: normalize, transpose via smem (reuse [128][72] f32 from F_KH)
    __syncthreads();
    {
        float inv0 = 1.0f / sm[F_LR + r0];
        float inv1 = 1.0f / sm[F_LR + r0 + 8];
#pragma unroll
        for (int nf = 0; nf < 8; nf++) {
            int d = ni * 64 + nf * 8 + 2 * q;
            sm[F_KH + d * 72 + r0]           = o[nf][0] * inv0;
            sm[F_KH + (d + 1) * 72 + r0]     = o[nf][1] * inv0;
            sm[F_KH + d * 72 + r0 + 8]       = o[nf][2] * inv1;
            sm[F_KH + (d + 1) * 72 + r0 + 8] = o[nf][3] * inv1;
        }
    }
    __syncthreads();
    {
        int d = t >> 1, qq = (t & 1) * 32;
        float* dst = g_xx + ((long)b * DHV + h * DV + d) * NTOK + q0 + qq;
#pragma unroll
        for (int p = 0; p < 8; p++)
            *(float4*)(dst + p * 4) = *(const float4*)(sm + F_KH + d * 72 + qq + p * 4);
    }
}

// ---------------------------------------------------------------------------
extern "C" void kernel_launch(void* const* d_in, const int* in_sizes, int n_in,
                              void* d_out, int out_size)
{
    const float* x   = (const float*)d_in[0];
    const float* wq  = (const float*)d_in[1];
    const float* bnq = (const float*)d_in[2];
    const float* wk  = (const float*)d_in[3];
    const float* bnk = (const float*)d_in[4];
    const float* wv  = (const float*)d_in[5];
    const float* bnv = (const float*)d_in[6];
    const float* wp  = (const float*)d_in[7];
    const float* bnp = (const float*)d_in[8];
    float* out = (float*)d_out;

    float *qs, *ks, *vs;
    cudaGetSymbolAddress((void**)&qs, g_q);
    cudaGetSymbolAddress((void**)&ks, g_k);
    cudaGetSymbolAddress((void**)&vs, g_v);

    const int smem_attn = ATTN_SMEM_F * 4;   // 38656 B
    cudaFuncSetAttribute(attn_fa, cudaFuncAttributeMaxDynamicSharedMemorySize,
                         smem_attn);
    dim3 blk(256);

    // Fused QKV projections (12 m-tiles: 2 q, 2 k, 8 v)
    gemm_qkv<<<dim3(8, 12, BB), blk>>>(x, wq, bnq, wk, bnk, wv, bnv, qs, ks, vs);

    // Attention
    attn_fa<<<dim3(NTOK / 64, BB * NH), blk, smem_attn>>>();

    // Output projection
    gemm_proj<<<dim3(8, 3, BB), blk>>>(wp, bnp, out);
}

// round 10
// speedup vs baseline: 4.2997x; 1.2704x over previous
#include <cuda_runtime.h>
#include <cuda_fp16.h>
#include <cstdint>
#include <math.h>

#define BB   16
#define DIM  384
#define NHKD 256
#define DHV  1024
#define NTOK 1024
#define NH   8
#define KDIM 32
#define DV   128

__device__ float g_q [BB * NHKD * NTOK];
__device__ float g_k [BB * NHKD * NTOK];
__device__ float g_v [BB * DHV  * NTOK];
__device__ float g_xx[BB * DHV  * NTOK];

__device__ __forceinline__ void mma16(float c[4], const uint32_t a[4],
                                      uint32_t b0, uint32_t b1) {
    asm volatile("mma.sync.aligned.m16n8k16.row.col.f32.f16.f16.f32 "
        "{%0,%1,%2,%3}, {%4,%5,%6,%7}, {%8,%9}, {%0,%1,%2,%3};"
        : "+f"(c[0]), "+f"(c[1]), "+f"(c[2]), "+f"(c[3])
        : "r"(a[0]), "r"(a[1]), "r"(a[2]), "r"(a[3]), "r"(b0), "r"(b1));
}

__device__ __forceinline__ uint32_t pack2(float x0, float x1) {
    __half2 h = __floats2half2_rn(x0, x1);
    return *(uint32_t*)&h;
}
__device__ __forceinline__ void splitpack(float x0, float x1,
                                          uint32_t& h, uint32_t& l) {
    __half2 hh = __floats2half2_rn(x0, x1);
    float2 bk = __half22float2(hh);
    __half2 ll = __floats2half2_rn(x0 - bk.x, x1 - bk.y);
    h = *(uint32_t*)&hh;
    l = *(uint32_t*)&ll;
}

// 2^z on FMA pipe, z <= 0 (clamped at -100). deg-5 poly.
__device__ __forceinline__ float fexp2(float z) {
    z = fmaxf(z, -100.0f);
    float zi = z + 12582912.0f;
    int   n  = __float_as_int(zi) - 0x4B400000;
    float t  = z - (zi - 12582912.0f);
    float p = fmaf(0.0013333558f, t, 0.0096181291f);
    p = fmaf(p, t, 0.0555041087f);
    p = fmaf(p, t, 0.2402265069f);
    p = fmaf(p, t, 0.6931471806f);
    p = fmaf(p, t, 1.0f);
    return __int_as_float(__float_as_int(p) + (n << 23));
}

// ============ fp16 3x-split tensor GEMM + BN (128x128 tile) ================
// Y[m][n] = BN_m( sum_k W[m][k] * X[k][n] ),  3 passes: WhXh + WhXl + WlXh.
// Staging: W and X both stored as [kpair p][col][stride 132] uint32 half2
// where half2 = (k=2p low, k=2p+1 high). All frag loads bank-conflict-free.
#define SW_H 0
#define SW_L 2112
#define SX_H 4224
#define SX_L 6336
#define GEMM_SMEM_U32 8448

__device__ __forceinline__ void gemm16_body(
    const float* __restrict__ W, const float* __restrict__ bn,
    const float* __restrict__ Xb, float* __restrict__ Yb,
    int M, int K, int m0, int n0, uint32_t* smu)
{
    const int t = threadIdx.x, lane = t & 31, w = t >> 5;
    const int g = lane >> 2, q = lane & 3;
    const int mw = (w >> 2) * 64, nw = (w & 3) * 32;
    const int wm = t & 127, wkh = t >> 7;       // W stager: row m, k-half
    const int xp = t >> 4, xn0 = (t & 15) * 8;  // X stager: kpair, n-offset

    float c[4][4][4];
#pragma unroll
    for (int i = 0; i < 4; i++)
#pragma unroll
        for (int j = 0; j < 4; j++)
#pragma unroll
            for (int r = 0; r < 4; r++) c[i][j][r] = 0.f;

    const int nc = K >> 5;
    for (int ch = 0; ch < nc; ch++) {
        const int kc = ch * 32;
        // ---- prefetch gmem -> regs
        const float* ws = W + (long)(m0 + wm) * K + kc + wkh * 16;
        float4 w0 = *(const float4*)ws;
        float4 w1 = *(const float4*)(ws + 4);
        float4 w2 = *(const float4*)(ws + 8);
        float4 w3 = *(const float4*)(ws + 12);
        const float* xs = Xb + (long)(kc + 2 * xp) * NTOK + n0 + xn0;
        float4 xa = *(const float4*)xs;
        float4 xb2 = *(const float4*)(xs + 4);
        float4 xc = *(const float4*)(xs + NTOK);
        float4 xd = *(const float4*)(xs + NTOK + 4);
        __syncthreads();   // previous chunk's fragment loads done
        // ---- pack W into [p][m]
        {
            float wf[16] = {w0.x, w0.y, w0.z, w0.w, w1.x, w1.y, w1.z, w1.w,
                            w2.x, w2.y, w2.z, w2.w, w3.x, w3.y, w3.z, w3.w};
#pragma unroll
            for (int j = 0; j < 8; j++) {
                uint32_t hh, ll;
                splitpack(wf[2 * j], wf[2 * j + 1], hh, ll);
                smu[SW_H + (wkh * 8 + j) * 132 + wm] = hh;
                smu[SW_L + (wkh * 8 + j) * 132 + wm] = ll;
            }
        }
        // ---- pack X into [p][n]
        {
            uint32_t xh[8], xl[8];
            splitpack(xa.x,  xc.x, xh[0], xl[0]);
            splitpack(xa.y,  xc.y, xh[1], xl[1]);
            splitpack(xa.z,  xc.z, xh[2], xl[2]);
            splitpack(xa.w,  xc.w, xh[3], xl[3]);
            splitpack(xb2.x, xd.x, xh[4], xl[4]);
            splitpack(xb2.y, xd.y, xh[5], xl[5]);
            splitpack(xb2.z, xd.z, xh[6], xl[6]);
            splitpack(xb2.w, xd.w, xh[7], xl[7]);
            *(uint4*)(smu + SX_H + xp * 132 + xn0)     = make_uint4(xh[0], xh[1], xh[2], xh[3]);
            *(uint4*)(smu + SX_H + xp * 132 + xn0 + 4) = make_uint4(xh[4], xh[5], xh[6], xh[7]);
            *(uint4*)(smu + SX_L + xp * 132 + xn0)     = make_uint4(xl[0], xl[1], xl[2], xl[3]);
            *(uint4*)(smu + SX_L + xp * 132 + xn0 + 4) = make_uint4(xl[4], xl[5], xl[6], xl[7]);
        }
        __syncthreads();
        // ---- compute
#pragma unroll
        for (int ks = 0; ks < 2; ks++) {
            const int p0 = ks * 8 + q, p1 = p0 + 4;
            uint32_t ah[4][4], al[4][4];
#pragma unroll
            for (int mf = 0; mf < 4; mf++) {
                int colm = mw + mf * 16 + g;
                ah[mf][0] = smu[SW_H + p0 * 132 + colm];
                ah[mf][1] = smu[SW_H + p0 * 132 + colm + 8];
                ah[mf][2] = smu[SW_H + p1 * 132 + colm];
                ah[mf][3] = smu[SW_H + p1 * 132 + colm + 8];
                al[mf][0] = smu[SW_L + p0 * 132 + colm];
                al[mf][1] = smu[SW_L + p0 * 132 + colm + 8];
                al[mf][2] = smu[SW_L + p1 * 132 + colm];
                al[mf][3] = smu[SW_L + p1 * 132 + colm + 8];
            }
#pragma unroll
            for (int nf = 0; nf < 4; nf++) {
                int coln = nw + nf * 8 + g;
                uint32_t b0h = smu[SX_H + p0 * 132 + coln];
                uint32_t b1h = smu[SX_H + p1 * 132 + coln];
                uint32_t b0l = smu[SX_L + p0 * 132 + coln];
                uint32_t b1l = smu[SX_L + p1 * 132 + coln];
#pragma unroll
                for (int mf = 0; mf < 4; mf++) {
                    mma16(c[mf][nf], ah[mf], b0h, b1h);
                    mma16(c[mf][nf], ah[mf], b0l, b1l);
                    mma16(c[mf][nf], al[mf], b0h, b1h);
                }
            }
        }
    }

    // ---- epilogue: BN + store
#pragma unroll
    for (int mf = 0; mf < 4; mf++) {
        int r0 = m0 + mw + mf * 16 + g;
        int r1 = r0 + 8;
        float sc0 = bn[r0] * rsqrtf(bn[3 * M + r0] + 1e-5f);
        float tt0 = bn[M + r0] - bn[2 * M + r0] * sc0;
        float sc1 = bn[r1] * rsqrtf(bn[3 * M + r1] + 1e-5f);
        float tt1 = bn[M + r1] - bn[2 * M + r1] * sc1;
#pragma unroll
        for (int nf = 0; nf < 4; nf++) {
            int nn = n0 + nw + nf * 8 + 2 * q;
            float2 v0, v1;
            v0.x = c[mf][nf][0] * sc0 + tt0;
            v0.y = c[mf][nf][1] * sc0 + tt0;
            v1.x = c[mf][nf][2] * sc1 + tt1;
            v1.y = c[mf][nf][3] * sc1 + tt1;
            *(float2*)(Yb + (long)r0 * NTOK + nn) = v0;
            *(float2*)(Yb + (long)r1 * NTOK + nn) = v1;
        }
    }
}

// Fused QKV projection: blockIdx.y 0-1 -> Q, 2-3 -> K, 4-11 -> V
__global__ __launch_bounds__(256) void gemm_qkv_tc(
    const float* __restrict__ x,
    const float* __restrict__ wq, const float* __restrict__ bnq,
    const float* __restrict__ wk, const float* __restrict__ bnk,
    const float* __restrict__ wv, const float* __restrict__ bnv,
    float* __restrict__ yq, float* __restrict__ yk, float* __restrict__ yv)
{
    __shared__ uint32_t smu[GEMM_SMEM_U32];
    const int y = blockIdx.y;
    const float *W, *bn;
    float* Y;
    int M, m0;
    if (y < 2)      { W = wq; bn = bnq; Y = yq; M = NHKD; m0 = y * 128; }
    else if (y < 4) { W = wk; bn = bnk; Y = yk; M = NHKD; m0 = (y - 2) * 128; }
    else            { W = wv; bn = bnv; Y = yv; M = DHV;  m0 = (y - 4) * 128; }
    gemm16_body(W, bn, x + (long)blockIdx.z * DIM * NTOK,
                Y + (long)blockIdx.z * M * NTOK,
                M, DIM, m0, blockIdx.x * 128, smu);
}

// Output projection
__global__ __launch_bounds__(256) void gemm_proj_tc(
    const float* __restrict__ wp, const float* __restrict__ bnp,
    float* __restrict__ out)
{
    __shared__ uint32_t smu[GEMM_SMEM_U32];
    gemm16_body(wp, bnp, g_xx + (long)blockIdx.z * DHV * NTOK,
                out + (long)blockIdx.z * DIM * NTOK,
                DIM, DHV, blockIdx.y * 128, blockIdx.x * 128, smu);
}

// ---------------- FA2 attention, fp16 m16n8k16 (unchanged R9) ---------------
#define F_KH 0
#define F_KL 1152
#define F_VH 2304
#define F_P  6912
#define F_MP 9216
#define F_SP 9344
#define F_MR 9472
#define F_LR 9600
#define ATTN_SMEM_F 9664   // 38656 B

__global__ __launch_bounds__(256) void attn_fa()
{
    extern __shared__ float sm[];
    uint32_t* smu = (uint32_t*)sm;
    const int t = threadIdx.x, lane = t & 31, w = t >> 5;
    const int mi = w >> 1, ni = w & 1;
    const int g = lane >> 2, q = lane & 3;
    const int q0 = blockIdx.x * 64;
    const int b = blockIdx.y >> 3, h = blockIdx.y & 7;
    const float* qp = g_q + ((long)b * NHKD + h * KDIM) * NTOK;
    const float* kp = g_k + ((long)b * NHKD + h * KDIM) * NTOK;
    const float* vp = g_v + ((long)b * DHV  + h * DV  ) * NTOK;
    const float SQ = 5.656854249492380f, L2E = 1.44269504088896f;

    {
        int kd = t >> 3, c8 = (t & 7) * 8;
        const float* s = qp + (long)kd * NTOK + q0 + c8;
        float4 u0 = *(const float4*)s, u1 = *(const float4*)(s + 4);
        u0.x *= SQ; u0.y *= SQ; u0.z *= SQ; u0.w *= SQ;
        u1.x *= SQ; u1.y *= SQ; u1.z *= SQ; u1.w *= SQ;
        *(float4*)(sm + F_VH + kd * 72 + c8)     = u0;
        *(float4*)(sm + F_VH + kd * 72 + c8 + 4) = u1;
    }
    if (t < 64) { sm[F_MR + t] = -1e30f; sm[F_MR + 64 + t] = -1e30f; sm[F_LR + t] = 0.f; }
    __syncthreads();

    const int r0 = mi * 16 + g;
    uint32_t qh[2][4], ql[2][4];
#pragma unroll
    for (int s = 0; s < 2; s++) {
        int kd0 = 16 * s + 2 * q;
        const float* Q = sm + F_VH;
        splitpack(Q[kd0 * 72 + r0],           Q[(kd0 + 1) * 72 + r0],     qh[s][0], ql[s][0]);
        splitpack(Q[kd0 * 72 + r0 + 8],       Q[(kd0 + 1) * 72 + r0 + 8], qh[s][1], ql[s][1]);
        splitpack(Q[(kd0 + 8) * 72 + r0],     Q[(kd0 + 9) * 72 + r0],     qh[s][2], ql[s][2]);
        splitpack(Q[(kd0 + 8) * 72 + r0 + 8], Q[(kd0 + 9) * 72 + r0 + 8], qh[s][3], ql[s][3]);
    }
    __syncthreads();

    float o[8][4];
#pragma unroll
    for (int nf = 0; nf < 8; nf++)
#pragma unroll
        for (int j = 0; j < 4; j++) o[nf][j] = 0.f;

    const int kpair = t >> 4, ktok4 = (t & 15) * 4;
    const int vd = t >> 1, vhalf = t & 1;

    for (int it = 0; it < 16; it++) {
        const int j0 = it * 64;
        __syncthreads();
        {
            const float* k0 = kp + (long)(2 * kpair) * NTOK + j0 + ktok4;
            float4 a4 = *(const float4*)k0;
            float4 b4 = *(const float4*)(k0 + NTOK);
            uint32_t hh[4], ll[4];
            splitpack(a4.x, b4.x, hh[0], ll[0]);
            splitpack(a4.y, b4.y, hh[1], ll[1]);
            splitpack(a4.z, b4.z, hh[2], ll[2]);
            splitpack(a4.w, b4.w, hh[3], ll[3]);
            *(uint4*)(smu + F_KH + kpair * 72 + ktok4) = make_uint4(hh[0], hh[1], hh[2], hh[3]);
            *(uint4*)(smu + F_KL + kpair * 72 + ktok4) = make_uint4(ll[0], ll[1], ll[2], ll[3]);
            const float* vs_ = vp + (long)vd * NTOK + j0 + vhalf * 32;
#pragma unroll
            for (int jj = 0; jj < 4; jj++) {
                float4 u = *(const float4*)(vs_ + jj * 8);
                float4 v = *(const float4*)(vs_ + jj * 8 + 4);
                *(uint4*)(smu + F_VH + vd * 36 + vhalf * 16 + jj * 4) =
                    make_uint4(pack2(u.x, u.y), pack2(u.z, u.w),
                               pack2(v.x, v.y), pack2(v.z, v.w));
            }
        }
        __syncthreads();

        float s4[4][4];
#pragma unroll
        for (int nf = 0; nf < 4; nf++)
#pragma unroll
            for (int j = 0; j < 4; j++) s4[nf][j] = 0.f;
#pragma unroll
        for (int s = 0; s < 2; s++) {
#pragma unroll
            for (int nf = 0; nf < 4; nf++) {
                int col = ni * 32 + nf * 8 + g;
                uint32_t bh0 = smu[F_KH + (8 * s + q) * 72 + col];
                uint32_t bh1 = smu[F_KH + (8 * s + q + 4) * 72 + col];
                uint32_t bl0 = smu[F_KL + (8 * s + q) * 72 + col];
                uint32_t bl1 = smu[F_KL + (8 * s + q + 4) * 72 + col];
                mma16(s4[nf], qh[s], bh0, bh1);
                mma16(s4[nf], qh[s], bl0, bl1);
                mma16(s4[nf], ql[s], bh0, bh1);
            }
        }

        {
            float m0 = fmaxf(fmaxf(s4[0][0], s4[0][1]), fmaxf(s4[1][0], s4[1][1]));
            m0 = fmaxf(m0, fmaxf(fmaxf(s4[2][0], s4[2][1]), fmaxf(s4[3][0], s4[3][1])));
            float m1 = fmaxf(fmaxf(s4[0][2], s4[0][3]), fmaxf(s4[1][2], s4[1][3]));
            m1 = fmaxf(m1, fmaxf(fmaxf(s4[2][2], s4[2][3]), fmaxf(s4[3][2], s4[3][3])));
            m0 = fmaxf(m0, __shfl_xor_sync(0xffffffffu, m0, 1));
            m0 = fmaxf(m0, __shfl_xor_sync(0xffffffffu, m0, 2));
            m1 = fmaxf(m1, __shfl_xor_sync(0xffffffffu, m1, 1));
            m1 = fmaxf(m1, __shfl_xor_sync(0xffffffffu, m1, 2));
            if (q == 0) {
                sm[F_MP + ni * 64 + r0] = m0;
                sm[F_MP + ni * 64 + r0 + 8] = m1;
            }
        }
        __syncthreads();

        {
            float moA = sm[F_MR + (it & 1) * 64 + r0];
            float moB = sm[F_MR + (it & 1) * 64 + r0 + 8];
            float mn0 = fmaxf(moA, fmaxf(sm[F_MP + r0], sm[F_MP + 64 + r0]));
            float mn1 = fmaxf(moB, fmaxf(sm[F_MP + r0 + 8], sm[F_MP + 64 + r0 + 8]));
            if (ni == 0 && q == 0) {
                sm[F_MR + ((it + 1) & 1) * 64 + r0] = mn0;
                sm[F_MR + ((it + 1) & 1) * 64 + r0 + 8] = mn1;
            }
            float al0 = fexp2((moA - mn0) * L2E);
            float al1 = fexp2((moB - mn1) * L2E);
            float c0 = -mn0 * L2E, c1 = -mn1 * L2E;
            float rs0 = 0.f, rs1 = 0.f;
#pragma unroll
            for (int nf = 0; nf < 4; nf++) {
                int colp = ni * 16 + nf * 4 + q;
                float e00 = fexp2(fmaf(s4[nf][0], L2E, c0));
                float e01 = fexp2(fmaf(s4[nf][1], L2E, c0));
                float e10 = fexp2(fmaf(s4[nf][2], L2E, c1));
                float e11 = fexp2(fmaf(s4[nf][3], L2E, c1));
                rs0 += e00 + e01; rs1 += e10 + e11;
                smu[F_P + r0 * 36 + colp]       = pack2(e00, e01);
                smu[F_P + (r0 + 8) * 36 + colp] = pack2(e10, e11);
            }
            rs0 += __shfl_xor_sync(0xffffffffu, rs0, 1);
            rs0 += __shfl_xor_sync(0xffffffffu, rs0, 2);
            rs1 += __shfl_xor_sync(0xffffffffu, rs1, 1);
            rs1 += __shfl_xor_sync(0xffffffffu, rs1, 2);
            if (q == 0) {
                sm[F_SP + ni * 64 + r0] = rs0;
                sm[F_SP + ni * 64 + r0 + 8] = rs1;
            }
#pragma unroll
            for (int nf = 0; nf < 8; nf++) {
                o[nf][0] *= al0; o[nf][1] *= al0;
                o[nf][2] *= al1; o[nf][3] *= al1;
            }
        }
        __syncthreads();

        if (t < 64) {
            float mo = sm[F_MR + (it & 1) * 64 + t];
            float mn = sm[F_MR + ((it + 1) & 1) * 64 + t];
            sm[F_LR + t] = sm[F_LR + t] * fexp2((mo - mn) * L2E)
                         + sm[F_SP + t] + sm[F_SP + 64 + t];
        }

#pragma unroll
        for (int s = 0; s < 4; s++) {
            uint32_t a[4];
            a[0] = smu[F_P + r0 * 36 + 8 * s + q];
            a[1] = smu[F_P + (r0 + 8) * 36 + 8 * s + q];
            a[2] = smu[F_P + r0 * 36 + 8 * s + q + 4];
            a[3] = smu[F_P + (r0 + 8) * 36 + 8 * s + q + 4];
#pragma unroll
            for (int nf = 0; nf < 8; nf++) {
                int d = ni * 64 + nf * 8 + g;
                uint32_t bh0 = smu[F_VH + d * 36 + 8 * s + q];
                uint32_t bh1 = smu[F_VH + d * 36 + 8 * s + q + 4];
                mma16(o[nf], a, bh0, bh1);
            }
        }
    }

    __syncthreads();
    {
        float inv0 = 1.0f / sm[F_LR + r0];
        float inv1 = 1.0f / sm[F_LR + r0 + 8];
#pragma unroll
        for (int nf = 0; nf < 8; nf++) {
            int d = ni * 64 + nf * 8 + 2 * q;
            sm[F_KH + d * 72 + r0]           = o[nf][0] * inv0;
            sm[F_KH + (d + 1) * 72 + r0]     = o[nf][1] * inv0;
            sm[F_KH + d * 72 + r0 + 8]       = o[nf][2] * inv1;
            sm[F_KH + (d + 1) * 72 + r0 + 8] = o[nf][3] * inv1;
        }
    }
    __syncthreads();
    {
        int d = t >> 1, qq = (t & 1) * 32;
        float* dst = g_xx + ((long)b * DHV + h * DV + d) * NTOK + q0 + qq;
#pragma unroll
        for (int p = 0; p < 8; p++)
            *(float4*)(dst + p * 4) = *(const float4*)(sm + F_KH + d * 72 + qq + p * 4);
    }
}

// ---------------------------------------------------------------------------
extern "C" void kernel_launch(void* const* d_in, const int* in_sizes, int n_in,
                              void* d_out, int out_size)
{
    const float* x   = (const float*)d_in[0];
    const float* wq  = (const float*)d_in[1];
    const float* bnq = (const float*)d_in[2];
    const float* wk  = (const float*)d_in[3];
    const float* bnk = (const float*)d_in[4];
    const float* wv  = (const float*)d_in[5];
    const float* bnv = (const float*)d_in[6];
    const float* wp  = (const float*)d_in[7];
    const float* bnp = (const float*)d_in[8];
    float* out = (float*)d_out;

    float *qs, *ks, *vs;
    cudaGetSymbolAddress((void**)&qs, g_q);
    cudaGetSymbolAddress((void**)&ks, g_k);
    cudaGetSymbolAddress((void**)&vs, g_v);

    const int smem_attn = ATTN_SMEM_F * 4;   // 38656 B
    cudaFuncSetAttribute(attn_fa, cudaFuncAttributeMaxDynamicSharedMemorySize,
                         smem_attn);
    dim3 blk(256);

    // Fused QKV projections (fp16 3x-split tensor)
    gemm_qkv_tc<<<dim3(8, 12, BB), blk>>>(x, wq, bnq, wk, bnk, wv, bnv, qs, ks, vs);

    // Attention
    attn_fa<<<dim3(NTOK / 64, BB * NH), blk, smem_attn>>>();

    // Output projection (fp16 3x-split tensor)
    gemm_proj_tc<<<dim3(8, 3, BB), blk>>>(wp, bnp, out);
}

// round 11
// speedup vs baseline: 4.7524x; 1.1053x over previous
#include <cuda_runtime.h>
#include <cuda_fp16.h>
#include <cstdint>
#include <math.h>

#define BB   16
#define DIM  384
#define NHKD 256
#define DHV  1024
#define NTOK 1024
#define NH   8
#define KDIM 32
#define DV   128

// float intermediates for attention inputs
__device__ float g_q [BB * NHKD * NTOK];
__device__ float g_k [BB * NHKD * NTOK];
__device__ float g_v [BB * DHV  * NTOK];
// packed fp16 hi/lo buffers
__device__ uint32_t g_xh [BB * 192 * NTOK];   // x packed [b][kpair][tok]
__device__ uint32_t g_xl [BB * 192 * NTOK];
__device__ uint32_t g_xxh[BB * 512 * NTOK];   // attn out packed [b][dpair][tok]
__device__ uint32_t g_xxl[BB * 512 * NTOK];
__device__ uint32_t g_wqh[192 * 256],  g_wql[192 * 256];
__device__ uint32_t g_wkh[192 * 256],  g_wkl[192 * 256];
__device__ uint32_t g_wvh[192 * 1024], g_wvl[192 * 1024];
__device__ uint32_t g_wph[512 * 384],  g_wpl[512 * 384];

__device__ __forceinline__ void mma16(float c[4], const uint32_t a[4],
                                      uint32_t b0, uint32_t b1) {
    asm volatile("mma.sync.aligned.m16n8k16.row.col.f32.f16.f16.f32 "
        "{%0,%1,%2,%3}, {%4,%5,%6,%7}, {%8,%9}, {%0,%1,%2,%3};"
        : "+f"(c[0]), "+f"(c[1]), "+f"(c[2]), "+f"(c[3])
        : "r"(a[0]), "r"(a[1]), "r"(a[2]), "r"(a[3]), "r"(b0), "r"(b1));
}
__device__ __forceinline__ uint32_t pack2(float x0, float x1) {
    __half2 h = __floats2half2_rn(x0, x1);
    return *(uint32_t*)&h;
}
__device__ __forceinline__ void splitpack(float x0, float x1,
                                          uint32_t& h, uint32_t& l) {
    __half2 hh = __floats2half2_rn(x0, x1);
    float2 bk = __half22float2(hh);
    __half2 ll = __floats2half2_rn(x0 - bk.x, x1 - bk.y);
    h = *(uint32_t*)&hh;
    l = *(uint32_t*)&ll;
}
__device__ __forceinline__ float fexp2(float z) {
    z = fmaxf(z, -100.0f);
    float zi = z + 12582912.0f;
    int   n  = __float_as_int(zi) - 0x4B400000;
    float t  = z - (zi - 12582912.0f);
    float p = fmaf(0.0013333558f, t, 0.0096181291f);
    p = fmaf(p, t, 0.0555041087f);
    p = fmaf(p, t, 0.2402265069f);
    p = fmaf(p, t, 0.6931471806f);
    p = fmaf(p, t, 1.0f);
    return __int_as_float(__float_as_int(p) + (n << 23));
}

// ---------------- prep: pack weights / activations to fp16 hi+lo ------------
// W float [M][K] -> H/L [K/2][M]
__global__ __launch_bounds__(256) void pack_w(
    const float* __restrict__ W, uint32_t* __restrict__ H,
    uint32_t* __restrict__ L, int M, int K)
{
    int idx = blockIdx.x * 256 + threadIdx.x;
    int p = idx / M, m = idx - p * M;
    float a = W[(long)m * K + 2 * p];
    float b = W[(long)m * K + 2 * p + 1];
    uint32_t hh, ll;
    splitpack(a, b, hh, ll);
    H[idx] = hh; L[idx] = ll;
}
// X float [b][C][1024] -> H/L [b][C/2][1024]
__global__ __launch_bounds__(256) void pack_x(
    const float* __restrict__ X, uint32_t* __restrict__ H,
    uint32_t* __restrict__ L, int C)
{
    int idx = blockIdx.x * 256 + threadIdx.x;
    int b = blockIdx.y;
    int p = idx >> 10, n = idx & 1023;
    long src = ((long)b * C + 2 * p) * NTOK + n;
    uint32_t hh, ll;
    splitpack(X[src], X[src + NTOK], hh, ll);
    long dst = ((long)b * (C >> 1) + p) * NTOK + n;
    H[dst] = hh; L[dst] = ll;
}

// ============ fp16 3x-split tensor GEMM + BN (128x128), packed inputs ======
#define SW_H 0
#define SW_L 2112
#define SX_H 4224
#define SX_L 6336
#define GEMM_SMEM_U32 8448

__device__ __forceinline__ void gemm16_body(
    const uint32_t* __restrict__ WH, const uint32_t* __restrict__ WL,
    const uint32_t* __restrict__ XH, const uint32_t* __restrict__ XL,
    const float* __restrict__ bn, float* __restrict__ Yb,
    int M, int Kp, int m0, int n0, uint32_t* smu)
{
    const int t = threadIdx.x, lane = t & 31, w = t >> 5;
    const int g = lane >> 2, q = lane & 3;
    const int mw = (w >> 2) * 64, nw = (w & 3) * 32;
    const int sp = t >> 5;           // staging base row 0..7
    const int c4 = (t & 31) * 4;

    float c[4][4][4];
#pragma unroll
    for (int i = 0; i < 4; i++)
#pragma unroll
        for (int j = 0; j < 4; j++)
#pragma unroll
            for (int r = 0; r < 4; r++) c[i][j][r] = 0.f;

    const int nc = Kp >> 4;
    for (int ch = 0; ch < nc; ch++) {
        const int pc = ch * 16;
        uint4 wh[2], wl[2], xh[2], xl[2];
#pragma unroll
        for (int r = 0; r < 2; r++) {
            int p = sp + 8 * r;
            wh[r] = *(const uint4*)(WH + (long)(pc + p) * M + m0 + c4);
            wl[r] = *(const uint4*)(WL + (long)(pc + p) * M + m0 + c4);
            xh[r] = *(const uint4*)(XH + (long)(pc + p) * NTOK + n0 + c4);
            xl[r] = *(const uint4*)(XL + (long)(pc + p) * NTOK + n0 + c4);
        }
        __syncthreads();
#pragma unroll
        for (int r = 0; r < 2; r++) {
            int p = sp + 8 * r;
            *(uint4*)(smu + SW_H + p * 132 + c4) = wh[r];
            *(uint4*)(smu + SW_L + p * 132 + c4) = wl[r];
            *(uint4*)(smu + SX_H + p * 132 + c4) = xh[r];
            *(uint4*)(smu + SX_L + p * 132 + c4) = xl[r];
        }
        __syncthreads();
#pragma unroll
        for (int ks = 0; ks < 2; ks++) {
            const int p0 = ks * 8 + q, p1 = p0 + 4;
            uint32_t ah[4][4], al[4][4];
#pragma unroll
            for (int mf = 0; mf < 4; mf++) {
                int colm = mw + mf * 16 + g;
                ah[mf][0] = smu[SW_H + p0 * 132 + colm];
                ah[mf][1] = smu[SW_H + p0 * 132 + colm + 8];
                ah[mf][2] = smu[SW_H + p1 * 132 + colm];
                ah[mf][3] = smu[SW_H + p1 * 132 + colm + 8];
                al[mf][0] = smu[SW_L + p0 * 132 + colm];
                al[mf][1] = smu[SW_L + p0 * 132 + colm + 8];
                al[mf][2] = smu[SW_L + p1 * 132 + colm];
                al[mf][3] = smu[SW_L + p1 * 132 + colm + 8];
            }
#pragma unroll
            for (int nf = 0; nf < 4; nf++) {
                int coln = nw + nf * 8 + g;
                uint32_t b0h = smu[SX_H + p0 * 132 + coln];
                uint32_t b1h = smu[SX_H + p1 * 132 + coln];
                uint32_t b0l = smu[SX_L + p0 * 132 + coln];
                uint32_t b1l = smu[SX_L + p1 * 132 + coln];
#pragma unroll
                for (int mf = 0; mf < 4; mf++) {
                    mma16(c[mf][nf], ah[mf], b0h, b1h);
                    mma16(c[mf][nf], ah[mf], b0l, b1l);
                    mma16(c[mf][nf], al[mf], b0h, b1h);
                }
            }
        }
    }

#pragma unroll
    for (int mf = 0; mf < 4; mf++) {
        int r0 = m0 + mw + mf * 16 + g;
        int r1 = r0 + 8;
        float sc0 = bn[r0] * rsqrtf(bn[3 * M + r0] + 1e-5f);
        float tt0 = bn[M + r0] - bn[2 * M + r0] * sc0;
        float sc1 = bn[r1] * rsqrtf(bn[3 * M + r1] + 1e-5f);
        float tt1 = bn[M + r1] - bn[2 * M + r1] * sc1;
#pragma unroll
        for (int nf = 0; nf < 4; nf++) {
            int nn = n0 + nw + nf * 8 + 2 * q;
            float2 v0, v1;
            v0.x = c[mf][nf][0] * sc0 + tt0;
            v0.y = c[mf][nf][1] * sc0 + tt0;
            v1.x = c[mf][nf][2] * sc1 + tt1;
            v1.y = c[mf][nf][3] * sc1 + tt1;
            *(float2*)(Yb + (long)r0 * NTOK + nn) = v0;
            *(float2*)(Yb + (long)r1 * NTOK + nn) = v1;
        }
    }
}

// Fused QKV projection: blockIdx.y 0-1 -> Q, 2-3 -> K, 4-11 -> V
__global__ __launch_bounds__(256, 2) void gemm_qkv_tc(
    const float* __restrict__ bnq, const float* __restrict__ bnk,
    const float* __restrict__ bnv)
{
    __shared__ uint32_t smu[GEMM_SMEM_U32];
    const int y = blockIdx.y, b = blockIdx.z;
    const uint32_t *WH, *WL;
    const float* bn;
    float* Y;
    int M, m0;
    if (y < 2)      { WH = g_wqh; WL = g_wql; bn = bnq; Y = g_q; M = NHKD; m0 = y * 128; }
    else if (y < 4) { WH = g_wkh; WL = g_wkl; bn = bnk; Y = g_k; M = NHKD; m0 = (y - 2) * 128; }
    else            { WH = g_wvh; WL = g_wvl; bn = bnv; Y = g_v; M = DHV;  m0 = (y - 4) * 128; }
    gemm16_body(WH, WL, g_xh + (long)b * 192 * NTOK, g_xl + (long)b * 192 * NTOK,
                bn, Y + (long)b * M * NTOK, M, 192, m0, blockIdx.x * 128, smu);
}

// Output projection (reads packed attention output)
__global__ __launch_bounds__(256, 2) void gemm_proj_tc(
    const float* __restrict__ bnp, float* __restrict__ out)
{
    __shared__ uint32_t smu[GEMM_SMEM_U32];
    const int b = blockIdx.z;
    gemm16_body(g_wph, g_wpl,
                g_xxh + (long)b * 512 * NTOK, g_xxl + (long)b * 512 * NTOK,
                bnp, out + (long)b * DIM * NTOK, DIM, 512,
                blockIdx.y * 128, blockIdx.x * 128, smu);
}

// ---------------- FA2 attention, fp16 m16n8k16 ------------------------------
// QK: 2x-split fp16; AV: P,V single fp16 with wide-load permuted layouts.
// V layout: [d][36] uint32, tokpair u at pos (u&3)*8 + 2*(u>>3) + ((u>>2)&1).
// P layout: [row][36] uint32, tokpair j=8s+4v+q at pos q*8 + 2*s + v.
// Output: packed hi/lo [dpair][tok] written directly from registers.
#define F_KH 0
#define F_KL 1152
#define F_VH 2304
#define F_P  6912
#define F_MP 9216
#define F_SP 9344
#define F_MR 9472
#define F_LR 9600
#define ATTN_SMEM_F 9664   // 38656 B

__global__ __launch_bounds__(256) void attn_fa()
{
    extern __shared__ float sm[];
    uint32_t* smu = (uint32_t*)sm;
    const int t = threadIdx.x, lane = t & 31, w = t >> 5;
    const int mi = w >> 1, ni = w & 1;
    const int g = lane >> 2, q = lane & 3;
    const int q0 = blockIdx.x * 64;
    const int b = blockIdx.y >> 3, h = blockIdx.y & 7;
    const float* qp = g_q + ((long)b * NHKD + h * KDIM) * NTOK;
    const float* kp = g_k + ((long)b * NHKD + h * KDIM) * NTOK;
    const float* vp = g_v + ((long)b * DHV  + h * DV  ) * NTOK;
    const float SQ = 5.656854249492380f, L2E = 1.44269504088896f;

    // stage Q [32 kd][64 q]*SQ into VH area (float, stride 72)
    {
        int kd = t >> 3, c8 = (t & 7) * 8;
        const float* s = qp + (long)kd * NTOK + q0 + c8;
        float4 u0 = *(const float4*)s, u1 = *(const float4*)(s + 4);
        u0.x *= SQ; u0.y *= SQ; u0.z *= SQ; u0.w *= SQ;
        u1.x *= SQ; u1.y *= SQ; u1.z *= SQ; u1.w *= SQ;
        *(float4*)(sm + F_VH + kd * 72 + c8)     = u0;
        *(float4*)(sm + F_VH + kd * 72 + c8 + 4) = u1;
    }
    if (t < 64) { sm[F_MR + t] = -1e30f; sm[F_MR + 64 + t] = -1e30f; sm[F_LR + t] = 0.f; }
    __syncthreads();

    const int r0 = mi * 16 + g;
    uint32_t qh[2][4], ql[2][4];
#pragma unroll
    for (int s = 0; s < 2; s++) {
        int kd0 = 16 * s + 2 * q;
        const float* Q = sm + F_VH;
        splitpack(Q[kd0 * 72 + r0],           Q[(kd0 + 1) * 72 + r0],     qh[s][0], ql[s][0]);
        splitpack(Q[kd0 * 72 + r0 + 8],       Q[(kd0 + 1) * 72 + r0 + 8], qh[s][1], ql[s][1]);
        splitpack(Q[(kd0 + 8) * 72 + r0],     Q[(kd0 + 9) * 72 + r0],     qh[s][2], ql[s][2]);
        splitpack(Q[(kd0 + 8) * 72 + r0 + 8], Q[(kd0 + 9) * 72 + r0 + 8], qh[s][3], ql[s][3]);
    }
    __syncthreads();

    float o[8][4];
#pragma unroll
    for (int nf = 0; nf < 8; nf++)
#pragma unroll
        for (int j = 0; j < 4; j++) o[nf][j] = 0.f;

    const int kpair = t >> 4, ktok4 = (t & 15) * 4;
    const int vd = t >> 1, vhalf = t & 1;

    for (int it = 0; it < 16; it++) {
        const int j0 = it * 64;
        __syncthreads();
        {
            const float* k0 = kp + (long)(2 * kpair) * NTOK + j0 + ktok4;
            float4 a4 = *(const float4*)k0;
            float4 b4 = *(const float4*)(k0 + NTOK);
            uint32_t hh[4], ll[4];
            splitpack(a4.x, b4.x, hh[0], ll[0]);
            splitpack(a4.y, b4.y, hh[1], ll[1]);
            splitpack(a4.z, b4.z, hh[2], ll[2]);
            splitpack(a4.w, b4.w, hh[3], ll[3]);
            *(uint4*)(smu + F_KH + kpair * 72 + ktok4) = make_uint4(hh[0], hh[1], hh[2], hh[3]);
            *(uint4*)(smu + F_KL + kpair * 72 + ktok4) = make_uint4(ll[0], ll[1], ll[2], ll[3]);
            // V: permuted tokpair slots for wide AV loads
            const float* vs_ = vp + (long)vd * NTOK + j0 + vhalf * 32;
#pragma unroll
            for (int jj = 0; jj < 4; jj++) {
                float4 u = *(const float4*)(vs_ + jj * 8);
                float4 v = *(const float4*)(vs_ + jj * 8 + 4);
                uint32_t vals[4] = {pack2(u.x, u.y), pack2(u.z, u.w),
                                    pack2(v.x, v.y), pack2(v.z, v.w)};
#pragma unroll
                for (int e = 0; e < 4; e++) {
                    int uu = jj * 4 + e;   // local within 16
                    int pos = e * 8 + 4 * vhalf + 2 * (uu >> 3) + ((uu >> 2) & 1);
                    smu[F_VH + vd * 36 + pos] = vals[e];
                }
            }
        }
        __syncthreads();

        // QK (2x-split fp16): S[16][32] per warp
        float s4[4][4];
#pragma unroll
        for (int nf = 0; nf < 4; nf++)
#pragma unroll
            for (int j = 0; j < 4; j++) s4[nf][j] = 0.f;
#pragma unroll
        for (int s = 0; s < 2; s++) {
#pragma unroll
            for (int nf = 0; nf < 4; nf++) {
                int col = ni * 32 + nf * 8 + g;
                uint32_t bh0 = smu[F_KH + (8 * s + q) * 72 + col];
                uint32_t bh1 = smu[F_KH + (8 * s + q + 4) * 72 + col];
                uint32_t bl0 = smu[F_KL + (8 * s + q) * 72 + col];
                uint32_t bl1 = smu[F_KL + (8 * s + q + 4) * 72 + col];
                mma16(s4[nf], qh[s], bh0, bh1);
                mma16(s4[nf], qh[s], bl0, bl1);
                mma16(s4[nf], ql[s], bh0, bh1);
            }
        }

        // warp-local row max -> MP
        {
            float m0 = fmaxf(fmaxf(s4[0][0], s4[0][1]), fmaxf(s4[1][0], s4[1][1]));
            m0 = fmaxf(m0, fmaxf(fmaxf(s4[2][0], s4[2][1]), fmaxf(s4[3][0], s4[3][1])));
            float m1 = fmaxf(fmaxf(s4[0][2], s4[0][3]), fmaxf(s4[1][2], s4[1][3]));
            m1 = fmaxf(m1, fmaxf(fmaxf(s4[2][2], s4[2][3]), fmaxf(s4[3][2], s4[3][3])));
            m0 = fmaxf(m0, __shfl_xor_sync(0xffffffffu, m0, 1));
            m0 = fmaxf(m0, __shfl_xor_sync(0xffffffffu, m0, 2));
            m1 = fmaxf(m1, __shfl_xor_sync(0xffffffffu, m1, 1));
            m1 = fmaxf(m1, __shfl_xor_sync(0xffffffffu, m1, 2));
            if (q == 0) {
                sm[F_MP + ni * 64 + r0] = m0;
                sm[F_MP + ni * 64 + r0 + 8] = m1;
            }
        }
        __syncthreads();

        // new max, alpha, P (fp16 half2, permuted positions), sums, O rescale
        {
            float moA = sm[F_MR + (it & 1) * 64 + r0];
            float moB = sm[F_MR + (it & 1) * 64 + r0 + 8];
            float mn0 = fmaxf(moA, fmaxf(sm[F_MP + r0], sm[F_MP + 64 + r0]));
            float mn1 = fmaxf(moB, fmaxf(sm[F_MP + r0 + 8], sm[F_MP + 64 + r0 + 8]));
            if (ni == 0 && q == 0) {
                sm[F_MR + ((it + 1) & 1) * 64 + r0] = mn0;
                sm[F_MR + ((it + 1) & 1) * 64 + r0 + 8] = mn1;
            }
            float al0 = fexp2((moA - mn0) * L2E);
            float al1 = fexp2((moB - mn1) * L2E);
            float c0 = -mn0 * L2E, c1 = -mn1 * L2E;
            float rs0 = 0.f, rs1 = 0.f;
#pragma unroll
            for (int nf = 0; nf < 4; nf++) {
                // tokpair j = ni*16 + nf*4 + q  ->  pos = q*8 + 2*s_g + v
                int posp = q * 8 + 4 * ni + 2 * (nf >> 1) + (nf & 1);
                float e00 = fexp2(fmaf(s4[nf][0], L2E, c0));
                float e01 = fexp2(fmaf(s4[nf][1], L2E, c0));
                float e10 = fexp2(fmaf(s4[nf][2], L2E, c1));
                float e11 = fexp2(fmaf(s4[nf][3], L2E, c1));
                rs0 += e00 + e01; rs1 += e10 + e11;
                smu[F_P + r0 * 36 + posp]       = pack2(e00, e01);
                smu[F_P + (r0 + 8) * 36 + posp] = pack2(e10, e11);
            }
            rs0 += __shfl_xor_sync(0xffffffffu, rs0, 1);
            rs0 += __shfl_xor_sync(0xffffffffu, rs0, 2);
            rs1 += __shfl_xor_sync(0xffffffffu, rs1, 1);
            rs1 += __shfl_xor_sync(0xffffffffu, rs1, 2);
            if (q == 0) {
                sm[F_SP + ni * 64 + r0] = rs0;
                sm[F_SP + ni * 64 + r0 + 8] = rs1;
            }
#pragma unroll
            for (int nf = 0; nf < 8; nf++) {
                o[nf][0] *= al0; o[nf][1] *= al0;
                o[nf][2] *= al1; o[nf][3] *= al1;
            }
        }
        __syncthreads();

        // l update (concurrent with AV)
        if (t < 64) {
            float mo = sm[F_MR + (it & 1) * 64 + t];
            float mn = sm[F_MR + ((it + 1) & 1) * 64 + t];
            sm[F_LR + t] = sm[F_LR + t] * fexp2((mo - mn) * L2E)
                         + sm[F_SP + t] + sm[F_SP + 64 + t];
        }

        // AV fp16 with wide loads: P 4 LDS.128, V 2 LDS.128 per nf
        {
            uint4 pa0 = *(const uint4*)(smu + F_P + r0 * 36 + q * 8);
            uint4 pa1 = *(const uint4*)(smu + F_P + r0 * 36 + q * 8 + 4);
            uint4 pb0 = *(const uint4*)(smu + F_P + (r0 + 8) * 36 + q * 8);
            uint4 pb1 = *(const uint4*)(smu + F_P + (r0 + 8) * 36 + q * 8 + 4);
            uint32_t a0[4] = {pa0.x, pb0.x, pa0.y, pb0.y};   // s=0
            uint32_t a1[4] = {pa0.z, pb0.z, pa0.w, pb0.w};   // s=1
            uint32_t a2[4] = {pa1.x, pb1.x, pa1.y, pb1.y};   // s=2
            uint32_t a3[4] = {pa1.z, pb1.z, pa1.w, pb1.w};   // s=3
#pragma unroll
            for (int nf = 0; nf < 8; nf++) {
                int d = ni * 64 + nf * 8 + g;
                uint4 vv0 = *(const uint4*)(smu + F_VH + d * 36 + q * 8);
                uint4 vv1 = *(const uint4*)(smu + F_VH + d * 36 + q * 8 + 4);
                mma16(o[nf], a0, vv0.x, vv0.y);
                mma16(o[nf], a1, vv0.z, vv0.w);
                mma16(o[nf], a2, vv1.x, vv1.y);
                mma16(o[nf], a3, vv1.z, vv1.w);
            }
        }
    }

    // epilogue: normalize and write packed hi/lo [dpair][tok] directly
    __syncthreads();
    {
        float inv0 = 1.0f / sm[F_LR + r0];
        float inv1 = 1.0f / sm[F_LR + r0 + 8];
#pragma unroll
        for (int nf = 0; nf < 8; nf++) {
            int d = ni * 64 + nf * 8 + 2 * q;          // channel pair (d, d+1)
            int dp = h * 64 + (d >> 1);
            long base = ((long)b * 512 + dp) * NTOK + q0;
            uint32_t h0, l0, h1, l1;
            splitpack(o[nf][0] * inv0, o[nf][1] * inv0, h0, l0);
            splitpack(o[nf][2] * inv1, o[nf][3] * inv1, h1, l1);
            g_xxh[base + r0]     = h0;
            g_xxl[base + r0]     = l0;
            g_xxh[base + r0 + 8] = h1;
            g_xxl[base + r0 + 8] = l1;
        }
    }
}

// ---------------------------------------------------------------------------
extern "C" void kernel_launch(void* const* d_in, const int* in_sizes, int n_in,
                              void* d_out, int out_size)
{
    const float* x   = (const float*)d_in[0];
    const float* wq  = (const float*)d_in[1];
    const float* bnq = (const float*)d_in[2];
    const float* wk  = (const float*)d_in[3];
    const float* bnk = (const float*)d_in[4];
    const float* wv  = (const float*)d_in[5];
    const float* bnv = (const float*)d_in[6];
    const float* wp  = (const float*)d_in[7];
    const float* bnp = (const float*)d_in[8];
    float* out = (float*)d_out;

    uint32_t *wqh, *wql, *wkh, *wkl, *wvh, *wvl, *wph, *wpl, *xh, *xl;
    cudaGetSymbolAddress((void**)&wqh, g_wqh);
    cudaGetSymbolAddress((void**)&wql, g_wql);
    cudaGetSymbolAddress((void**)&wkh, g_wkh);
    cudaGetSymbolAddress((void**)&wkl, g_wkl);
    cudaGetSymbolAddress((void**)&wvh, g_wvh);
    cudaGetSymbolAddress((void**)&wvl, g_wvl);
    cudaGetSymbolAddress((void**)&wph, g_wph);
    cudaGetSymbolAddress((void**)&wpl, g_wpl);
    cudaGetSymbolAddress((void**)&xh,  g_xh);
    cudaGetSymbolAddress((void**)&xl,  g_xl);

    const int smem_attn = ATTN_SMEM_F * 4;   // 38656 B
    cudaFuncSetAttribute(attn_fa, cudaFuncAttributeMaxDynamicSharedMemorySize,
                         smem_attn);
    dim3 blk(256);

    // prep: pack weights + x
    pack_w<<<192, blk>>>(wq, wqh, wql, NHKD, DIM);
    pack_w<<<192, blk>>>(wk, wkh, wkl, NHKD, DIM);
    pack_w<<<768, blk>>>(wv, wvh, wvl, DHV,  DIM);
    pack_w<<<768, blk>>>(wp, wph, wpl, DIM,  DHV);
    pack_x<<<dim3(768, BB), blk>>>(x, xh, xl, DIM);

    // fused QKV projections
    gemm_qkv_tc<<<dim3(8, 12, BB), blk>>>(bnq, bnk, bnv);

    // attention (writes packed xx)
    attn_fa<<<dim3(NTOK / 64, BB * NH), blk, smem_attn>>>();

    // output projection
    gemm_proj_tc<<<dim3(8, 3, BB), blk>>>(bnp, out);
}

// round 12
// speedup vs baseline: 4.8187x; 1.0140x over previous
#include <cuda_runtime.h>
#include <cuda_fp16.h>
#include <cstdint>
#include <math.h>

#define BB   16
#define DIM  384
#define NHKD 256
#define DHV  1024
#define NTOK 1024
#define NH   8
#define KDIM 32
#define DV   128

// float intermediates for attention inputs
__device__ float g_q [BB * NHKD * NTOK];
__device__ float g_k [BB * NHKD * NTOK];
__device__ float g_v [BB * DHV  * NTOK];
// packed fp16 hi/lo buffers
__device__ uint32_t g_xh [BB * 192 * NTOK];
__device__ uint32_t g_xl [BB * 192 * NTOK];
__device__ uint32_t g_xxh[BB * 512 * NTOK];
__device__ uint32_t g_xxl[BB * 512 * NTOK];
__device__ uint32_t g_wqh[192 * 256],  g_wql[192 * 256];
__device__ uint32_t g_wkh[192 * 256],  g_wkl[192 * 256];
__device__ uint32_t g_wvh[192 * 1024], g_wvl[192 * 1024];
__device__ uint32_t g_wph[512 * 384],  g_wpl[512 * 384];

__device__ __forceinline__ void mma16(float c[4], const uint32_t a[4],
                                      uint32_t b0, uint32_t b1) {
    asm volatile("mma.sync.aligned.m16n8k16.row.col.f32.f16.f16.f32 "
        "{%0,%1,%2,%3}, {%4,%5,%6,%7}, {%8,%9}, {%0,%1,%2,%3};"
        : "+f"(c[0]), "+f"(c[1]), "+f"(c[2]), "+f"(c[3])
        : "r"(a[0]), "r"(a[1]), "r"(a[2]), "r"(a[3]), "r"(b0), "r"(b1));
}
__device__ __forceinline__ uint32_t pack2(float x0, float x1) {
    __half2 h = __floats2half2_rn(x0, x1);
    return *(uint32_t*)&h;
}
__device__ __forceinline__ void splitpack(float x0, float x1,
                                          uint32_t& h, uint32_t& l) {
    __half2 hh = __floats2half2_rn(x0, x1);
    float2 bk = __half22float2(hh);
    __half2 ll = __floats2half2_rn(x0 - bk.x, x1 - bk.y);
    h = *(uint32_t*)&hh;
    l = *(uint32_t*)&ll;
}
__device__ __forceinline__ float fexp2(float z) {
    z = fmaxf(z, -100.0f);
    float zi = z + 12582912.0f;
    int   n  = __float_as_int(zi) - 0x4B400000;
    float t  = z - (zi - 12582912.0f);
    float p = fmaf(0.0013333558f, t, 0.0096181291f);
    p = fmaf(p, t, 0.0555041087f);
    p = fmaf(p, t, 0.2402265069f);
    p = fmaf(p, t, 0.6931471806f);
    p = fmaf(p, t, 1.0f);
    return __int_as_float(__float_as_int(p) + (n << 23));
}

// ---------------- prep: pack weights / activations to fp16 hi+lo ------------
__global__ __launch_bounds__(256) void pack_w(
    const float* __restrict__ W, uint32_t* __restrict__ H,
    uint32_t* __restrict__ L, int M, int K)
{
    int idx = blockIdx.x * 256 + threadIdx.x;
    int p = idx / M, m = idx - p * M;
    float a = W[(long)m * K + 2 * p];
    float b = W[(long)m * K + 2 * p + 1];
    uint32_t hh, ll;
    splitpack(a, b, hh, ll);
    H[idx] = hh; L[idx] = ll;
}
__global__ __launch_bounds__(256) void pack_x(
    const float* __restrict__ X, uint32_t* __restrict__ H,
    uint32_t* __restrict__ L, int C)
{
    int idx = blockIdx.x * 256 + threadIdx.x;
    int b = blockIdx.y;
    int p = idx >> 10, n = idx & 1023;
    long src = ((long)b * C + 2 * p) * NTOK + n;
    uint32_t hh, ll;
    splitpack(X[src], X[src + NTOK], hh, ll);
    long dst = ((long)b * (C >> 1) + p) * NTOK + n;
    H[dst] = hh; L[dst] = ll;
}

// ============ fp16 3x-split tensor GEMM + BN (128x128), packed inputs ======
#define SW_H 0
#define SW_L 2112
#define SX_H 4224
#define SX_L 6336
#define GEMM_SMEM_U32 8448

__device__ __forceinline__ void gemm16_body(
    const uint32_t* __restrict__ WH, const uint32_t* __restrict__ WL,
    const uint32_t* __restrict__ XH, const uint32_t* __restrict__ XL,
    const float* __restrict__ bn, float* __restrict__ Yb,
    int M, int Kp, int m0, int n0, uint32_t* smu)
{
    const int t = threadIdx.x, lane = t & 31, w = t >> 5;
    const int g = lane >> 2, q = lane & 3;
    const int mw = (w >> 2) * 64, nw = (w & 3) * 32;
    const int sp = t >> 5;
    const int c4 = (t & 31) * 4;

    float c[4][4][4];
#pragma unroll
    for (int i = 0; i < 4; i++)
#pragma unroll
        for (int j = 0; j < 4; j++)
#pragma unroll
            for (int r = 0; r < 4; r++) c[i][j][r] = 0.f;

    const int nc = Kp >> 4;
    for (int ch = 0; ch < nc; ch++) {
        const int pc = ch * 16;
        uint4 wh[2], wl[2], xh[2], xl[2];
#pragma unroll
        for (int r = 0; r < 2; r++) {
            int p = sp + 8 * r;
            wh[r] = *(const uint4*)(WH + (long)(pc + p) * M + m0 + c4);
            wl[r] = *(const uint4*)(WL + (long)(pc + p) * M + m0 + c4);
            xh[r] = *(const uint4*)(XH + (long)(pc + p) * NTOK + n0 + c4);
            xl[r] = *(const uint4*)(XL + (long)(pc + p) * NTOK + n0 + c4);
        }
        __syncthreads();
#pragma unroll
        for (int r = 0; r < 2; r++) {
            int p = sp + 8 * r;
            *(uint4*)(smu + SW_H + p * 132 + c4) = wh[r];
            *(uint4*)(smu + SW_L + p * 132 + c4) = wl[r];
            *(uint4*)(smu + SX_H + p * 132 + c4) = xh[r];
            *(uint4*)(smu + SX_L + p * 132 + c4) = xl[r];
        }
        __syncthreads();
#pragma unroll
        for (int ks = 0; ks < 2; ks++) {
            const int p0 = ks * 8 + q, p1 = p0 + 4;
            uint32_t ah[4][4], al[4][4];
#pragma unroll
            for (int mf = 0; mf < 4; mf++) {
                int colm = mw + mf * 16 + g;
                ah[mf][0] = smu[SW_H + p0 * 132 + colm];
                ah[mf][1] = smu[SW_H + p0 * 132 + colm + 8];
                ah[mf][2] = smu[SW_H + p1 * 132 + colm];
                ah[mf][3] = smu[SW_H + p1 * 132 + colm + 8];
                al[mf][0] = smu[SW_L + p0 * 132 + colm];
                al[mf][1] = smu[SW_L + p0 * 132 + colm + 8];
                al[mf][2] = smu[SW_L + p1 * 132 + colm];
                al[mf][3] = smu[SW_L + p1 * 132 + colm + 8];
            }
#pragma unroll
            for (int nf = 0; nf < 4; nf++) {
                int coln = nw + nf * 8 + g;
                uint32_t b0h = smu[SX_H + p0 * 132 + coln];
                uint32_t b1h = smu[SX_H + p1 * 132 + coln];
                uint32_t b0l = smu[SX_L + p0 * 132 + coln];
                uint32_t b1l = smu[SX_L + p1 * 132 + coln];
#pragma unroll
                for (int mf = 0; mf < 4; mf++) {
                    mma16(c[mf][nf], ah[mf], b0h, b1h);
                    mma16(c[mf][nf], ah[mf], b0l, b1l);
                    mma16(c[mf][nf], al[mf], b0h, b1h);
                }
            }
        }
    }

#pragma unroll
    for (int mf = 0; mf < 4; mf++) {
        int r0 = m0 + mw + mf * 16 + g;
        int r1 = r0 + 8;
        float sc0 = bn[r0] * rsqrtf(bn[3 * M + r0] + 1e-5f);
        float tt0 = bn[M + r0] - bn[2 * M + r0] * sc0;
        float sc1 = bn[r1] * rsqrtf(bn[3 * M + r1] + 1e-5f);
        float tt1 = bn[M + r1] - bn[2 * M + r1] * sc1;
#pragma unroll
        for (int nf = 0; nf < 4; nf++) {
            int nn = n0 + nw + nf * 8 + 2 * q;
            float2 v0, v1;
            v0.x = c[mf][nf][0] * sc0 + tt0;
            v0.y = c[mf][nf][1] * sc0 + tt0;
            v1.x = c[mf][nf][2] * sc1 + tt1;
            v1.y = c[mf][nf][3] * sc1 + tt1;
            *(float2*)(Yb + (long)r0 * NTOK + nn) = v0;
            *(float2*)(Yb + (long)r1 * NTOK + nn) = v1;
        }
    }
}

__global__ __launch_bounds__(256, 2) void gemm_qkv_tc(
    const float* __restrict__ bnq, const float* __restrict__ bnk,
    const float* __restrict__ bnv)
{
    __shared__ uint32_t smu[GEMM_SMEM_U32];
    const int y = blockIdx.y, b = blockIdx.z;
    const uint32_t *WH, *WL;
    const float* bn;
    float* Y;
    int M, m0;
    if (y < 2)      { WH = g_wqh; WL = g_wql; bn = bnq; Y = g_q; M = NHKD; m0 = y * 128; }
    else if (y < 4) { WH = g_wkh; WL = g_wkl; bn = bnk; Y = g_k; M = NHKD; m0 = (y - 2) * 128; }
    else            { WH = g_wvh; WL = g_wvl; bn = bnv; Y = g_v; M = DHV;  m0 = (y - 4) * 128; }
    gemm16_body(WH, WL, g_xh + (long)b * 192 * NTOK, g_xl + (long)b * 192 * NTOK,
                bn, Y + (long)b * M * NTOK, M, 192, m0, blockIdx.x * 128, smu);
}

__global__ __launch_bounds__(256, 2) void gemm_proj_tc(
    const float* __restrict__ bnp, float* __restrict__ out)
{
    __shared__ uint32_t smu[GEMM_SMEM_U32];
    const int b = blockIdx.z;
    gemm16_body(g_wph, g_wpl,
                g_xxh + (long)b * 512 * NTOK, g_xxl + (long)b * 512 * NTOK,
                bnp, out + (long)b * DIM * NTOK, DIM, 512,
                blockIdx.y * 128, blockIdx.x * 128, smu);
}

// ---------------- FA2 attention, fp16 m16n8k16, 128-key iterations ----------
// Warp (mi=w>>1, ni=w&1): QK S[16q][64k] at cols ni*64; AV O[16q][64d] at
// d cols ni*64. P layout [64 rows][76]: slot = half*32 + q*8 + nf (uint4-able).
// V layout [128 d][76]: slot = half*32 + e*8 + jj. Strides 76 -> conflict-free
// LDS.128 in AV (12g+8q distinct per 8-lane phase).
#define F2_KH 0
#define F2_KL 2176
#define F2_VH 4352
#define F2_P  14080
#define F2_MP 18944
#define F2_SP 19072
#define F2_MR 19200
#define F2_LR 19328
#define ATTN_SMEM_U32 19392   // 77568 B

__global__ __launch_bounds__(256, 2) void attn_fa()
{
    extern __shared__ float sm[];
    uint32_t* smu = (uint32_t*)sm;
    const int t = threadIdx.x, lane = t & 31, w = t >> 5;
    const int mi = w >> 1, ni = w & 1;
    const int g = lane >> 2, q = lane & 3;
    const int q0 = blockIdx.x * 64;
    const int b = blockIdx.y >> 3, h = blockIdx.y & 7;
    const float* qp = g_q + ((long)b * NHKD + h * KDIM) * NTOK;
    const float* kp = g_k + ((long)b * NHKD + h * KDIM) * NTOK;
    const float* vp = g_v + ((long)b * DHV  + h * DV  ) * NTOK;
    const float SQ = 5.656854249492380f, L2E = 1.44269504088896f;

    // stage Q [32 kd][64 q]*SQ into VH area (float, stride 72)
    {
        int kd = t >> 3, c8 = (t & 7) * 8;
        const float* s = qp + (long)kd * NTOK + q0 + c8;
        float4 u0 = *(const float4*)s, u1 = *(const float4*)(s + 4);
        u0.x *= SQ; u0.y *= SQ; u0.z *= SQ; u0.w *= SQ;
        u1.x *= SQ; u1.y *= SQ; u1.z *= SQ; u1.w *= SQ;
        *(float4*)(sm + F2_VH + kd * 72 + c8)     = u0;
        *(float4*)(sm + F2_VH + kd * 72 + c8 + 4) = u1;
    }
    if (t < 64) { sm[F2_MR + t] = -1e30f; sm[F2_MR + 64 + t] = -1e30f; sm[F2_LR + t] = 0.f; }
    __syncthreads();

    const int r0 = mi * 16 + g;
    uint32_t qh[2][4], ql[2][4];
#pragma unroll
    for (int s = 0; s < 2; s++) {
        int kd0 = 16 * s + 2 * q;
        const float* Q = sm + F2_VH;
        splitpack(Q[kd0 * 72 + r0],           Q[(kd0 + 1) * 72 + r0],     qh[s][0], ql[s][0]);
        splitpack(Q[kd0 * 72 + r0 + 8],       Q[(kd0 + 1) * 72 + r0 + 8], qh[s][1], ql[s][1]);
        splitpack(Q[(kd0 + 8) * 72 + r0],     Q[(kd0 + 9) * 72 + r0],     qh[s][2], ql[s][2]);
        splitpack(Q[(kd0 + 8) * 72 + r0 + 8], Q[(kd0 + 9) * 72 + r0 + 8], qh[s][3], ql[s][3]);
    }
    __syncthreads();

    float o[8][4];
#pragma unroll
    for (int nf = 0; nf < 8; nf++)
#pragma unroll
        for (int j = 0; j < 4; j++) o[nf][j] = 0.f;

    const int kpair = t >> 4, ktok8 = (t & 15) * 8;   // K staging
    const int vd = t >> 1, hfv = t & 1;               // V staging

    for (int it = 0; it < 8; it++) {
        const int j0 = it * 128;
        __syncthreads();   // prev iter's K/V/P reads done
        // ---- K stage: 32 kd x 128 tok, hi/lo split
        {
            const float* k0 = kp + (long)(2 * kpair) * NTOK + j0 + ktok8;
            float4 a0 = *(const float4*)k0;
            float4 a1 = *(const float4*)(k0 + 4);
            float4 b0 = *(const float4*)(k0 + NTOK);
            float4 b1 = *(const float4*)(k0 + NTOK + 4);
            uint32_t hh[8], ll[8];
            splitpack(a0.x, b0.x, hh[0], ll[0]);
            splitpack(a0.y, b0.y, hh[1], ll[1]);
            splitpack(a0.z, b0.z, hh[2], ll[2]);
            splitpack(a0.w, b0.w, hh[3], ll[3]);
            splitpack(a1.x, b1.x, hh[4], ll[4]);
            splitpack(a1.y, b1.y, hh[5], ll[5]);
            splitpack(a1.z, b1.z, hh[6], ll[6]);
            splitpack(a1.w, b1.w, hh[7], ll[7]);
            *(uint4*)(smu + F2_KH + kpair * 136 + ktok8)     = make_uint4(hh[0], hh[1], hh[2], hh[3]);
            *(uint4*)(smu + F2_KH + kpair * 136 + ktok8 + 4) = make_uint4(hh[4], hh[5], hh[6], hh[7]);
            *(uint4*)(smu + F2_KL + kpair * 136 + ktok8)     = make_uint4(ll[0], ll[1], ll[2], ll[3]);
            *(uint4*)(smu + F2_KL + kpair * 136 + ktok8 + 4) = make_uint4(ll[4], ll[5], ll[6], ll[7]);
        }
        // ---- V stage: 128 d x 128 tok (single fp16, permuted, STS.128)
        {
            const float* vs_ = vp + (long)vd * NTOK + j0 + hfv * 64;
#pragma unroll
            for (int r = 0; r < 2; r++) {
                uint32_t vals[4][4];
#pragma unroll
                for (int j2 = 0; j2 < 4; j2++) {
                    int jj = r * 4 + j2;
                    float4 u0 = *(const float4*)(vs_ + jj * 8);
                    float4 u1 = *(const float4*)(vs_ + jj * 8 + 4);
                    vals[0][j2] = pack2(u0.x, u0.y);
                    vals[1][j2] = pack2(u0.z, u0.w);
                    vals[2][j2] = pack2(u1.x, u1.y);
                    vals[3][j2] = pack2(u1.z, u1.w);
                }
#pragma unroll
                for (int e = 0; e < 4; e++)
                    *(uint4*)(smu + F2_VH + vd * 76 + hfv * 32 + e * 8 + r * 4) =
                        make_uint4(vals[e][0], vals[e][1], vals[e][2], vals[e][3]);
            }
        }
        __syncthreads();

        // ---- QK (2x-split fp16): S[16][64] per warp
        float s4[8][4];
#pragma unroll
        for (int nf = 0; nf < 8; nf++)
#pragma unroll
            for (int j = 0; j < 4; j++) s4[nf][j] = 0.f;
#pragma unroll
        for (int s = 0; s < 2; s++) {
#pragma unroll
            for (int nf = 0; nf < 8; nf++) {
                int col = ni * 64 + nf * 8 + g;
                uint32_t bh0 = smu[F2_KH + (8 * s + q) * 136 + col];
                uint32_t bh1 = smu[F2_KH + (8 * s + q + 4) * 136 + col];
                uint32_t bl0 = smu[F2_KL + (8 * s + q) * 136 + col];
                uint32_t bl1 = smu[F2_KL + (8 * s + q + 4) * 136 + col];
                mma16(s4[nf], qh[s], bh0, bh1);
                mma16(s4[nf], qh[s], bl0, bl1);
                mma16(s4[nf], ql[s], bh0, bh1);
            }
        }

        // ---- warp-local row max -> MP
        {
            float m0 = fmaxf(s4[0][0], s4[0][1]);
            float m1 = fmaxf(s4[0][2], s4[0][3]);
#pragma unroll
            for (int nf = 1; nf < 8; nf++) {
                m0 = fmaxf(m0, fmaxf(s4[nf][0], s4[nf][1]));
                m1 = fmaxf(m1, fmaxf(s4[nf][2], s4[nf][3]));
            }
            m0 = fmaxf(m0, __shfl_xor_sync(0xffffffffu, m0, 1));
            m0 = fmaxf(m0, __shfl_xor_sync(0xffffffffu, m0, 2));
            m1 = fmaxf(m1, __shfl_xor_sync(0xffffffffu, m1, 1));
            m1 = fmaxf(m1, __shfl_xor_sync(0xffffffffu, m1, 2));
            if (q == 0) {
                sm[F2_MP + ni * 64 + r0] = m0;
                sm[F2_MP + ni * 64 + r0 + 8] = m1;
            }
        }
        __syncthreads();

        // ---- new max, alpha, P (uint4 stores), partial sums, O rescale
        {
            float moA = sm[F2_MR + (it & 1) * 64 + r0];
            float moB = sm[F2_MR + (it & 1) * 64 + r0 + 8];
            float mn0 = fmaxf(moA, fmaxf(sm[F2_MP + r0], sm[F2_MP + 64 + r0]));
            float mn1 = fmaxf(moB, fmaxf(sm[F2_MP + r0 + 8], sm[F2_MP + 64 + r0 + 8]));
            if (ni == 0 && q == 0) {
                sm[F2_MR + ((it + 1) & 1) * 64 + r0] = mn0;
                sm[F2_MR + ((it + 1) & 1) * 64 + r0 + 8] = mn1;
            }
            float al0 = fexp2((moA - mn0) * L2E);
            float al1 = fexp2((moB - mn1) * L2E);
            float c0 = -mn0 * L2E, c1 = -mn1 * L2E;
            float rs0 = 0.f, rs1 = 0.f;
            uint32_t p0v[8], p1v[8];
#pragma unroll
            for (int nf = 0; nf < 8; nf++) {
                float e00 = fexp2(fmaf(s4[nf][0], L2E, c0));
                float e01 = fexp2(fmaf(s4[nf][1], L2E, c0));
                float e10 = fexp2(fmaf(s4[nf][2], L2E, c1));
                float e11 = fexp2(fmaf(s4[nf][3], L2E, c1));
                rs0 += e00 + e01; rs1 += e10 + e11;
                p0v[nf] = pack2(e00, e01);
                p1v[nf] = pack2(e10, e11);
            }
            {
                uint32_t base = F2_P + r0 * 76 + ni * 32 + q * 8;
                *(uint4*)(smu + base)     = make_uint4(p0v[0], p0v[1], p0v[2], p0v[3]);
                *(uint4*)(smu + base + 4) = make_uint4(p0v[4], p0v[5], p0v[6], p0v[7]);
                uint32_t base1 = F2_P + (r0 + 8) * 76 + ni * 32 + q * 8;
                *(uint4*)(smu + base1)     = make_uint4(p1v[0], p1v[1], p1v[2], p1v[3]);
                *(uint4*)(smu + base1 + 4) = make_uint4(p1v[4], p1v[5], p1v[6], p1v[7]);
            }
            rs0 += __shfl_xor_sync(0xffffffffu, rs0, 1);
            rs0 += __shfl_xor_sync(0xffffffffu, rs0, 2);
            rs1 += __shfl_xor_sync(0xffffffffu, rs1, 1);
            rs1 += __shfl_xor_sync(0xffffffffu, rs1, 2);
            if (q == 0) {
                sm[F2_SP + ni * 64 + r0] = rs0;
                sm[F2_SP + ni * 64 + r0 + 8] = rs1;
            }
#pragma unroll
            for (int nf = 0; nf < 8; nf++) {
                o[nf][0] *= al0; o[nf][1] *= al0;
                o[nf][2] *= al1; o[nf][3] *= al1;
            }
        }
        __syncthreads();

        // ---- l update (concurrent with AV)
        if (t < 64) {
            float mo = sm[F2_MR + (it & 1) * 64 + t];
            float mn = sm[F2_MR + ((it + 1) & 1) * 64 + t];
            sm[F2_LR + t] = sm[F2_LR + t] * fexp2((mo - mn) * L2E)
                          + sm[F2_SP + t] + sm[F2_SP + 64 + t];
        }

        // ---- AV fp16, 128 keys = 2 halves x 4 k-steps
#pragma unroll
        for (int hf = 0; hf < 2; hf++) {
            uint4 pa0 = *(const uint4*)(smu + F2_P + r0 * 76 + hf * 32 + q * 8);
            uint4 pa1 = *(const uint4*)(smu + F2_P + r0 * 76 + hf * 32 + q * 8 + 4);
            uint4 pb0 = *(const uint4*)(smu + F2_P + (r0 + 8) * 76 + hf * 32 + q * 8);
            uint4 pb1 = *(const uint4*)(smu + F2_P + (r0 + 8) * 76 + hf * 32 + q * 8 + 4);
            uint32_t pa[8] = {pa0.x, pa0.y, pa0.z, pa0.w, pa1.x, pa1.y, pa1.z, pa1.w};
            uint32_t pb[8] = {pb0.x, pb0.y, pb0.z, pb0.w, pb1.x, pb1.y, pb1.z, pb1.w};
            uint32_t as_[4][4];
#pragma unroll
            for (int s = 0; s < 4; s++) {
                as_[s][0] = pa[2 * s];     as_[s][1] = pb[2 * s];
                as_[s][2] = pa[2 * s + 1]; as_[s][3] = pb[2 * s + 1];
            }
#pragma unroll
            for (int nf = 0; nf < 8; nf++) {
                int d = ni * 64 + nf * 8 + g;
                uint4 v0 = *(const uint4*)(smu + F2_VH + d * 76 + hf * 32 + q * 8);
                uint4 v1 = *(const uint4*)(smu + F2_VH + d * 76 + hf * 32 + q * 8 + 4);
                uint32_t vv[8] = {v0.x, v0.y, v0.z, v0.w, v1.x, v1.y, v1.z, v1.w};
#pragma unroll
                for (int s = 0; s < 4; s++)
                    mma16(o[nf], as_[s], vv[2 * s], vv[2 * s + 1]);
            }
        }
    }

    // epilogue: normalize, write packed hi/lo [dpair][tok] directly
    __syncthreads();
    {
        float inv0 = 1.0f / sm[F2_LR + r0];
        float inv1 = 1.0f / sm[F2_LR + r0 + 8];
#pragma unroll
        for (int nf = 0; nf < 8; nf++) {
            int d = ni * 64 + nf * 8 + 2 * q;
            int dp = h * 64 + (d >> 1);
            long base = ((long)b * 512 + dp) * NTOK + q0;
            uint32_t h0, l0, h1, l1;
            splitpack(o[nf][0] * inv0, o[nf][1] * inv0, h0, l0);
            splitpack(o[nf][2] * inv1, o[nf][3] * inv1, h1, l1);
            g_xxh[base + r0]     = h0;
            g_xxl[base + r0]     = l0;
            g_xxh[base + r0 + 8] = h1;
            g_xxl[base + r0 + 8] = l1;
        }
    }
}

// ---------------------------------------------------------------------------
extern "C" void kernel_launch(void* const* d_in, const int* in_sizes, int n_in,
                              void* d_out, int out_size)
{
    const float* x   = (const float*)d_in[0];
    const float* wq  = (const float*)d_in[1];
    const float* bnq = (const float*)d_in[2];
    const float* wk  = (const float*)d_in[3];
    const float* bnk = (const float*)d_in[4];
    const float* wv  = (const float*)d_in[5];
    const float* bnv = (const float*)d_in[6];
    const float* wp  = (const float*)d_in[7];
    const float* bnp = (const float*)d_in[8];
    float* out = (float*)d_out;

    uint32_t *wqh, *wql, *wkh, *wkl, *wvh, *wvl, *wph, *wpl, *xh, *xl;
    cudaGetSymbolAddress((void**)&wqh, g_wqh);
    cudaGetSymbolAddress((void**)&wql, g_wql);
    cudaGetSymbolAddress((void**)&wkh, g_wkh);
    cudaGetSymbolAddress((void**)&wkl, g_wkl);
    cudaGetSymbolAddress((void**)&wvh, g_wvh);
    cudaGetSymbolAddress((void**)&wvl, g_wvl);
    cudaGetSymbolAddress((void**)&wph, g_wph);
    cudaGetSymbolAddress((void**)&wpl, g_wpl);
    cudaGetSymbolAddress((void**)&xh,  g_xh);
    cudaGetSymbolAddress((void**)&xl,  g_xl);

    const int smem_attn = ATTN_SMEM_U32 * 4;   // 77568 B
    cudaFuncSetAttribute(attn_fa, cudaFuncAttributeMaxDynamicSharedMemorySize,
                         smem_attn);
    dim3 blk(256);

    pack_w<<<192, blk>>>(wq, wqh, wql, NHKD, DIM);
    pack_w<<<192, blk>>>(wk, wkh, wkl, NHKD, DIM);
    pack_w<<<768, blk>>>(wv, wvh, wvl, DHV,  DIM);
    pack_w<<<768, blk>>>(wp, wph, wpl, DIM,  DHV);
    pack_x<<<dim3(768, BB), blk>>>(x, xh, xl, DIM);

    gemm_qkv_tc<<<dim3(8, 12, BB), blk>>>(bnq, bnk, bnv);
    attn_fa<<<dim3(NTOK / 64, BB * NH), blk, smem_attn>>>();
    gemm_proj_tc<<<dim3(8, 3, BB), blk>>>(bnp, out);
}

// round 13
// speedup vs baseline: 5.6742x; 1.1775x over previous
#include <cuda_runtime.h>
#include <cuda_fp16.h>
#include <cstdint>
#include <math.h>

#define BB   16
#define DIM  384
#define NHKD 256
#define DHV  1024
#define NTOK 1024
#define NH   8
#define KDIM 32
#define DV   128

// float intermediates (Q/K only; V goes straight to packed)
__device__ float g_q [BB * NHKD * NTOK];
__device__ float g_k [BB * NHKD * NTOK];
// packed fp16 hi/lo buffers
__device__ uint32_t g_xh [BB * 192 * NTOK];
__device__ uint32_t g_xl [BB * 192 * NTOK];
__device__ uint32_t g_xxh[BB * 512 * NTOK];
__device__ uint32_t g_xxl[BB * 512 * NTOK];
__device__ uint32_t g_qph[BB * 128 * NTOK], g_qpl[BB * 128 * NTOK];
__device__ uint32_t g_kph[BB * 128 * NTOK], g_kpl[BB * 128 * NTOK];
__device__ uint32_t g_vp [BB * 1024 * 512];           // V packed, permuted slots
__device__ uint32_t g_wqh[192 * 256],  g_wql[192 * 256];
__device__ uint32_t g_wkh[192 * 256],  g_wkl[192 * 256];
__device__ uint32_t g_wvh[192 * 1024], g_wvl[192 * 1024];
__device__ uint32_t g_wph[512 * 384],  g_wpl[512 * 384];

__device__ __forceinline__ void mma16(float c[4], const uint32_t a[4],
                                      uint32_t b0, uint32_t b1) {
    asm volatile("mma.sync.aligned.m16n8k16.row.col.f32.f16.f16.f32 "
        "{%0,%1,%2,%3}, {%4,%5,%6,%7}, {%8,%9}, {%0,%1,%2,%3};"
        : "+f"(c[0]), "+f"(c[1]), "+f"(c[2]), "+f"(c[3])
        : "r"(a[0]), "r"(a[1]), "r"(a[2]), "r"(a[3]), "r"(b0), "r"(b1));
}
__device__ __forceinline__ uint32_t pack2(float x0, float x1) {
    __half2 h = __floats2half2_rn(x0, x1);
    return *(uint32_t*)&h;
}
__device__ __forceinline__ void splitpack(float x0, float x1,
                                          uint32_t& h, uint32_t& l) {
    __half2 hh = __floats2half2_rn(x0, x1);
    float2 bk = __half22float2(hh);
    __half2 ll = __floats2half2_rn(x0 - bk.x, x1 - bk.y);
    h = *(uint32_t*)&hh;
    l = *(uint32_t*)&ll;
}
__device__ __forceinline__ float fexp2(float z) {
    z = fmaxf(z, -100.0f);
    float zi = z + 12582912.0f;
    int   n  = __float_as_int(zi) - 0x4B400000;
    float t  = z - (zi - 12582912.0f);
    float p = fmaf(0.0013333558f, t, 0.0096181291f);
    p = fmaf(p, t, 0.0555041087f);
    p = fmaf(p, t, 0.2402265069f);
    p = fmaf(p, t, 0.6931471806f);
    p = fmaf(p, t, 1.0f);
    return __int_as_float(__float_as_int(p) + (n << 23));
}

// ---------------- prep kernels ----------------------------------------------
__global__ __launch_bounds__(256) void pack_w(
    const float* __restrict__ W, uint32_t* __restrict__ H,
    uint32_t* __restrict__ L, int M, int K)
{
    int idx = blockIdx.x * 256 + threadIdx.x;
    int p = idx / M, m = idx - p * M;
    float a = W[(long)m * K + 2 * p];
    float b = W[(long)m * K + 2 * p + 1];
    uint32_t hh, ll;
    splitpack(a, b, hh, ll);
    H[idx] = hh; L[idx] = ll;
}
__global__ __launch_bounds__(256) void pack_x(
    const float* __restrict__ X, uint32_t* __restrict__ H,
    uint32_t* __restrict__ L, int C)
{
    int idx = blockIdx.x * 256 + threadIdx.x;
    int b = blockIdx.y;
    int p = idx >> 10, n = idx & 1023;
    long src = ((long)b * C + 2 * p) * NTOK + n;
    uint32_t hh, ll;
    splitpack(X[src], X[src + NTOK], hh, ll);
    long dst = ((long)b * (C >> 1) + p) * NTOK + n;
    H[dst] = hh; L[dst] = ll;
}
// Q/K float [b][256 kd][1024] -> packed hi/lo [b][128 kpair][1024] (x scale)
__global__ __launch_bounds__(256) void pack_qk(
    const float* __restrict__ X, uint32_t* __restrict__ H,
    uint32_t* __restrict__ L, float scale)
{
    int idx = blockIdx.x * 256 + threadIdx.x;   // 128*1024 per batch
    int b = blockIdx.y;
    int p = idx >> 10, n = idx & 1023;
    long src = ((long)b * 256 + 2 * p) * NTOK + n;
    uint32_t hh, ll;
    splitpack(X[src] * scale, X[src + NTOK] * scale, hh, ll);
    long dst = ((long)b * 128 + p) * NTOK + n;
    H[dst] = hh; L[dst] = ll;
}

// ============ fp16 3x-split tensor GEMM + BN (128x128), packed inputs ======
#define SW_H 0
#define SW_L 2112
#define SX_H 4224
#define SX_L 6336
#define GEMM_SMEM_U32 8448

template <bool PACKV>
__device__ __forceinline__ void gemm16_body(
    const uint32_t* __restrict__ WH, const uint32_t* __restrict__ WL,
    const uint32_t* __restrict__ XH, const uint32_t* __restrict__ XL,
    const float* __restrict__ bn, float* __restrict__ Yb,
    uint32_t* __restrict__ Vout,
    int M, int Kp, int m0, int n0, uint32_t* smu)
{
    const int t = threadIdx.x, lane = t & 31, w = t >> 5;
    const int g = lane >> 2, q = lane & 3;
    const int mw = (w >> 2) * 64, nw = (w & 3) * 32;
    const int sp = t >> 5;
    const int c4 = (t & 31) * 4;

    float c[4][4][4];
#pragma unroll
    for (int i = 0; i < 4; i++)
#pragma unroll
        for (int j = 0; j < 4; j++)
#pragma unroll
            for (int r = 0; r < 4; r++) c[i][j][r] = 0.f;

    const int nc = Kp >> 4;
    for (int ch = 0; ch < nc; ch++) {
        const int pc = ch * 16;
        uint4 wh[2], wl[2], xh[2], xl[2];
#pragma unroll
        for (int r = 0; r < 2; r++) {
            int p = sp + 8 * r;
            wh[r] = *(const uint4*)(WH + (long)(pc + p) * M + m0 + c4);
            wl[r] = *(const uint4*)(WL + (long)(pc + p) * M + m0 + c4);
            xh[r] = *(const uint4*)(XH + (long)(pc + p) * NTOK + n0 + c4);
            xl[r] = *(const uint4*)(XL + (long)(pc + p) * NTOK + n0 + c4);
        }
        __syncthreads();
#pragma unroll
        for (int r = 0; r < 2; r++) {
            int p = sp + 8 * r;
            *(uint4*)(smu + SW_H + p * 132 + c4) = wh[r];
            *(uint4*)(smu + SW_L + p * 132 + c4) = wl[r];
            *(uint4*)(smu + SX_H + p * 132 + c4) = xh[r];
            *(uint4*)(smu + SX_L + p * 132 + c4) = xl[r];
        }
        __syncthreads();
#pragma unroll
        for (int ks = 0; ks < 2; ks++) {
            const int p0 = ks * 8 + q, p1 = p0 + 4;
            uint32_t ah[4][4], al[4][4];
#pragma unroll
            for (int mf = 0; mf < 4; mf++) {
                int colm = mw + mf * 16 + g;
                ah[mf][0] = smu[SW_H + p0 * 132 + colm];
                ah[mf][1] = smu[SW_H + p0 * 132 + colm + 8];
                ah[mf][2] = smu[SW_H + p1 * 132 + colm];
                ah[mf][3] = smu[SW_H + p1 * 132 + colm + 8];
                al[mf][0] = smu[SW_L + p0 * 132 + colm];
                al[mf][1] = smu[SW_L + p0 * 132 + colm + 8];
                al[mf][2] = smu[SW_L + p1 * 132 + colm];
                al[mf][3] = smu[SW_L + p1 * 132 + colm + 8];
            }
#pragma unroll
            for (int nf = 0; nf < 4; nf++) {
                int coln = nw + nf * 8 + g;
                uint32_t b0h = smu[SX_H + p0 * 132 + coln];
                uint32_t b1h = smu[SX_H + p1 * 132 + coln];
                uint32_t b0l = smu[SX_L + p0 * 132 + coln];
                uint32_t b1l = smu[SX_L + p1 * 132 + coln];
#pragma unroll
                for (int mf = 0; mf < 4; mf++) {
                    mma16(c[mf][nf], ah[mf], b0h, b1h);
                    mma16(c[mf][nf], ah[mf], b0l, b1l);
                    mma16(c[mf][nf], al[mf], b0h, b1h);
                }
            }
        }
    }

#pragma unroll
    for (int mf = 0; mf < 4; mf++) {
        int r0 = m0 + mw + mf * 16 + g;
        int r1 = r0 + 8;
        float sc0 = bn[r0] * rsqrtf(bn[3 * M + r0] + 1e-5f);
        float tt0 = bn[M + r0] - bn[2 * M + r0] * sc0;
        float sc1 = bn[r1] * rsqrtf(bn[3 * M + r1] + 1e-5f);
        float tt1 = bn[M + r1] - bn[2 * M + r1] * sc1;
        if (PACKV) {
            // V: write packed fp16 directly in attention's permuted slot layout
            uint32_t a0[4], a1[4];
#pragma unroll
            for (int nf = 0; nf < 4; nf++) {
                a0[nf] = pack2(c[mf][nf][0] * sc0 + tt0, c[mf][nf][1] * sc0 + tt0);
                a1[nf] = pack2(c[mf][nf][2] * sc1 + tt1, c[mf][nf][3] * sc1 + tt1);
            }
            int slot = (n0 >> 1) + ((nw & 64) ? 32 : 0) + q * 8 + ((nw & 32) >> 3);
            *(uint4*)(Vout + (long)r0 * 512 + slot) = make_uint4(a0[0], a0[1], a0[2], a0[3]);
            *(uint4*)(Vout + (long)r1 * 512 + slot) = make_uint4(a1[0], a1[1], a1[2], a1[3]);
        } else {
#pragma unroll
            for (int nf = 0; nf < 4; nf++) {
                int nn = n0 + nw + nf * 8 + 2 * q;
                float2 v0, v1;
                v0.x = c[mf][nf][0] * sc0 + tt0;
                v0.y = c[mf][nf][1] * sc0 + tt0;
                v1.x = c[mf][nf][2] * sc1 + tt1;
                v1.y = c[mf][nf][3] * sc1 + tt1;
                *(float2*)(Yb + (long)r0 * NTOK + nn) = v0;
                *(float2*)(Yb + (long)r1 * NTOK + nn) = v1;
            }
        }
    }
}

__global__ __launch_bounds__(256, 2) void gemm_qkv_tc(
    const float* __restrict__ bnq, const float* __restrict__ bnk,
    const float* __restrict__ bnv)
{
    __shared__ uint32_t smu[GEMM_SMEM_U32];
    const int y = blockIdx.y, b = blockIdx.z;
    const uint32_t* XH = g_xh + (long)b * 192 * NTOK;
    const uint32_t* XL = g_xl + (long)b * 192 * NTOK;
    if (y < 2) {
        gemm16_body<false>(g_wqh, g_wql, XH, XL, bnq,
                           g_q + (long)b * NHKD * NTOK, nullptr,
                           NHKD, 192, y * 128, blockIdx.x * 128, smu);
    } else if (y < 4) {
        gemm16_body<false>(g_wkh, g_wkl, XH, XL, bnk,
                           g_k + (long)b * NHKD * NTOK, nullptr,
                           NHKD, 192, (y - 2) * 128, blockIdx.x * 128, smu);
    } else {
        gemm16_body<true>(g_wvh, g_wvl, XH, XL, bnv,
                          nullptr, g_vp + (long)b * 1024 * 512,
                          DHV, 192, (y - 4) * 128, blockIdx.x * 128, smu);
    }
}

__global__ __launch_bounds__(256, 2) void gemm_proj_tc(
    const float* __restrict__ bnp, float* __restrict__ out)
{
    __shared__ uint32_t smu[GEMM_SMEM_U32];
    const int b = blockIdx.z;
    gemm16_body<false>(g_wph, g_wpl,
                       g_xxh + (long)b * 512 * NTOK, g_xxl + (long)b * 512 * NTOK,
                       bnp, out + (long)b * DIM * NTOK, nullptr, DIM, 512,
                       blockIdx.y * 128, blockIdx.x * 128, smu);
}

// ---------------- FA2 attention, fp16 m16n8k16, 128-key iters, packed I/O ---
#define F2_KH 0
#define F2_KL 2176
#define F2_VH 4352
#define F2_P  14080
#define F2_MP 18944
#define F2_SP 19072
#define F2_MR 19200
#define F2_LR 19328
#define ATTN_SMEM_U32 19392   // 77568 B

__global__ __launch_bounds__(256, 2) void attn_fa()
{
    extern __shared__ float sm[];
    uint32_t* smu = (uint32_t*)sm;
    const int t = threadIdx.x, lane = t & 31, w = t >> 5;
    const int mi = w >> 1, ni = w & 1;
    const int g = lane >> 2, q = lane & 3;
    const int q0 = blockIdx.x * 64;
    const int b = blockIdx.y >> 3, h = blockIdx.y & 7;
    const float L2E = 1.44269504088896f;

    const uint32_t* qph = g_qph + ((long)b * 128 + h * 16) * NTOK + q0;
    const uint32_t* qpl = g_qpl + ((long)b * 128 + h * 16) * NTOK + q0;
    const uint32_t* kph = g_kph + ((long)b * 128 + h * 16) * NTOK;
    const uint32_t* kpl = g_kpl + ((long)b * 128 + h * 16) * NTOK;
    const uint32_t* vpk = g_vp + ((long)b * 1024 + h * 128) * 512;

    if (t < 64) { sm[F2_MR + t] = -1e30f; sm[F2_MR + 64 + t] = -1e30f; sm[F2_LR + t] = 0.f; }

    // Q fragments straight from packed gmem (pre-scaled by sqrt(32))
    const int r0 = mi * 16 + g;
    uint32_t qh[2][4], ql[2][4];
#pragma unroll
    for (int s = 0; s < 2; s++) {
        int p0 = 8 * s + q;
        qh[s][0] = qph[(long)p0 * NTOK + r0];
        qh[s][1] = qph[(long)p0 * NTOK + r0 + 8];
        qh[s][2] = qph[(long)(p0 + 4) * NTOK + r0];
        qh[s][3] = qph[(long)(p0 + 4) * NTOK + r0 + 8];
        ql[s][0] = qpl[(long)p0 * NTOK + r0];
        ql[s][1] = qpl[(long)p0 * NTOK + r0 + 8];
        ql[s][2] = qpl[(long)(p0 + 4) * NTOK + r0];
        ql[s][3] = qpl[(long)(p0 + 4) * NTOK + r0 + 8];
    }

    float o[8][4];
#pragma unroll
    for (int nf = 0; nf < 8; nf++)
#pragma unroll
        for (int j = 0; j < 4; j++) o[nf][j] = 0.f;

    const int kpair = t >> 4, ktok8 = (t & 15) * 8;   // K staging coords
    const int vd = t >> 1, hfv = t & 1;               // V staging coords

    for (int it = 0; it < 8; it++) {
        const int j0 = it * 128;
        __syncthreads();   // prev iter's K/V/P reads done (and MR/LR init at it=0)
        // ---- K stage: pure uint4 copies of packed hi/lo
        {
            const uint32_t* sh = kph + (long)kpair * NTOK + j0 + ktok8;
            const uint32_t* sl = kpl + (long)kpair * NTOK + j0 + ktok8;
            *(uint4*)(smu + F2_KH + kpair * 136 + ktok8)     = *(const uint4*)sh;
            *(uint4*)(smu + F2_KH + kpair * 136 + ktok8 + 4) = *(const uint4*)(sh + 4);
            *(uint4*)(smu + F2_KL + kpair * 136 + ktok8)     = *(const uint4*)sl;
            *(uint4*)(smu + F2_KL + kpair * 136 + ktok8 + 4) = *(const uint4*)(sl + 4);
        }
        // ---- V stage: pure uint4 copies (already permuted + packed)
        {
            const uint32_t* sv = vpk + (long)vd * 512 + it * 64 + hfv * 32;
            uint32_t* dv = smu + F2_VH + vd * 76 + hfv * 32;
#pragma unroll
            for (int r = 0; r < 8; r++)
                *(uint4*)(dv + r * 4) = *(const uint4*)(sv + r * 4);
        }
        __syncthreads();

        // ---- QK (2x-split fp16): S[16][64] per warp
        float s4[8][4];
#pragma unroll
        for (int nf = 0; nf < 8; nf++)
#pragma unroll
            for (int j = 0; j < 4; j++) s4[nf][j] = 0.f;
#pragma unroll
        for (int s = 0; s < 2; s++) {
#pragma unroll
            for (int nf = 0; nf < 8; nf++) {
                int col = ni * 64 + nf * 8 + g;
                uint32_t bh0 = smu[F2_KH + (8 * s + q) * 136 + col];
                uint32_t bh1 = smu[F2_KH + (8 * s + q + 4) * 136 + col];
                uint32_t bl0 = smu[F2_KL + (8 * s + q) * 136 + col];
                uint32_t bl1 = smu[F2_KL + (8 * s + q + 4) * 136 + col];
                mma16(s4[nf], qh[s], bh0, bh1);
                mma16(s4[nf], qh[s], bl0, bl1);
                mma16(s4[nf], ql[s], bh0, bh1);
            }
        }

        // ---- warp-local row max -> MP
        {
            float m0 = fmaxf(s4[0][0], s4[0][1]);
            float m1 = fmaxf(s4[0][2], s4[0][3]);
#pragma unroll
            for (int nf = 1; nf < 8; nf++) {
                m0 = fmaxf(m0, fmaxf(s4[nf][0], s4[nf][1]));
                m1 = fmaxf(m1, fmaxf(s4[nf][2], s4[nf][3]));
            }
            m0 = fmaxf(m0, __shfl_xor_sync(0xffffffffu, m0, 1));
            m0 = fmaxf(m0, __shfl_xor_sync(0xffffffffu, m0, 2));
            m1 = fmaxf(m1, __shfl_xor_sync(0xffffffffu, m1, 1));
            m1 = fmaxf(m1, __shfl_xor_sync(0xffffffffu, m1, 2));
            if (q == 0) {
                sm[F2_MP + ni * 64 + r0] = m0;
                sm[F2_MP + ni * 64 + r0 + 8] = m1;
            }
        }
        __syncthreads();

        // ---- new max, alpha, P (uint4 stores), partial sums, O rescale
        {
            float moA = sm[F2_MR + (it & 1) * 64 + r0];
            float moB = sm[F2_MR + (it & 1) * 64 + r0 + 8];
            float mn0 = fmaxf(moA, fmaxf(sm[F2_MP + r0], sm[F2_MP + 64 + r0]));
            float mn1 = fmaxf(moB, fmaxf(sm[F2_MP + r0 + 8], sm[F2_MP + 64 + r0 + 8]));
            if (ni == 0 && q == 0) {
                sm[F2_MR + ((it + 1) & 1) * 64 + r0] = mn0;
                sm[F2_MR + ((it + 1) & 1) * 64 + r0 + 8] = mn1;
            }
            float al0 = fexp2((moA - mn0) * L2E);
            float al1 = fexp2((moB - mn1) * L2E);
            float c0 = -mn0 * L2E, c1 = -mn1 * L2E;
            float rs0 = 0.f, rs1 = 0.f;
            uint32_t p0v[8], p1v[8];
#pragma unroll
            for (int nf = 0; nf < 8; nf++) {
                float e00 = fexp2(fmaf(s4[nf][0], L2E, c0));
                float e01 = fexp2(fmaf(s4[nf][1], L2E, c0));
                float e10 = fexp2(fmaf(s4[nf][2], L2E, c1));
                float e11 = fexp2(fmaf(s4[nf][3], L2E, c1));
                rs0 += e00 + e01; rs1 += e10 + e11;
                p0v[nf] = pack2(e00, e01);
                p1v[nf] = pack2(e10, e11);
            }
            {
                uint32_t base = F2_P + r0 * 76 + ni * 32 + q * 8;
                *(uint4*)(smu + base)     = make_uint4(p0v[0], p0v[1], p0v[2], p0v[3]);
                *(uint4*)(smu + base + 4) = make_uint4(p0v[4], p0v[5], p0v[6], p0v[7]);
                uint32_t base1 = F2_P + (r0 + 8) * 76 + ni * 32 + q * 8;
                *(uint4*)(smu + base1)     = make_uint4(p1v[0], p1v[1], p1v[2], p1v[3]);
                *(uint4*)(smu + base1 + 4) = make_uint4(p1v[4], p1v[5], p1v[6], p1v[7]);
            }
            rs0 += __shfl_xor_sync(0xffffffffu, rs0, 1);
            rs0 += __shfl_xor_sync(0xffffffffu, rs0, 2);
            rs1 += __shfl_xor_sync(0xffffffffu, rs1, 1);
            rs1 += __shfl_xor_sync(0xffffffffu, rs1, 2);
            if (q == 0) {
                sm[F2_SP + ni * 64 + r0] = rs0;
                sm[F2_SP + ni * 64 + r0 + 8] = rs1;
            }
#pragma unroll
            for (int nf = 0; nf < 8; nf++) {
                o[nf][0] *= al0; o[nf][1] *= al0;
                o[nf][2] *= al1; o[nf][3] *= al1;
            }
        }
        __syncthreads();

        // ---- l update (concurrent with AV)
        if (t < 64) {
            float mo = sm[F2_MR + (it & 1) * 64 + t];
            float mn = sm[F2_MR + ((it + 1) & 1) * 64 + t];
            sm[F2_LR + t] = sm[F2_LR + t] * fexp2((mo - mn) * L2E)
                          + sm[F2_SP + t] + sm[F2_SP + 64 + t];
        }

        // ---- AV fp16, 128 keys = 2 halves x 4 k-steps
#pragma unroll
        for (int hf = 0; hf < 2; hf++) {
            uint4 pa0 = *(const uint4*)(smu + F2_P + r0 * 76 + hf * 32 + q * 8);
            uint4 pa1 = *(const uint4*)(smu + F2_P + r0 * 76 + hf * 32 + q * 8 + 4);
            uint4 pb0 = *(const uint4*)(smu + F2_P + (r0 + 8) * 76 + hf * 32 + q * 8);
            uint4 pb1 = *(const uint4*)(smu + F2_P + (r0 + 8) * 76 + hf * 32 + q * 8 + 4);
            uint32_t pa[8] = {pa0.x, pa0.y, pa0.z, pa0.w, pa1.x, pa1.y, pa1.z, pa1.w};
            uint32_t pb[8] = {pb0.x, pb0.y, pb0.z, pb0.w, pb1.x, pb1.y, pb1.z, pb1.w};
            uint32_t as_[4][4];
#pragma unroll
            for (int s = 0; s < 4; s++) {
                as_[s][0] = pa[2 * s];     as_[s][1] = pb[2 * s];
                as_[s][2] = pa[2 * s + 1]; as_[s][3] = pb[2 * s + 1];
            }
#pragma unroll
            for (int nf = 0; nf < 8; nf++) {
                int d = ni * 64 + nf * 8 + g;
                uint4 v0 = *(const uint4*)(smu + F2_VH + d * 76 + hf * 32 + q * 8);
                uint4 v1 = *(const uint4*)(smu + F2_VH + d * 76 + hf * 32 + q * 8 + 4);
                uint32_t vv[8] = {v0.x, v0.y, v0.z, v0.w, v1.x, v1.y, v1.z, v1.w};
#pragma unroll
                for (int s = 0; s < 4; s++)
                    mma16(o[nf], as_[s], vv[2 * s], vv[2 * s + 1]);
            }
        }
    }

    // epilogue: normalize, write packed hi/lo [dpair][tok] directly
    __syncthreads();
    {
        float inv0 = 1.0f / sm[F2_LR + r0];
        float inv1 = 1.0f / sm[F2_LR + r0 + 8];
#pragma unroll
        for (int nf = 0; nf < 8; nf++) {
            int d = ni * 64 + nf * 8 + 2 * q;
            int dp = h * 64 + (d >> 1);
            long base = ((long)b * 512 + dp) * NTOK + q0;
            uint32_t h0, l0, h1, l1;
            splitpack(o[nf][0] * inv0, o[nf][1] * inv0, h0, l0);
            splitpack(o[nf][2] * inv1, o[nf][3] * inv1, h1, l1);
            g_xxh[base + r0]     = h0;
            g_xxl[base + r0]     = l0;
            g_xxh[base + r0 + 8] = h1;
            g_xxl[base + r0 + 8] = l1;
        }
    }
}

// ---------------------------------------------------------------------------
extern "C" void kernel_launch(void* const* d_in, const int* in_sizes, int n_in,
                              void* d_out, int out_size)
{
    const float* x   = (const float*)d_in[0];
    const float* wq  = (const float*)d_in[1];
    const float* bnq = (const float*)d_in[2];
    const float* wk  = (const float*)d_in[3];
    const float* bnk = (const float*)d_in[4];
    const float* wv  = (const float*)d_in[5];
    const float* bnv = (const float*)d_in[6];
    const float* wp  = (const float*)d_in[7];
    const float* bnp = (const float*)d_in[8];
    float* out = (float*)d_out;

    uint32_t *wqh, *wql, *wkh, *wkl, *wvh, *wvl, *wph, *wpl, *xh, *xl;
    uint32_t *qph, *qpl, *kph, *kpl;
    float *qs, *ks;
    cudaGetSymbolAddress((void**)&wqh, g_wqh);
    cudaGetSymbolAddress((void**)&wql, g_wql);
    cudaGetSymbolAddress((void**)&wkh, g_wkh);
    cudaGetSymbolAddress((void**)&wkl, g_wkl);
    cudaGetSymbolAddress((void**)&wvh, g_wvh);
    cudaGetSymbolAddress((void**)&wvl, g_wvl);
    cudaGetSymbolAddress((void**)&wph, g_wph);
    cudaGetSymbolAddress((void**)&wpl, g_wpl);
    cudaGetSymbolAddress((void**)&xh,  g_xh);
    cudaGetSymbolAddress((void**)&xl,  g_xl);
    cudaGetSymbolAddress((void**)&qph, g_qph);
    cudaGetSymbolAddress((void**)&qpl, g_qpl);
    cudaGetSymbolAddress((void**)&kph, g_kph);
    cudaGetSymbolAddress((void**)&kpl, g_kpl);
    cudaGetSymbolAddress((void**)&qs,  g_q);
    cudaGetSymbolAddress((void**)&ks,  g_k);

    const int smem_attn = ATTN_SMEM_U32 * 4;   // 77568 B
    cudaFuncSetAttribute(attn_fa, cudaFuncAttributeMaxDynamicSharedMemorySize,
                         smem_attn);
    dim3 blk(256);

    pack_w<<<192, blk>>>(wq, wqh, wql, NHKD, DIM);
    pack_w<<<192, blk>>>(wk, wkh, wkl, NHKD, DIM);
    pack_w<<<768, blk>>>(wv, wvh, wvl, DHV,  DIM);
    pack_w<<<768, blk>>>(wp, wph, wpl, DIM,  DHV);
    pack_x<<<dim3(768, BB), blk>>>(x, xh, xl, DIM);

    gemm_qkv_tc<<<dim3(8, 12, BB), blk>>>(bnq, bnk, bnv);

    // pack Q (scaled by sqrt(32)) and K into kpair half2 hi/lo
    pack_qk<<<dim3(512, BB), blk>>>(qs, qph, qpl, 5.656854249492380f);
    pack_qk<<<dim3(512, BB), blk>>>(ks, kph, kpl, 1.0f);

    attn_fa<<<dim3(NTOK / 64, BB * NH), blk, smem_attn>>>();
    gemm_proj_tc<<<dim3(8, 3, BB), blk>>>(bnp, out);
}

// round 14
// speedup vs baseline: 6.1080x; 1.0765x over previous
#include <cuda_runtime.h>
#include <cuda_fp16.h>
#include <cstdint>
#include <math.h>

#define BB   16
#define DIM  384
#define NHKD 256
#define DHV  1024
#define NTOK 1024
#define NH   8
#define KDIM 32
#define DV   128

// float intermediates (Q/K only)
__device__ float g_q [BB * NHKD * NTOK];
__device__ float g_k [BB * NHKD * NTOK];
// packed fp16 buffers
__device__ uint2 g_xh2 [BB * 96 * NTOK];    // x paired hi: [b][pair][tok]
__device__ uint2 g_xl2 [BB * 96 * NTOK];
__device__ uint2 g_xx2h[BB * 256 * NTOK];   // attn out paired hi
__device__ uint2 g_xx2l[BB * 256 * NTOK];
__device__ uint2 g_qp2h[BB * 64 * NTOK], g_qp2l[BB * 64 * NTOK];
__device__ uint2 g_kp2h[BB * 64 * NTOK], g_kp2l[BB * 64 * NTOK];
__device__ uint32_t g_vp [BB * 1024 * 512]; // V packed, permuted slots
// weights packed [m][kpair] (for ldmatrix A)
__device__ uint32_t g_wqh[256 * 192],  g_wql[256 * 192];
__device__ uint32_t g_wkh[256 * 192],  g_wkl[256 * 192];
__device__ uint32_t g_wvh[1024 * 192], g_wvl[1024 * 192];
__device__ uint32_t g_wph[384 * 512],  g_wpl[384 * 512];

__device__ __forceinline__ void mma16(float c[4], const uint32_t a[4],
                                      uint32_t b0, uint32_t b1) {
    asm volatile("mma.sync.aligned.m16n8k16.row.col.f32.f16.f16.f32 "
        "{%0,%1,%2,%3}, {%4,%5,%6,%7}, {%8,%9}, {%0,%1,%2,%3};"
        : "+f"(c[0]), "+f"(c[1]), "+f"(c[2]), "+f"(c[3])
        : "r"(a[0]), "r"(a[1]), "r"(a[2]), "r"(a[3]), "r"(b0), "r"(b1));
}
__device__ __forceinline__ void ldsm4(uint32_t r[4], const uint32_t* p) {
    uint32_t a = (uint32_t)__cvta_generic_to_shared(p);
    asm volatile("ldmatrix.sync.aligned.m8n8.x4.shared.b16 {%0,%1,%2,%3}, [%4];"
        : "=r"(r[0]), "=r"(r[1]), "=r"(r[2]), "=r"(r[3]) : "r"(a));
}
__device__ __forceinline__ uint32_t pack2(float x0, float x1) {
    __half2 h = __floats2half2_rn(x0, x1);
    return *(uint32_t*)&h;
}
__device__ __forceinline__ void splitpack(float x0, float x1,
                                          uint32_t& h, uint32_t& l) {
    __half2 hh = __floats2half2_rn(x0, x1);
    float2 bk = __half22float2(hh);
    __half2 ll = __floats2half2_rn(x0 - bk.x, x1 - bk.y);
    h = *(uint32_t*)&hh;
    l = *(uint32_t*)&ll;
}
__device__ __forceinline__ float fexp2(float z) {
    z = fmaxf(z, -100.0f);
    float zi = z + 12582912.0f;
    int   n  = __float_as_int(zi) - 0x4B400000;
    float t  = z - (zi - 12582912.0f);
    float p = fmaf(0.0013333558f, t, 0.0096181291f);
    p = fmaf(p, t, 0.0555041087f);
    p = fmaf(p, t, 0.2402265069f);
    p = fmaf(p, t, 0.6931471806f);
    p = fmaf(p, t, 1.0f);
    return __int_as_float(__float_as_int(p) + (n << 23));
}

// ---------------- prep kernels ----------------------------------------------
// W [M][K] -> H/L [m][kpair]
__global__ __launch_bounds__(256) void pack_w(
    const float* __restrict__ W, uint32_t* __restrict__ H,
    uint32_t* __restrict__ L, int M, int Kp)
{
    int idx = blockIdx.x * 256 + threadIdx.x;
    int m = idx / Kp, p = idx - m * Kp;
    float a = W[(long)m * (2 * Kp) + 2 * p];
    float b = W[(long)m * (2 * Kp) + 2 * p + 1];
    uint32_t hh, ll;
    splitpack(a, b, hh, ll);
    H[idx] = hh; L[idx] = ll;
}
// X float [b][384][1024] -> paired uint2 [b][96][1024]
__global__ __launch_bounds__(256) void pack_x(
    const float* __restrict__ X, uint2* __restrict__ H2,
    uint2* __restrict__ L2)
{
    int idx = blockIdx.x * 256 + threadIdx.x;
    int b = blockIdx.y;
    int gp = idx >> 10, n = idx & 1023;
    int c = gp >> 3, j = gp & 7, s = j >> 2, qq = j & 3;
    int k0 = 2 * (c * 16 + 8 * s + qq);
    const float* src = X + ((long)b * DIM + k0) * NTOK + n;
    uint32_t h0, l0, h1, l1;
    splitpack(src[0], src[NTOK], h0, l0);
    splitpack(src[8 * NTOK], src[9 * NTOK], h1, l1);
    long dst = ((long)b * 96 + gp) * NTOK + n;
    H2[dst] = make_uint2(h0, h1);
    L2[dst] = make_uint2(l0, l1);
}
// Q/K float [b][256][1024] -> paired uint2 [b][64][1024] (x scale)
__global__ __launch_bounds__(256) void pack_qk(
    const float* __restrict__ X, uint2* __restrict__ H2,
    uint2* __restrict__ L2, float scale)
{
    int idx = blockIdx.x * 256 + threadIdx.x;
    int b = blockIdx.y;
    int gp = idx >> 10, n = idx & 1023;
    int h = gp >> 3, j = gp & 7, s = j >> 2, qq = j & 3;
    int k0 = 2 * (h * 16 + 8 * s + qq);
    const float* src = X + ((long)b * 256 + k0) * NTOK + n;
    uint32_t h0, l0, h1, l1;
    splitpack(src[0] * scale, src[NTOK] * scale, h0, l0);
    splitpack(src[8 * NTOK] * scale, src[9 * NTOK] * scale, h1, l1);
    long dst = ((long)b * 64 + gp) * NTOK + n;
    H2[dst] = make_uint2(h0, h1);
    L2[dst] = make_uint2(l0, l1);
}

// ============ fp16 3x-split GEMM + BN (128x128), ldmatrix A, paired B ======
// smem: W hi [128][20] u32, W lo, B hi [8][132] uint2, B lo
#define SW_H 0
#define SW_L 2560
#define SB_H 5120
#define SB_L 7232
#define GEMM_SMEM_U32 9344

template <bool PACKV>
__device__ __forceinline__ void gemm16_body(
    const uint32_t* __restrict__ WH, const uint32_t* __restrict__ WL,
    const uint2* __restrict__ XH2, const uint2* __restrict__ XL2,
    const float* __restrict__ bn, float* __restrict__ Yb,
    uint32_t* __restrict__ Vout,
    int M, int Kp, int m0, int n0, uint32_t* smu)
{
    const int t = threadIdx.x, lane = t & 31, w = t >> 5;
    const int g = lane >> 2, q = lane & 3;
    const int mw = (w >> 2) * 64, nw = (w & 3) * 32;
    const int lrow = lane & 15, lsel = (lane >> 4) * 4;
    const int wrow = t >> 2, wquad = t & 3;        // W stager (x2)
    const int pr = t >> 5, cq = t & 31;            // B stager (x2)
    uint2* smBH = (uint2*)(smu + SB_H);
    uint2* smBL = (uint2*)(smu + SB_L);

    float c[4][4][4];
#pragma unroll
    for (int i = 0; i < 4; i++)
#pragma unroll
        for (int j = 0; j < 4; j++)
#pragma unroll
            for (int r = 0; r < 4; r++) c[i][j][r] = 0.f;

    const int nc = Kp >> 4;
    for (int ch = 0; ch < nc; ch++) {
        const int pc = ch * 16, pg = ch * 8;
        uint4 wh_[2], wl_[2], xh_[2], xl_[2];
#pragma unroll
        for (int i = 0; i < 2; i++) {
            int row = wrow + i * 64;
            wh_[i] = *(const uint4*)(WH + (long)(m0 + row) * Kp + pc + wquad * 4);
            wl_[i] = *(const uint4*)(WL + (long)(m0 + row) * Kp + pc + wquad * 4);
            int c2 = (cq + 32 * i) * 2;
            xh_[i] = *(const uint4*)(XH2 + (long)(pg + pr) * NTOK + n0 + c2);
            xl_[i] = *(const uint4*)(XL2 + (long)(pg + pr) * NTOK + n0 + c2);
        }
        __syncthreads();
#pragma unroll
        for (int i = 0; i < 2; i++) {
            int row = wrow + i * 64;
            *(uint4*)(smu + SW_H + row * 20 + wquad * 4) = wh_[i];
            *(uint4*)(smu + SW_L + row * 20 + wquad * 4) = wl_[i];
            int c2 = (cq + 32 * i) * 2;
            *(uint4*)(smBH + pr * 132 + c2) = xh_[i];
            *(uint4*)(smBL + pr * 132 + c2) = xl_[i];
        }
        __syncthreads();
#pragma unroll
        for (int ks = 0; ks < 2; ks++) {
            uint32_t ah[4][4], al[4][4];
#pragma unroll
            for (int mf = 0; mf < 4; mf++) {
                int ra = (mw + mf * 16 + lrow) * 20 + ks * 8 + lsel;
                ldsm4(ah[mf], smu + SW_H + ra);
                ldsm4(al[mf], smu + SW_L + ra);
            }
#pragma unroll
            for (int nf = 0; nf < 4; nf++) {
                int coln = nw + nf * 8 + g;
                uint2 bh = smBH[(4 * ks + q) * 132 + coln];
                uint2 bl = smBL[(4 * ks + q) * 132 + coln];
#pragma unroll
                for (int mf = 0; mf < 4; mf++) {
                    mma16(c[mf][nf], ah[mf], bh.x, bh.y);
                    mma16(c[mf][nf], ah[mf], bl.x, bl.y);
                    mma16(c[mf][nf], al[mf], bh.x, bh.y);
                }
            }
        }
    }

#pragma unroll
    for (int mf = 0; mf < 4; mf++) {
        int r0 = m0 + mw + mf * 16 + g;
        int r1 = r0 + 8;
        float sc0 = bn[r0] * rsqrtf(bn[3 * M + r0] + 1e-5f);
        float tt0 = bn[M + r0] - bn[2 * M + r0] * sc0;
        float sc1 = bn[r1] * rsqrtf(bn[3 * M + r1] + 1e-5f);
        float tt1 = bn[M + r1] - bn[2 * M + r1] * sc1;
        if (PACKV) {
            uint32_t a0[4], a1[4];
#pragma unroll
            for (int nf = 0; nf < 4; nf++) {
                a0[nf] = pack2(c[mf][nf][0] * sc0 + tt0, c[mf][nf][1] * sc0 + tt0);
                a1[nf] = pack2(c[mf][nf][2] * sc1 + tt1, c[mf][nf][3] * sc1 + tt1);
            }
            int slot = (n0 >> 1) + ((nw & 64) ? 32 : 0) + q * 8 + ((nw & 32) >> 3);
            *(uint4*)(Vout + (long)r0 * 512 + slot) = make_uint4(a0[0], a0[1], a0[2], a0[3]);
            *(uint4*)(Vout + (long)r1 * 512 + slot) = make_uint4(a1[0], a1[1], a1[2], a1[3]);
        } else {
#pragma unroll
            for (int nf = 0; nf < 4; nf++) {
                int nn = n0 + nw + nf * 8 + 2 * q;
                float2 v0, v1;
                v0.x = c[mf][nf][0] * sc0 + tt0;
                v0.y = c[mf][nf][1] * sc0 + tt0;
                v1.x = c[mf][nf][2] * sc1 + tt1;
                v1.y = c[mf][nf][3] * sc1 + tt1;
                *(float2*)(Yb + (long)r0 * NTOK + nn) = v0;
                *(float2*)(Yb + (long)r1 * NTOK + nn) = v1;
            }
        }
    }
}

__global__ __launch_bounds__(256, 2) void gemm_qkv_tc(
    const float* __restrict__ bnq, const float* __restrict__ bnk,
    const float* __restrict__ bnv)
{
    __shared__ uint32_t smu[GEMM_SMEM_U32];
    const int y = blockIdx.y, b = blockIdx.z;
    const uint2* XH = g_xh2 + (long)b * 96 * NTOK;
    const uint2* XL = g_xl2 + (long)b * 96 * NTOK;
    if (y < 2) {
        gemm16_body<false>(g_wqh, g_wql, XH, XL, bnq,
                           g_q + (long)b * NHKD * NTOK, nullptr,
                           NHKD, 192, y * 128, blockIdx.x * 128, smu);
    } else if (y < 4) {
        gemm16_body<false>(g_wkh, g_wkl, XH, XL, bnk,
                           g_k + (long)b * NHKD * NTOK, nullptr,
                           NHKD, 192, (y - 2) * 128, blockIdx.x * 128, smu);
    } else {
        gemm16_body<true>(g_wvh, g_wvl, XH, XL, bnv,
                          nullptr, g_vp + (long)b * 1024 * 512,
                          DHV, 192, (y - 4) * 128, blockIdx.x * 128, smu);
    }
}

__global__ __launch_bounds__(256, 2) void gemm_proj_tc(
    const float* __restrict__ bnp, float* __restrict__ out)
{
    __shared__ uint32_t smu[GEMM_SMEM_U32];
    const int b = blockIdx.z;
    gemm16_body<false>(g_wph, g_wpl,
                       g_xx2h + (long)b * 256 * NTOK, g_xx2l + (long)b * 256 * NTOK,
                       bnp, out + (long)b * DIM * NTOK, nullptr, DIM, 512,
                       blockIdx.y * 128, blockIdx.x * 128, smu);
}

// ---------------- FA2 attention, fp16 m16n8k16, paired K, packed I/O --------
#define A_KH 0        // uint2 [8][132] = 2112 u32
#define A_KL 2112
#define A_V  4224     // u32 [128][76] = 9728
#define A_P  13952    // u32 [64][76] = 4864
#define A_MP 18816
#define A_SP 18944
#define A_MR 19072
#define A_LR 19200
#define ATTN_SMEM_U32 19264   // 77056 B

__global__ __launch_bounds__(256, 2) void attn_fa()
{
    extern __shared__ float sm[];
    uint32_t* smu = (uint32_t*)sm;
    uint2* smKH = (uint2*)(smu + A_KH);
    uint2* smKL = (uint2*)(smu + A_KL);
    const int t = threadIdx.x, lane = t & 31, w = t >> 5;
    const int mi = w >> 1, ni = w & 1;
    const int g = lane >> 2, q = lane & 3;
    const int q0 = blockIdx.x * 64;
    const int b = blockIdx.y >> 3, h = blockIdx.y & 7;
    const float L2E = 1.44269504088896f;

    const uint2* qp2h = g_qp2h + ((long)b * 64 + h * 8) * NTOK + q0;
    const uint2* qp2l = g_qp2l + ((long)b * 64 + h * 8) * NTOK + q0;
    const uint2* kp2h = g_kp2h + ((long)b * 64 + h * 8) * NTOK;
    const uint2* kp2l = g_kp2l + ((long)b * 64 + h * 8) * NTOK;
    const uint32_t* vpk = g_vp + ((long)b * 1024 + h * 128) * 512;

    if (t < 64) { sm[A_MR + t] = -1e30f; sm[A_MR + 64 + t] = -1e30f; sm[A_LR + t] = 0.f; }

    // Q fragments from paired gmem (pre-scaled by sqrt(32))
    const int r0 = mi * 16 + g;
    uint32_t qh[2][4], ql[2][4];
#pragma unroll
    for (int s = 0; s < 2; s++) {
        long pi = (long)(4 * s + q) * NTOK;
        uint2 h0 = qp2h[pi + r0],  h1 = qp2h[pi + r0 + 8];
        uint2 l0 = qp2l[pi + r0],  l1 = qp2l[pi + r0 + 8];
        qh[s][0] = h0.x; qh[s][1] = h1.x; qh[s][2] = h0.y; qh[s][3] = h1.y;
        ql[s][0] = l0.x; ql[s][1] = l1.x; ql[s][2] = l0.y; ql[s][3] = l1.y;
    }

    float o[8][4];
#pragma unroll
    for (int nf = 0; nf < 8; nf++)
#pragma unroll
        for (int j = 0; j < 4; j++) o[nf][j] = 0.f;

    const int pr = t >> 5, cq = t & 31;   // K staging
    const int vd = t >> 1, hfv = t & 1;   // V staging

    for (int it = 0; it < 8; it++) {
        const int j0 = it * 128;
        __syncthreads();   // prev iter's K/V/P reads done
        // ---- K stage: pure uint4 copies of paired hi/lo
        {
            long srow = (long)pr * NTOK + j0;
#pragma unroll
            for (int i = 0; i < 2; i++) {
                int c2 = (cq + 32 * i) * 2;
                *(uint4*)(smKH + pr * 132 + c2) = *(const uint4*)(kp2h + srow + c2);
                *(uint4*)(smKL + pr * 132 + c2) = *(const uint4*)(kp2l + srow + c2);
            }
        }
        // ---- V stage: pure uint4 copies (permuted + packed upstream)
        {
            const uint32_t* sv = vpk + (long)vd * 512 + it * 64 + hfv * 32;
            uint32_t* dv = smu + A_V + vd * 76 + hfv * 32;
#pragma unroll
            for (int r = 0; r < 8; r++)
                *(uint4*)(dv + r * 4) = *(const uint4*)(sv + r * 4);
        }
        __syncthreads();

        // ---- QK (2x-split fp16): S[16][64] per warp, LDS.64 B frags
        float s4[8][4];
#pragma unroll
        for (int nf = 0; nf < 8; nf++)
#pragma unroll
            for (int j = 0; j < 4; j++) s4[nf][j] = 0.f;
#pragma unroll
        for (int s = 0; s < 2; s++) {
#pragma unroll
            for (int nf = 0; nf < 8; nf++) {
                int col = ni * 64 + nf * 8 + g;
                uint2 bh = smKH[(4 * s + q) * 132 + col];
                uint2 bl = smKL[(4 * s + q) * 132 + col];
                mma16(s4[nf], qh[s], bh.x, bh.y);
                mma16(s4[nf], qh[s], bl.x, bl.y);
                mma16(s4[nf], ql[s], bh.x, bh.y);
            }
        }

        // ---- warp-local row max -> MP
        {
            float m0 = fmaxf(s4[0][0], s4[0][1]);
            float m1 = fmaxf(s4[0][2], s4[0][3]);
#pragma unroll
            for (int nf = 1; nf < 8; nf++) {
                m0 = fmaxf(m0, fmaxf(s4[nf][0], s4[nf][1]));
                m1 = fmaxf(m1, fmaxf(s4[nf][2], s4[nf][3]));
            }
            m0 = fmaxf(m0, __shfl_xor_sync(0xffffffffu, m0, 1));
            m0 = fmaxf(m0, __shfl_xor_sync(0xffffffffu, m0, 2));
            m1 = fmaxf(m1, __shfl_xor_sync(0xffffffffu, m1, 1));
            m1 = fmaxf(m1, __shfl_xor_sync(0xffffffffu, m1, 2));
            if (q == 0) {
                sm[A_MP + ni * 64 + r0] = m0;
                sm[A_MP + ni * 64 + r0 + 8] = m1;
            }
        }
        __syncthreads();

        // ---- new max, alpha, P (uint4 stores), partial sums, O rescale
        {
            float moA = sm[A_MR + (it & 1) * 64 + r0];
            float moB = sm[A_MR + (it & 1) * 64 + r0 + 8];
            float mn0 = fmaxf(moA, fmaxf(sm[A_MP + r0], sm[A_MP + 64 + r0]));
            float mn1 = fmaxf(moB, fmaxf(sm[A_MP + r0 + 8], sm[A_MP + 64 + r0 + 8]));
            if (ni == 0 && q == 0) {
                sm[A_MR + ((it + 1) & 1) * 64 + r0] = mn0;
                sm[A_MR + ((it + 1) & 1) * 64 + r0 + 8] = mn1;
            }
            float al0 = fexp2((moA - mn0) * L2E);
            float al1 = fexp2((moB - mn1) * L2E);
            float c0 = -mn0 * L2E, c1 = -mn1 * L2E;
            float rs0 = 0.f, rs1 = 0.f;
            uint32_t p0v[8], p1v[8];
#pragma unroll
            for (int nf = 0; nf < 8; nf++) {
                float e00 = fexp2(fmaf(s4[nf][0], L2E, c0));
                float e01 = fexp2(fmaf(s4[nf][1], L2E, c0));
                float e10 = fexp2(fmaf(s4[nf][2], L2E, c1));
                float e11 = fexp2(fmaf(s4[nf][3], L2E, c1));
                rs0 += e00 + e01; rs1 += e10 + e11;
                p0v[nf] = pack2(e00, e01);
                p1v[nf] = pack2(e10, e11);
            }
            {
                uint32_t base = A_P + r0 * 76 + ni * 32 + q * 8;
                *(uint4*)(smu + base)     = make_uint4(p0v[0], p0v[1], p0v[2], p0v[3]);
                *(uint4*)(smu + base + 4) = make_uint4(p0v[4], p0v[5], p0v[6], p0v[7]);
                uint32_t base1 = A_P + (r0 + 8) * 76 + ni * 32 + q * 8;
                *(uint4*)(smu + base1)     = make_uint4(p1v[0], p1v[1], p1v[2], p1v[3]);
                *(uint4*)(smu + base1 + 4) = make_uint4(p1v[4], p1v[5], p1v[6], p1v[7]);
            }
            rs0 += __shfl_xor_sync(0xffffffffu, rs0, 1);
            rs0 += __shfl_xor_sync(0xffffffffu, rs0, 2);
            rs1 += __shfl_xor_sync(0xffffffffu, rs1, 1);
            rs1 += __shfl_xor_sync(0xffffffffu, rs1, 2);
            if (q == 0) {
                sm[A_SP + ni * 64 + r0] = rs0;
                sm[A_SP + ni * 64 + r0 + 8] = rs1;
            }
#pragma unroll
            for (int nf = 0; nf < 8; nf++) {
                o[nf][0] *= al0; o[nf][1] *= al0;
                o[nf][2] *= al1; o[nf][3] *= al1;
            }
        }
        __syncthreads();

        // ---- l update (concurrent with AV)
        if (t < 64) {
            float mo = sm[A_MR + (it & 1) * 64 + t];
            float mn = sm[A_MR + ((it + 1) & 1) * 64 + t];
            sm[A_LR + t] = sm[A_LR + t] * fexp2((mo - mn) * L2E)
                         + sm[A_SP + t] + sm[A_SP + 64 + t];
        }

        // ---- AV fp16, 128 keys = 2 halves x 4 k-steps (all LDS.128)
#pragma unroll
        for (int hf = 0; hf < 2; hf++) {
            uint4 pa0 = *(const uint4*)(smu + A_P + r0 * 76 + hf * 32 + q * 8);
            uint4 pa1 = *(const uint4*)(smu + A_P + r0 * 76 + hf * 32 + q * 8 + 4);
            uint4 pb0 = *(const uint4*)(smu + A_P + (r0 + 8) * 76 + hf * 32 + q * 8);
            uint4 pb1 = *(const uint4*)(smu + A_P + (r0 + 8) * 76 + hf * 32 + q * 8 + 4);
            uint32_t pa[8] = {pa0.x, pa0.y, pa0.z, pa0.w, pa1.x, pa1.y, pa1.z, pa1.w};
            uint32_t pb[8] = {pb0.x, pb0.y, pb0.z, pb0.w, pb1.x, pb1.y, pb1.z, pb1.w};
            uint32_t as_[4][4];
#pragma unroll
            for (int s = 0; s < 4; s++) {
                as_[s][0] = pa[2 * s];     as_[s][1] = pb[2 * s];
                as_[s][2] = pa[2 * s + 1]; as_[s][3] = pb[2 * s + 1];
            }
#pragma unroll
            for (int nf = 0; nf < 8; nf++) {
                int d = ni * 64 + nf * 8 + g;
                uint4 v0 = *(const uint4*)(smu + A_V + d * 76 + hf * 32 + q * 8);
                uint4 v1 = *(const uint4*)(smu + A_V + d * 76 + hf * 32 + q * 8 + 4);
                uint32_t vv[8] = {v0.x, v0.y, v0.z, v0.w, v1.x, v1.y, v1.z, v1.w};
#pragma unroll
                for (int s = 0; s < 4; s++)
                    mma16(o[nf], as_[s], vv[2 * s], vv[2 * s + 1]);
            }
        }
    }

    // epilogue: normalize, write paired hi/lo [pair][tok]
    __syncthreads();
    {
        float inv0 = 1.0f / sm[A_LR + r0];
        float inv1 = 1.0f / sm[A_LR + r0 + 8];
#pragma unroll
        for (int nf = 0; nf < 8; nf += 2) {
            // dpair dp = h*64 + ni*32 + nf*4 + q ; partner = dp+4 (nf+1)
            int gpair = (h * 4 + ni * 2 + (nf >> 2)) * 8 + 4 * ((nf >> 1) & 1) + q;
            long base = ((long)b * 256 + gpair) * NTOK + q0;
            uint32_t hA0, lA0, hB0, lB0;   // nf, tokens r0 / r0+8
            uint32_t hA1, lA1, hB1, lB1;   // nf+1
            splitpack(o[nf][0] * inv0,     o[nf][1] * inv0,     hA0, lA0);
            splitpack(o[nf][2] * inv1,     o[nf][3] * inv1,     hB0, lB0);
            splitpack(o[nf + 1][0] * inv0, o[nf + 1][1] * inv0, hA1, lA1);
            splitpack(o[nf + 1][2] * inv1, o[nf + 1][3] * inv1, hB1, lB1);
            g_xx2h[base + r0]     = make_uint2(hA0, hA1);
            g_xx2l[base + r0]     = make_uint2(lA0, lA1);
            g_xx2h[base + r0 + 8] = make_uint2(hB0, hB1);
            g_xx2l[base + r0 + 8] = make_uint2(lB0, lB1);
        }
    }
}

// ---------------------------------------------------------------------------
extern "C" void kernel_launch(void* const* d_in, const int* in_sizes, int n_in,
                              void* d_out, int out_size)
{
    const float* x   = (const float*)d_in[0];
    const float* wq  = (const float*)d_in[1];
    const float* bnq = (const float*)d_in[2];
    const float* wk  = (const float*)d_in[3];
    const float* bnk = (const float*)d_in[4];
    const float* wv  = (const float*)d_in[5];
    const float* bnv = (const float*)d_in[6];
    const float* wp  = (const float*)d_in[7];
    const float* bnp = (const float*)d_in[8];
    float* out = (float*)d_out;

    uint32_t *wqh, *wql, *wkh, *wkl, *wvh, *wvl, *wph, *wpl;
    uint2 *xh2, *xl2, *qp2h, *qp2l, *kp2h, *kp2l;
    float *qs, *ks;
    cudaGetSymbolAddress((void**)&wqh, g_wqh);
    cudaGetSymbolAddress((void**)&wql, g_wql);
    cudaGetSymbolAddress((void**)&wkh, g_wkh);
    cudaGetSymbolAddress((void**)&wkl, g_wkl);
    cudaGetSymbolAddress((void**)&wvh, g_wvh);
    cudaGetSymbolAddress((void**)&wvl, g_wvl);
    cudaGetSymbolAddress((void**)&wph, g_wph);
    cudaGetSymbolAddress((void**)&wpl, g_wpl);
    cudaGetSymbolAddress((void**)&xh2, g_xh2);
    cudaGetSymbolAddress((void**)&xl2, g_xl2);
    cudaGetSymbolAddress((void**)&qp2h, g_qp2h);
    cudaGetSymbolAddress((void**)&qp2l, g_qp2l);
    cudaGetSymbolAddress((void**)&kp2h, g_kp2h);
    cudaGetSymbolAddress((void**)&kp2l, g_kp2l);
    cudaGetSymbolAddress((void**)&qs, g_q);
    cudaGetSymbolAddress((void**)&ks, g_k);

    const int smem_attn = ATTN_SMEM_U32 * 4;   // 77056 B
    cudaFuncSetAttribute(attn_fa, cudaFuncAttributeMaxDynamicSharedMemorySize,
                         smem_attn);
    dim3 blk(256);

    pack_w<<<192, blk>>>(wq, wqh, wql, NHKD, 192);
    pack_w<<<192, blk>>>(wk, wkh, wkl, NHKD, 192);
    pack_w<<<768, blk>>>(wv, wvh, wvl, DHV,  192);
    pack_w<<<768, blk>>>(wp, wph, wpl, DIM,  512);
    pack_x<<<dim3(384, BB), blk>>>(x, xh2, xl2);

    gemm_qkv_tc<<<dim3(8, 12, BB), blk>>>(bnq, bnk, bnv);

    pack_qk<<<dim3(256, BB), blk>>>(qs, qp2h, qp2l, 5.656854249492380f);
    pack_qk<<<dim3(256, BB), blk>>>(ks, kp2h, kp2l, 1.0f);

    attn_fa<<<dim3(NTOK / 64, BB * NH), blk, smem_attn>>>();
    gemm_proj_tc<<<dim3(8, 3, BB), blk>>>(bnp, out);
}

// round 15
// speedup vs baseline: 7.2205x; 1.1821x over previous
#include <cuda_runtime.h>
#include <cuda_fp16.h>
#include <cstdint>
#include <math.h>

#define BB   16
#define DIM  384
#define NHKD 256
#define DHV  1024
#define NTOK 1024
#define NH   8
#define KDIM 32
#define DV   128

// float intermediates (Q/K only)
__device__ float g_q [BB * NHKD * NTOK];
__device__ float g_k [BB * NHKD * NTOK];
// packed fp16 buffers
__device__ uint2 g_xh2 [BB * 96 * NTOK];
__device__ uint2 g_xl2 [BB * 96 * NTOK];
__device__ uint2 g_xx2h[BB * 256 * NTOK];
__device__ uint2 g_xx2l[BB * 256 * NTOK];
__device__ uint2 g_qp2h[BB * 64 * NTOK], g_qp2l[BB * 64 * NTOK];
__device__ uint2 g_kp2h[BB * 64 * NTOK], g_kp2l[BB * 64 * NTOK];
__device__ uint32_t g_vp [BB * 1024 * 512];
// weights packed [m][kpair]
__device__ uint32_t g_wqh[256 * 192],  g_wql[256 * 192];
__device__ uint32_t g_wkh[256 * 192],  g_wkl[256 * 192];
__device__ uint32_t g_wvh[1024 * 192], g_wvl[1024 * 192];
__device__ uint32_t g_wph[384 * 512],  g_wpl[384 * 512];

__device__ __forceinline__ void mma16(float c[4], const uint32_t a[4],
                                      uint32_t b0, uint32_t b1) {
    asm volatile("mma.sync.aligned.m16n8k16.row.col.f32.f16.f16.f32 "
        "{%0,%1,%2,%3}, {%4,%5,%6,%7}, {%8,%9}, {%0,%1,%2,%3};"
        : "+f"(c[0]), "+f"(c[1]), "+f"(c[2]), "+f"(c[3])
        : "r"(a[0]), "r"(a[1]), "r"(a[2]), "r"(a[3]), "r"(b0), "r"(b1));
}
__device__ __forceinline__ void ldsm4(uint32_t r[4], const uint32_t* p) {
    uint32_t a = (uint32_t)__cvta_generic_to_shared(p);
    asm volatile("ldmatrix.sync.aligned.m8n8.x4.shared.b16 {%0,%1,%2,%3}, [%4];"
        : "=r"(r[0]), "=r"(r[1]), "=r"(r[2]), "=r"(r[3]) : "r"(a));
}
__device__ __forceinline__ void cpa16(void* dst, const void* src) {
    uint32_t a = (uint32_t)__cvta_generic_to_shared(dst);
    asm volatile("cp.async.cg.shared.global [%0], [%1], 16;" :: "r"(a), "l"(src));
}
#define CP_COMMIT() asm volatile("cp.async.commit_group;" ::: "memory")
#define CP_WAIT(n)  asm volatile("cp.async.wait_group %0;" :: "n"(n) : "memory")

__device__ __forceinline__ uint32_t pack2(float x0, float x1) {
    __half2 h = __floats2half2_rn(x0, x1);
    return *(uint32_t*)&h;
}
__device__ __forceinline__ void splitpack(float x0, float x1,
                                          uint32_t& h, uint32_t& l) {
    __half2 hh = __floats2half2_rn(x0, x1);
    float2 bk = __half22float2(hh);
    __half2 ll = __floats2half2_rn(x0 - bk.x, x1 - bk.y);
    h = *(uint32_t*)&hh;
    l = *(uint32_t*)&ll;
}
__device__ __forceinline__ float fexp2(float z) {
    z = fmaxf(z, -100.0f);
    float zi = z + 12582912.0f;
    int   n  = __float_as_int(zi) - 0x4B400000;
    float t  = z - (zi - 12582912.0f);
    float p = fmaf(0.0013333558f, t, 0.0096181291f);
    p = fmaf(p, t, 0.0555041087f);
    p = fmaf(p, t, 0.2402265069f);
    p = fmaf(p, t, 0.6931471806f);
    p = fmaf(p, t, 1.0f);
    return __int_as_float(__float_as_int(p) + (n << 23));
}

// ---------------- prep kernels ----------------------------------------------
__global__ __launch_bounds__(256) void pack_w(
    const float* __restrict__ W, uint32_t* __restrict__ H,
    uint32_t* __restrict__ L, int M, int Kp)
{
    int idx = blockIdx.x * 256 + threadIdx.x;
    int m = idx / Kp, p = idx - m * Kp;
    float a = W[(long)m * (2 * Kp) + 2 * p];
    float b = W[(long)m * (2 * Kp) + 2 * p + 1];
    uint32_t hh, ll;
    splitpack(a, b, hh, ll);
    H[idx] = hh; L[idx] = ll;
}
__global__ __launch_bounds__(256) void pack_x(
    const float* __restrict__ X, uint2* __restrict__ H2,
    uint2* __restrict__ L2)
{
    int idx = blockIdx.x * 256 + threadIdx.x;
    int b = blockIdx.y;
    int gp = idx >> 10, n = idx & 1023;
    int c = gp >> 3, j = gp & 7, s = j >> 2, qq = j & 3;
    int k0 = 2 * (c * 16 + 8 * s + qq);
    const float* src = X + ((long)b * DIM + k0) * NTOK + n;
    uint32_t h0, l0, h1, l1;
    splitpack(src[0], src[NTOK], h0, l0);
    splitpack(src[8 * NTOK], src[9 * NTOK], h1, l1);
    long dst = ((long)b * 96 + gp) * NTOK + n;
    H2[dst] = make_uint2(h0, h1);
    L2[dst] = make_uint2(l0, l1);
}
__global__ __launch_bounds__(256) void pack_qk(
    const float* __restrict__ X, uint2* __restrict__ H2,
    uint2* __restrict__ L2, float scale)
{
    int idx = blockIdx.x * 256 + threadIdx.x;
    int b = blockIdx.y;
    int gp = idx >> 10, n = idx & 1023;
    int h = gp >> 3, j = gp & 7, s = j >> 2, qq = j & 3;
    int k0 = 2 * (h * 16 + 8 * s + qq);
    const float* src = X + ((long)b * 256 + k0) * NTOK + n;
    uint32_t h0, l0, h1, l1;
    splitpack(src[0] * scale, src[NTOK] * scale, h0, l0);
    splitpack(src[8 * NTOK] * scale, src[9 * NTOK] * scale, h1, l1);
    long dst = ((long)b * 64 + gp) * NTOK + n;
    H2[dst] = make_uint2(h0, h1);
    L2[dst] = make_uint2(l0, l1);
}

// ============ fp16 3x-split GEMM + BN, cp.async 2-stage double buffer =======
#define SW_H 0
#define SW_L 2560
#define SB_H 5120
#define SB_L 7232
#define GEMM_BUF_U32 9344
#define GEMM_SMEM_BYTES (2 * GEMM_BUF_U32 * 4)

template <bool PACKV>
__device__ __forceinline__ void gemm16_body(
    const uint32_t* __restrict__ WH, const uint32_t* __restrict__ WL,
    const uint2* __restrict__ XH2, const uint2* __restrict__ XL2,
    const float* __restrict__ bn, float* __restrict__ Yb,
    uint32_t* __restrict__ Vout,
    int M, int Kp, int m0, int n0, uint32_t* smu)
{
    const int t = threadIdx.x, lane = t & 31, w = t >> 5;
    const int g = lane >> 2, q = lane & 3;
    const int mw = (w >> 2) * 64, nw = (w & 3) * 32;
    const int lrow = lane & 15, lsel = (lane >> 4) * 4;
    const int wrow = t >> 2, wquad = t & 3;
    const int pr = t >> 5, cq = t & 31;

    float c[4][4][4];
#pragma unroll
    for (int i = 0; i < 4; i++)
#pragma unroll
        for (int j = 0; j < 4; j++)
#pragma unroll
            for (int r = 0; r < 4; r++) c[i][j][r] = 0.f;

    const int nc = Kp >> 4;
    // prologue: stage chunk 0 into buffer 0
    {
        uint32_t* base = smu;
#pragma unroll
        for (int i = 0; i < 2; i++) {
            int row = wrow + i * 64;
            cpa16(base + SW_H + row * 20 + wquad * 4,
                  WH + (long)(m0 + row) * Kp + wquad * 4);
            cpa16(base + SW_L + row * 20 + wquad * 4,
                  WL + (long)(m0 + row) * Kp + wquad * 4);
            int c2 = (cq + 32 * i) * 2;
            cpa16(base + SB_H + (pr * 132 + c2) * 2,
                  XH2 + (long)pr * NTOK + n0 + c2);
            cpa16(base + SB_L + (pr * 132 + c2) * 2,
                  XL2 + (long)pr * NTOK + n0 + c2);
        }
        CP_COMMIT();
    }

    for (int ch = 0; ch < nc; ch++) {
        if (ch + 1 < nc) {
            uint32_t* base = smu + ((ch + 1) & 1) * GEMM_BUF_U32;
            const int pc = (ch + 1) * 16, pg = (ch + 1) * 8;
#pragma unroll
            for (int i = 0; i < 2; i++) {
                int row = wrow + i * 64;
                cpa16(base + SW_H + row * 20 + wquad * 4,
                      WH + (long)(m0 + row) * Kp + pc + wquad * 4);
                cpa16(base + SW_L + row * 20 + wquad * 4,
                      WL + (long)(m0 + row) * Kp + pc + wquad * 4);
                int c2 = (cq + 32 * i) * 2;
                cpa16(base + SB_H + (pr * 132 + c2) * 2,
                      XH2 + (long)(pg + pr) * NTOK + n0 + c2);
                cpa16(base + SB_L + (pr * 132 + c2) * 2,
                      XL2 + (long)(pg + pr) * NTOK + n0 + c2);
            }
            CP_COMMIT();
            CP_WAIT(1);
        } else {
            CP_WAIT(0);
        }
        __syncthreads();

        uint32_t* base = smu + (ch & 1) * GEMM_BUF_U32;
        uint2* smBH = (uint2*)(base + SB_H);
        uint2* smBL = (uint2*)(base + SB_L);
#pragma unroll
        for (int ks = 0; ks < 2; ks++) {
            uint32_t ah[4][4], al[4][4];
#pragma unroll
            for (int mf = 0; mf < 4; mf++) {
                int ra = (mw + mf * 16 + lrow) * 20 + ks * 8 + lsel;
                ldsm4(ah[mf], base + SW_H + ra);
                ldsm4(al[mf], base + SW_L + ra);
            }
#pragma unroll
            for (int nf = 0; nf < 4; nf++) {
                int coln = nw + nf * 8 + g;
                uint2 bh = smBH[(4 * ks + q) * 132 + coln];
                uint2 bl = smBL[(4 * ks + q) * 132 + coln];
#pragma unroll
                for (int mf = 0; mf < 4; mf++) {
                    mma16(c[mf][nf], ah[mf], bh.x, bh.y);
                    mma16(c[mf][nf], ah[mf], bl.x, bl.y);
                    mma16(c[mf][nf], al[mf], bh.x, bh.y);
                }
            }
        }
        __syncthreads();   // reads done before this buffer is re-staged
    }

#pragma unroll
    for (int mf = 0; mf < 4; mf++) {
        int r0 = m0 + mw + mf * 16 + g;
        int r1 = r0 + 8;
        float sc0 = bn[r0] * rsqrtf(bn[3 * M + r0] + 1e-5f);
        float tt0 = bn[M + r0] - bn[2 * M + r0] * sc0;
        float sc1 = bn[r1] * rsqrtf(bn[3 * M + r1] + 1e-5f);
        float tt1 = bn[M + r1] - bn[2 * M + r1] * sc1;
        if (PACKV) {
            uint32_t a0[4], a1[4];
#pragma unroll
            for (int nf = 0; nf < 4; nf++) {
                a0[nf] = pack2(c[mf][nf][0] * sc0 + tt0, c[mf][nf][1] * sc0 + tt0);
                a1[nf] = pack2(c[mf][nf][2] * sc1 + tt1, c[mf][nf][3] * sc1 + tt1);
            }
            int slot = (n0 >> 1) + ((nw & 64) ? 32 : 0) + q * 8 + ((nw & 32) >> 3);
            *(uint4*)(Vout + (long)r0 * 512 + slot) = make_uint4(a0[0], a0[1], a0[2], a0[3]);
            *(uint4*)(Vout + (long)r1 * 512 + slot) = make_uint4(a1[0], a1[1], a1[2], a1[3]);
        } else {
#pragma unroll
            for (int nf = 0; nf < 4; nf++) {
                int nn = n0 + nw + nf * 8 + 2 * q;
                float2 v0, v1;
                v0.x = c[mf][nf][0] * sc0 + tt0;
                v0.y = c[mf][nf][1] * sc0 + tt0;
                v1.x = c[mf][nf][2] * sc1 + tt1;
                v1.y = c[mf][nf][3] * sc1 + tt1;
                *(float2*)(Yb + (long)r0 * NTOK + nn) = v0;
                *(float2*)(Yb + (long)r1 * NTOK + nn) = v1;
            }
        }
    }
}

__global__ __launch_bounds__(256, 2) void gemm_qkv_tc(
    const float* __restrict__ bnq, const float* __restrict__ bnk,
    const float* __restrict__ bnv)
{
    extern __shared__ uint32_t smu[];
    const int y = blockIdx.y, b = blockIdx.z;
    const uint2* XH = g_xh2 + (long)b * 96 * NTOK;
    const uint2* XL = g_xl2 + (long)b * 96 * NTOK;
    if (y < 2) {
        gemm16_body<false>(g_wqh, g_wql, XH, XL, bnq,
                           g_q + (long)b * NHKD * NTOK, nullptr,
                           NHKD, 192, y * 128, blockIdx.x * 128, smu);
    } else if (y < 4) {
        gemm16_body<false>(g_wkh, g_wkl, XH, XL, bnk,
                           g_k + (long)b * NHKD * NTOK, nullptr,
                           NHKD, 192, (y - 2) * 128, blockIdx.x * 128, smu);
    } else {
        gemm16_body<true>(g_wvh, g_wvl, XH, XL, bnv,
                          nullptr, g_vp + (long)b * 1024 * 512,
                          DHV, 192, (y - 4) * 128, blockIdx.x * 128, smu);
    }
}

__global__ __launch_bounds__(256, 2) void gemm_proj_tc(
    const float* __restrict__ bnp, float* __restrict__ out)
{
    extern __shared__ uint32_t smu[];
    const int b = blockIdx.z;
    gemm16_body<false>(g_wph, g_wpl,
                       g_xx2h + (long)b * 256 * NTOK, g_xx2l + (long)b * 256 * NTOK,
                       bnp, out + (long)b * DIM * NTOK, nullptr, DIM, 512,
                       blockIdx.y * 128, blockIdx.x * 128, smu);
}

// ---------------- FA2 attention, cp.async rotating prefetch -----------------
// V split into token halves V0/V1 [128][36]; K single buffer (prefetch slot
// opens after the row-max sync). Schedule per iter:
//   top: CP_WAIT(0) [K(it),V0(it)]; sync
//   QK; MP-sync; issue K(it+1)+V1(it), commit
//   softmax/P; sync; AV-h0 + l-update
//   CP_WAIT(0); sync; issue V0(it+1), commit; AV-h1
#define A_KH 0        // uint2 [8][132]
#define A_KL 2112
#define A_V0 4224     // u32 [128][36]
#define A_V1 8832
#define A_P  13440    // u32 [64][76]
#define A_MP 18304
#define A_SP 18432
#define A_MR 18560
#define A_LR 18688
#define ATTN_SMEM_U32 18752   // 75008 B

__global__ __launch_bounds__(256, 2) void attn_fa()
{
    extern __shared__ float sm[];
    uint32_t* smu = (uint32_t*)sm;
    uint2* smKH = (uint2*)(smu + A_KH);
    uint2* smKL = (uint2*)(smu + A_KL);
    const int t = threadIdx.x, lane = t & 31, w = t >> 5;
    const int mi = w >> 1, ni = w & 1;
    const int g = lane >> 2, q = lane & 3;
    const int q0 = blockIdx.x * 64;
    const int b = blockIdx.y >> 3, h = blockIdx.y & 7;
    const float L2E = 1.44269504088896f;

    const uint2* qp2h = g_qp2h + ((long)b * 64 + h * 8) * NTOK + q0;
    const uint2* qp2l = g_qp2l + ((long)b * 64 + h * 8) * NTOK + q0;
    const uint2* kp2h = g_kp2h + ((long)b * 64 + h * 8) * NTOK;
    const uint2* kp2l = g_kp2l + ((long)b * 64 + h * 8) * NTOK;
    const uint32_t* vpk = g_vp + ((long)b * 1024 + h * 128) * 512;

    const int pr = t >> 5, cq = t & 31;   // K staging
    const int vd = t >> 1, hv = t & 1;    // V staging

    if (t < 64) { sm[A_MR + t] = -1e30f; sm[A_MR + 64 + t] = -1e30f; sm[A_LR + t] = 0.f; }

    // prologue: stage K(0) + V0(0)
    {
        long srow = (long)pr * NTOK;
#pragma unroll
        for (int i = 0; i < 2; i++) {
            int c2 = (cq + 32 * i) * 2;
            cpa16(smu + A_KH + (pr * 132 + c2) * 2, kp2h + srow + c2);
            cpa16(smu + A_KL + (pr * 132 + c2) * 2, kp2l + srow + c2);
        }
        const uint32_t* sv = vpk + (long)vd * 512 + hv * 16;
#pragma unroll
        for (int r = 0; r < 4; r++)
            cpa16(smu + A_V0 + vd * 36 + hv * 16 + r * 4, sv + r * 4);
        CP_COMMIT();
    }

    // Q fragments from paired gmem (pre-scaled by sqrt(32))
    const int r0 = mi * 16 + g;
    uint32_t qh[2][4], ql[2][4];
#pragma unroll
    for (int s = 0; s < 2; s++) {
        long pi = (long)(4 * s + q) * NTOK;
        uint2 h0 = qp2h[pi + r0],  h1 = qp2h[pi + r0 + 8];
        uint2 l0 = qp2l[pi + r0],  l1 = qp2l[pi + r0 + 8];
        qh[s][0] = h0.x; qh[s][1] = h1.x; qh[s][2] = h0.y; qh[s][3] = h1.y;
        ql[s][0] = l0.x; ql[s][1] = l1.x; ql[s][2] = l0.y; ql[s][3] = l1.y;
    }

    float o[8][4];
#pragma unroll
    for (int nf = 0; nf < 8; nf++)
#pragma unroll
        for (int j = 0; j < 4; j++) o[nf][j] = 0.f;

    for (int it = 0; it < 8; it++) {
        CP_WAIT(0);          // K(it), V0(it) landed (V1(it) waited later too)
        __syncthreads();     // visible to all; prev AV-h1 reads done

        // ---- QK (2x-split fp16): S[16][64] per warp
        float s4[8][4];
#pragma unroll
        for (int nf = 0; nf < 8; nf++)
#pragma unroll
            for (int j = 0; j < 4; j++) s4[nf][j] = 0.f;
#pragma unroll
        for (int s = 0; s < 2; s++) {
#pragma unroll
            for (int nf = 0; nf < 8; nf++) {
                int col = ni * 64 + nf * 8 + g;
                uint2 bh = smKH[(4 * s + q) * 132 + col];
                uint2 bl = smKL[(4 * s + q) * 132 + col];
                mma16(s4[nf], qh[s], bh.x, bh.y);
                mma16(s4[nf], qh[s], bl.x, bl.y);
                mma16(s4[nf], ql[s], bh.x, bh.y);
            }
        }

        // ---- warp-local row max -> MP
        {
            float m0 = fmaxf(s4[0][0], s4[0][1]);
            float m1 = fmaxf(s4[0][2], s4[0][3]);
#pragma unroll
            for (int nf = 1; nf < 8; nf++) {
                m0 = fmaxf(m0, fmaxf(s4[nf][0], s4[nf][1]));
                m1 = fmaxf(m1, fmaxf(s4[nf][2], s4[nf][3]));
            }
            m0 = fmaxf(m0, __shfl_xor_sync(0xffffffffu, m0, 1));
            m0 = fmaxf(m0, __shfl_xor_sync(0xffffffffu, m0, 2));
            m1 = fmaxf(m1, __shfl_xor_sync(0xffffffffu, m1, 1));
            m1 = fmaxf(m1, __shfl_xor_sync(0xffffffffu, m1, 2));
            if (q == 0) {
                sm[A_MP + ni * 64 + r0] = m0;
                sm[A_MP + ni * 64 + r0 + 8] = m1;
            }
        }
        __syncthreads();     // MP visible; all QK reads of K done

        // ---- prefetch K(it+1) + V1(it)
        {
            if (it < 7) {
                long srow = (long)pr * NTOK + (it + 1) * 128;
#pragma unroll
                for (int i = 0; i < 2; i++) {
                    int c2 = (cq + 32 * i) * 2;
                    cpa16(smu + A_KH + (pr * 132 + c2) * 2, kp2h + srow + c2);
                    cpa16(smu + A_KL + (pr * 132 + c2) * 2, kp2l + srow + c2);
                }
            }
            const uint32_t* sv = vpk + (long)vd * 512 + it * 64 + 32 + hv * 16;
#pragma unroll
            for (int r = 0; r < 4; r++)
                cpa16(smu + A_V1 + vd * 36 + hv * 16 + r * 4, sv + r * 4);
            CP_COMMIT();
        }

        // ---- new max, alpha, P (uint4 stores), partial sums, O rescale
        {
            float moA = sm[A_MR + (it & 1) * 64 + r0];
            float moB = sm[A_MR + (it & 1) * 64 + r0 + 8];
            float mn0 = fmaxf(moA, fmaxf(sm[A_MP + r0], sm[A_MP + 64 + r0]));
            float mn1 = fmaxf(moB, fmaxf(sm[A_MP + r0 + 8], sm[A_MP + 64 + r0 + 8]));
            if (ni == 0 && q == 0) {
                sm[A_MR + ((it + 1) & 1) * 64 + r0] = mn0;
                sm[A_MR + ((it + 1) & 1) * 64 + r0 + 8] = mn1;
            }
            float al0 = fexp2((moA - mn0) * L2E);
            float al1 = fexp2((moB - mn1) * L2E);
            float c0 = -mn0 * L2E, c1 = -mn1 * L2E;
            float rs0 = 0.f, rs1 = 0.f;
            uint32_t p0v[8], p1v[8];
#pragma unroll
            for (int nf = 0; nf < 8; nf++) {
                float e00 = fexp2(fmaf(s4[nf][0], L2E, c0));
                float e01 = fexp2(fmaf(s4[nf][1], L2E, c0));
                float e10 = fexp2(fmaf(s4[nf][2], L2E, c1));
                float e11 = fexp2(fmaf(s4[nf][3], L2E, c1));
                rs0 += e00 + e01; rs1 += e10 + e11;
                p0v[nf] = pack2(e00, e01);
                p1v[nf] = pack2(e10, e11);
            }
            {
                uint32_t base = A_P + r0 * 76 + ni * 32 + q * 8;
                *(uint4*)(smu + base)     = make_uint4(p0v[0], p0v[1], p0v[2], p0v[3]);
                *(uint4*)(smu + base + 4) = make_uint4(p0v[4], p0v[5], p0v[6], p0v[7]);
                uint32_t base1 = A_P + (r0 + 8) * 76 + ni * 32 + q * 8;
                *(uint4*)(smu + base1)     = make_uint4(p1v[0], p1v[1], p1v[2], p1v[3]);
                *(uint4*)(smu + base1 + 4) = make_uint4(p1v[4], p1v[5], p1v[6], p1v[7]);
            }
            rs0 += __shfl_xor_sync(0xffffffffu, rs0, 1);
            rs0 += __shfl_xor_sync(0xffffffffu, rs0, 2);
            rs1 += __shfl_xor_sync(0xffffffffu, rs1, 1);
            rs1 += __shfl_xor_sync(0xffffffffu, rs1, 2);
            if (q == 0) {
                sm[A_SP + ni * 64 + r0] = rs0;
                sm[A_SP + ni * 64 + r0 + 8] = rs1;
            }
#pragma unroll
            for (int nf = 0; nf < 8; nf++) {
                o[nf][0] *= al0; o[nf][1] *= al0;
                o[nf][2] *= al1; o[nf][3] *= al1;
            }
        }
        __syncthreads();     // P visible

        // ---- l update (concurrent with AV-h0)
        if (t < 64) {
            float mo = sm[A_MR + (it & 1) * 64 + t];
            float mn = sm[A_MR + ((it + 1) & 1) * 64 + t];
            sm[A_LR + t] = sm[A_LR + t] * fexp2((mo - mn) * L2E)
                         + sm[A_SP + t] + sm[A_SP + 64 + t];
        }

        // ---- AV half 0 (V0)
        {
            uint4 pa0 = *(const uint4*)(smu + A_P + r0 * 76 + q * 8);
            uint4 pa1 = *(const uint4*)(smu + A_P + r0 * 76 + q * 8 + 4);
            uint4 pb0 = *(const uint4*)(smu + A_P + (r0 + 8) * 76 + q * 8);
            uint4 pb1 = *(const uint4*)(smu + A_P + (r0 + 8) * 76 + q * 8 + 4);
            uint32_t pa[8] = {pa0.x, pa0.y, pa0.z, pa0.w, pa1.x, pa1.y, pa1.z, pa1.w};
            uint32_t pb[8] = {pb0.x, pb0.y, pb0.z, pb0.w, pb1.x, pb1.y, pb1.z, pb1.w};
            uint32_t as_[4][4];
#pragma unroll
            for (int s = 0; s < 4; s++) {
                as_[s][0] = pa[2 * s];     as_[s][1] = pb[2 * s];
                as_[s][2] = pa[2 * s + 1]; as_[s][3] = pb[2 * s + 1];
            }
#pragma unroll
            for (int nf = 0; nf < 8; nf++) {
                int d = ni * 64 + nf * 8 + g;
                uint4 v0 = *(const uint4*)(smu + A_V0 + d * 36 + q * 8);
                uint4 v1 = *(const uint4*)(smu + A_V0 + d * 36 + q * 8 + 4);
                uint32_t vv[8] = {v0.x, v0.y, v0.z, v0.w, v1.x, v1.y, v1.z, v1.w};
#pragma unroll
                for (int s = 0; s < 4; s++)
                    mma16(o[nf], as_[s], vv[2 * s], vv[2 * s + 1]);
            }
        }

        CP_WAIT(0);          // K(it+1), V1(it) landed
        __syncthreads();     // AV-h0 reads of V0 done; V1 visible

        // ---- prefetch V0(it+1) into V0
        if (it < 7) {
            const uint32_t* sv = vpk + (long)vd * 512 + (it + 1) * 64 + hv * 16;
#pragma unroll
            for (int r = 0; r < 4; r++)
                cpa16(smu + A_V0 + vd * 36 + hv * 16 + r * 4, sv + r * 4);
            CP_COMMIT();
        }

        // ---- AV half 1 (V1)
        {
            uint4 pa0 = *(const uint4*)(smu + A_P + r0 * 76 + 32 + q * 8);
            uint4 pa1 = *(const uint4*)(smu + A_P + r0 * 76 + 32 + q * 8 + 4);
            uint4 pb0 = *(const uint4*)(smu + A_P + (r0 + 8) * 76 + 32 + q * 8);
            uint4 pb1 = *(const uint4*)(smu + A_P + (r0 + 8) * 76 + 32 + q * 8 + 4);
            uint32_t pa[8] = {pa0.x, pa0.y, pa0.z, pa0.w, pa1.x, pa1.y, pa1.z, pa1.w};
            uint32_t pb[8] = {pb0.x, pb0.y, pb0.z, pb0.w, pb1.x, pb1.y, pb1.z, pb1.w};
            uint32_t as_[4][4];
#pragma unroll
            for (int s = 0; s < 4; s++) {
                as_[s][0] = pa[2 * s];     as_[s][1] = pb[2 * s];
                as_[s][2] = pa[2 * s + 1]; as_[s][3] = pb[2 * s + 1];
            }
#pragma unroll
            for (int nf = 0; nf < 8; nf++) {
                int d = ni * 64 + nf * 8 + g;
                uint4 v0 = *(const uint4*)(smu + A_V1 + d * 36 + q * 8);
                uint4 v1 = *(const uint4*)(smu + A_V1 + d * 36 + q * 8 + 4);
                uint32_t vv[8] = {v0.x, v0.y, v0.z, v0.w, v1.x, v1.y, v1.z, v1.w};
#pragma unroll
                for (int s = 0; s < 4; s++)
                    mma16(o[nf], as_[s], vv[2 * s], vv[2 * s + 1]);
            }
        }
    }

    // epilogue: normalize, write paired hi/lo [pair][tok]
    __syncthreads();
    {
        float inv0 = 1.0f / sm[A_LR + r0];
        float inv1 = 1.0f / sm[A_LR + r0 + 8];
#pragma unroll
        for (int nf = 0; nf < 8; nf += 2) {
            int gpair = (h * 4 + ni * 2 + (nf >> 2)) * 8 + 4 * ((nf >> 1) & 1) + q;
            long base = ((long)b * 256 + gpair) * NTOK + q0;
            uint32_t hA0, lA0, hB0, lB0;
            uint32_t hA1, lA1, hB1, lB1;
            splitpack(o[nf][0] * inv0,     o[nf][1] * inv0,     hA0, lA0);
            splitpack(o[nf][2] * inv1,     o[nf][3] * inv1,     hB0, lB0);
            splitpack(o[nf + 1][0] * inv0, o[nf + 1][1] * inv0, hA1, lA1);
            splitpack(o[nf + 1][2] * inv1, o[nf + 1][3] * inv1, hB1, lB1);
            g_xx2h[base + r0]     = make_uint2(hA0, hA1);
            g_xx2l[base + r0]     = make_uint2(lA0, lA1);
            g_xx2h[base + r0 + 8] = make_uint2(hB0, hB1);
            g_xx2l[base + r0 + 8] = make_uint2(lB0, lB1);
        }
    }
}

// ---------------------------------------------------------------------------
extern "C" void kernel_launch(void* const* d_in, const int* in_sizes, int n_in,
                              void* d_out, int out_size)
{
    const float* x   = (const float*)d_in[0];
    const float* wq  = (const float*)d_in[1];
    const float* bnq = (const float*)d_in[2];
    const float* wk  = (const float*)d_in[3];
    const float* bnk = (const float*)d_in[4];
    const float* wv  = (const float*)d_in[5];
    const float* bnv = (const float*)d_in[6];
    const float* wp  = (const float*)d_in[7];
    const float* bnp = (const float*)d_in[8];
    float* out = (float*)d_out;

    uint32_t *wqh, *wql, *wkh, *wkl, *wvh, *wvl, *wph, *wpl;
    uint2 *xh2, *xl2, *qp2h, *qp2l, *kp2h, *kp2l;
    float *qs, *ks;
    cudaGetSymbolAddress((void**)&wqh, g_wqh);
    cudaGetSymbolAddress((void**)&wql, g_wql);
    cudaGetSymbolAddress((void**)&wkh, g_wkh);
    cudaGetSymbolAddress((void**)&wkl, g_wkl);
    cudaGetSymbolAddress((void**)&wvh, g_wvh);
    cudaGetSymbolAddress((void**)&wvl, g_wvl);
    cudaGetSymbolAddress((void**)&wph, g_wph);
    cudaGetSymbolAddress((void**)&wpl, g_wpl);
    cudaGetSymbolAddress((void**)&xh2, g_xh2);
    cudaGetSymbolAddress((void**)&xl2, g_xl2);
    cudaGetSymbolAddress((void**)&qp2h, g_qp2h);
    cudaGetSymbolAddress((void**)&qp2l, g_qp2l);
    cudaGetSymbolAddress((void**)&kp2h, g_kp2h);
    cudaGetSymbolAddress((void**)&kp2l, g_kp2l);
    cudaGetSymbolAddress((void**)&qs, g_q);
    cudaGetSymbolAddress((void**)&ks, g_k);

    const int smem_attn = ATTN_SMEM_U32 * 4;   // 75008 B
    cudaFuncSetAttribute(attn_fa, cudaFuncAttributeMaxDynamicSharedMemorySize,
                         smem_attn);
    cudaFuncSetAttribute(gemm_qkv_tc, cudaFuncAttributeMaxDynamicSharedMemorySize,
                         GEMM_SMEM_BYTES);
    cudaFuncSetAttribute(gemm_proj_tc, cudaFuncAttributeMaxDynamicSharedMemorySize,
                         GEMM_SMEM_BYTES);
    dim3 blk(256);

    pack_w<<<192, blk>>>(wq, wqh, wql, NHKD, 192);
    pack_w<<<192, blk>>>(wk, wkh, wkl, NHKD, 192);
    pack_w<<<768, blk>>>(wv, wvh, wvl, DHV,  192);
    pack_w<<<768, blk>>>(wp, wph, wpl, DIM,  512);
    pack_x<<<dim3(384, BB), blk>>>(x, xh2, xl2);

    gemm_qkv_tc<<<dim3(8, 12, BB), blk, GEMM_SMEM_BYTES>>>(bnq, bnk, bnv);

    pack_qk<<<dim3(256, BB), blk>>>(qs, qp2h, qp2l, 5.656854249492380f);
    pack_qk<<<dim3(256, BB), blk>>>(ks, kp2h, kp2l, 1.0f);

    attn_fa<<<dim3(NTOK / 64, BB * NH), blk, smem_attn>>>();
    gemm_proj_tc<<<dim3(8, 3, BB), blk, GEMM_SMEM_BYTES>>>(bnp, out);
}

// round 16
// speedup vs baseline: 7.3066x; 1.0119x over previous
#include <cuda_runtime.h>
#include <cuda_fp16.h>
#include <cstdint>
#include <math.h>

#define BB   16
#define DIM  384
#define NHKD 256
#define DHV  1024
#define NTOK 1024
#define NH   8
#define KDIM 32
#define DV   128

// packed fp16 buffers
__device__ uint2 g_xh2 [BB * 96 * NTOK];
__device__ uint2 g_xl2 [BB * 96 * NTOK];
__device__ uint2 g_xx2h[BB * 256 * NTOK];
__device__ uint2 g_xx2l[BB * 256 * NTOK];
__device__ uint2 g_qp2h[BB * 64 * NTOK], g_qp2l[BB * 64 * NTOK];
__device__ uint2 g_kp2h[BB * 64 * NTOK], g_kp2l[BB * 64 * NTOK];
__device__ uint32_t g_vp [BB * 1024 * 512];
// weights packed [m][kpair]
__device__ uint32_t g_wqh[256 * 192],  g_wql[256 * 192];
__device__ uint32_t g_wkh[256 * 192],  g_wkl[256 * 192];
__device__ uint32_t g_wvh[1024 * 192], g_wvl[1024 * 192];
__device__ uint32_t g_wph[384 * 512],  g_wpl[384 * 512];

__device__ __forceinline__ void mma16(float c[4], const uint32_t a[4],
                                      uint32_t b0, uint32_t b1) {
    asm volatile("mma.sync.aligned.m16n8k16.row.col.f32.f16.f16.f32 "
        "{%0,%1,%2,%3}, {%4,%5,%6,%7}, {%8,%9}, {%0,%1,%2,%3};"
        : "+f"(c[0]), "+f"(c[1]), "+f"(c[2]), "+f"(c[3])
        : "r"(a[0]), "r"(a[1]), "r"(a[2]), "r"(a[3]), "r"(b0), "r"(b1));
}
__device__ __forceinline__ void ldsm4(uint32_t r[4], const uint32_t* p) {
    uint32_t a = (uint32_t)__cvta_generic_to_shared(p);
    asm volatile("ldmatrix.sync.aligned.m8n8.x4.shared.b16 {%0,%1,%2,%3}, [%4];"
        : "=r"(r[0]), "=r"(r[1]), "=r"(r[2]), "=r"(r[3]) : "r"(a));
}
__device__ __forceinline__ void cpa16(void* dst, const void* src) {
    uint32_t a = (uint32_t)__cvta_generic_to_shared(dst);
    asm volatile("cp.async.cg.shared.global [%0], [%1], 16;" :: "r"(a), "l"(src));
}
#define CP_COMMIT() asm volatile("cp.async.commit_group;" ::: "memory")
#define CP_WAIT(n)  asm volatile("cp.async.wait_group %0;" :: "n"(n) : "memory")

__device__ __forceinline__ uint32_t pack2(float x0, float x1) {
    __half2 h = __floats2half2_rn(x0, x1);
    return *(uint32_t*)&h;
}
__device__ __forceinline__ void splitpack(float x0, float x1,
                                          uint32_t& h, uint32_t& l) {
    __half2 hh = __floats2half2_rn(x0, x1);
    float2 bk = __half22float2(hh);
    __half2 ll = __floats2half2_rn(x0 - bk.x, x1 - bk.y);
    h = *(uint32_t*)&hh;
    l = *(uint32_t*)&ll;
}
// deg-5 (accurate, for alpha / l)
__device__ __forceinline__ float fexp2(float z) {
    z = fmaxf(z, -100.0f);
    float zi = z + 12582912.0f;
    int   n  = __float_as_int(zi) - 0x4B400000;
    float t  = z - (zi - 12582912.0f);
    float p = fmaf(0.0013333558f, t, 0.0096181291f);
    p = fmaf(p, t, 0.0555041087f);
    p = fmaf(p, t, 0.2402265069f);
    p = fmaf(p, t, 0.6931471806f);
    p = fmaf(p, t, 1.0f);
    return __int_as_float(__float_as_int(p) + (n << 23));
}
// deg-4 (err ~4e-5, enough for fp16 P)
__device__ __forceinline__ float fexp2p(float z) {
    z = fmaxf(z, -100.0f);
    float zi = z + 12582912.0f;
    int   n  = __float_as_int(zi) - 0x4B400000;
    float t  = z - (zi - 12582912.0f);
    float p = fmaf(0.0096303680f, t, 0.0555046265f);
    p = fmaf(p, t, 0.2402264696f);
    p = fmaf(p, t, 0.6931471434f);
    p = fmaf(p, t, 1.0f);
    return __int_as_float(__float_as_int(p) + (n << 23));
}

// ---------------- prep kernels ----------------------------------------------
__global__ __launch_bounds__(256) void pack_w(
    const float* __restrict__ W, uint32_t* __restrict__ H,
    uint32_t* __restrict__ L, int M, int Kp)
{
    int idx = blockIdx.x * 256 + threadIdx.x;
    int m = idx / Kp, p = idx - m * Kp;
    float a = W[(long)m * (2 * Kp) + 2 * p];
    float b = W[(long)m * (2 * Kp) + 2 * p + 1];
    uint32_t hh, ll;
    splitpack(a, b, hh, ll);
    H[idx] = hh; L[idx] = ll;
}
__global__ __launch_bounds__(256) void pack_x(
    const float* __restrict__ X, uint2* __restrict__ H2,
    uint2* __restrict__ L2)
{
    int idx = blockIdx.x * 256 + threadIdx.x;
    int b = blockIdx.y;
    int gp = idx >> 10, n = idx & 1023;
    int c = gp >> 3, j = gp & 7, s = j >> 2, qq = j & 3;
    int k0 = 2 * (c * 16 + 8 * s + qq);
    const float* src = X + ((long)b * DIM + k0) * NTOK + n;
    uint32_t h0, l0, h1, l1;
    splitpack(src[0], src[NTOK], h0, l0);
    splitpack(src[8 * NTOK], src[9 * NTOK], h1, l1);
    long dst = ((long)b * 96 + gp) * NTOK + n;
    H2[dst] = make_uint2(h0, h1);
    L2[dst] = make_uint2(l0, l1);
}

// ============ fp16 3x-split GEMM + BN, cp.async 2-stage double buffer =======
// MODE 0: float output; MODE 1: V packed permuted; MODE 2: Q/K paired packed.
#define SW_H 0
#define SW_L 2560
#define SB_H 5120
#define SB_L 7232
#define GEMM_BUF_U32 9344
#define GEMM_SMEM_BYTES (2 * GEMM_BUF_U32 * 4)

template <int MODE>
__device__ __forceinline__ void gemm16_body(
    const uint32_t* __restrict__ WH, const uint32_t* __restrict__ WL,
    const uint2* __restrict__ XH2, const uint2* __restrict__ XL2,
    const float* __restrict__ bn, float* __restrict__ Yb,
    uint32_t* __restrict__ Vout, uint2* __restrict__ QHo,
    uint2* __restrict__ QLo, float qscale,
    int M, int Kp, int m0, int n0, uint32_t* smu)
{
    const int t = threadIdx.x, lane = t & 31, w = t >> 5;
    const int g = lane >> 2, q = lane & 3;
    const int mw = (w >> 2) * 64, nw = (w & 3) * 32;
    const int lrow = lane & 15, lsel = (lane >> 4) * 4;
    const int wrow = t >> 2, wquad = t & 3;
    const int pr = t >> 5, cq = t & 31;

    float c[4][4][4];
#pragma unroll
    for (int i = 0; i < 4; i++)
#pragma unroll
        for (int j = 0; j < 4; j++)
#pragma unroll
            for (int r = 0; r < 4; r++) c[i][j][r] = 0.f;

    const int nc = Kp >> 4;
    {
        uint32_t* base = smu;
#pragma unroll
        for (int i = 0; i < 2; i++) {
            int row = wrow + i * 64;
            cpa16(base + SW_H + row * 20 + wquad * 4,
                  WH + (long)(m0 + row) * Kp + wquad * 4);
            cpa16(base + SW_L + row * 20 + wquad * 4,
                  WL + (long)(m0 + row) * Kp + wquad * 4);
            int c2 = (cq + 32 * i) * 2;
            cpa16(base + SB_H + (pr * 132 + c2) * 2,
                  XH2 + (long)pr * NTOK + n0 + c2);
            cpa16(base + SB_L + (pr * 132 + c2) * 2,
                  XL2 + (long)pr * NTOK + n0 + c2);
        }
        CP_COMMIT();
    }

    for (int ch = 0; ch < nc; ch++) {
        if (ch + 1 < nc) {
            uint32_t* base = smu + ((ch + 1) & 1) * GEMM_BUF_U32;
            const int pc = (ch + 1) * 16, pg = (ch + 1) * 8;
#pragma unroll
            for (int i = 0; i < 2; i++) {
                int row = wrow + i * 64;
                cpa16(base + SW_H + row * 20 + wquad * 4,
                      WH + (long)(m0 + row) * Kp + pc + wquad * 4);
                cpa16(base + SW_L + row * 20 + wquad * 4,
                      WL + (long)(m0 + row) * Kp + pc + wquad * 4);
                int c2 = (cq + 32 * i) * 2;
                cpa16(base + SB_H + (pr * 132 + c2) * 2,
                      XH2 + (long)(pg + pr) * NTOK + n0 + c2);
                cpa16(base + SB_L + (pr * 132 + c2) * 2,
                      XL2 + (long)(pg + pr) * NTOK + n0 + c2);
            }
            CP_COMMIT();
            CP_WAIT(1);
        } else {
            CP_WAIT(0);
        }
        __syncthreads();

        uint32_t* base = smu + (ch & 1) * GEMM_BUF_U32;
        uint2* smBH = (uint2*)(base + SB_H);
        uint2* smBL = (uint2*)(base + SB_L);
#pragma unroll
        for (int ks = 0; ks < 2; ks++) {
            uint32_t ah[4][4], al[4][4];
#pragma unroll
            for (int mf = 0; mf < 4; mf++) {
                int ra = (mw + mf * 16 + lrow) * 20 + ks * 8 + lsel;
                ldsm4(ah[mf], base + SW_H + ra);
                ldsm4(al[mf], base + SW_L + ra);
            }
#pragma unroll
            for (int nf = 0; nf < 4; nf++) {
                int coln = nw + nf * 8 + g;
                uint2 bh = smBH[(4 * ks + q) * 132 + coln];
                uint2 bl = smBL[(4 * ks + q) * 132 + coln];
#pragma unroll
                for (int mf = 0; mf < 4; mf++) {
                    mma16(c[mf][nf], ah[mf], bh.x, bh.y);
                    mma16(c[mf][nf], ah[mf], bl.x, bl.y);
                    mma16(c[mf][nf], al[mf], bh.x, bh.y);
                }
            }
        }
        __syncthreads();
    }

#pragma unroll
    for (int mf = 0; mf < 4; mf++) {
        int r0 = m0 + mw + mf * 16 + g;
        int r1 = r0 + 8;
        float sc0 = bn[r0] * rsqrtf(bn[3 * M + r0] + 1e-5f);
        float tt0 = bn[M + r0] - bn[2 * M + r0] * sc0;
        float sc1 = bn[r1] * rsqrtf(bn[3 * M + r1] + 1e-5f);
        float tt1 = bn[M + r1] - bn[2 * M + r1] * sc1;
        if (MODE == 1) {
            uint32_t a0[4], a1[4];
#pragma unroll
            for (int nf = 0; nf < 4; nf++) {
                a0[nf] = pack2(c[mf][nf][0] * sc0 + tt0, c[mf][nf][1] * sc0 + tt0);
                a1[nf] = pack2(c[mf][nf][2] * sc1 + tt1, c[mf][nf][3] * sc1 + tt1);
            }
            int slot = (n0 >> 1) + ((nw & 64) ? 32 : 0) + q * 8 + ((nw & 32) >> 3);
            *(uint4*)(Vout + (long)r0 * 512 + slot) = make_uint4(a0[0], a0[1], a0[2], a0[3]);
            *(uint4*)(Vout + (long)r1 * 512 + slot) = make_uint4(a1[0], a1[1], a1[2], a1[3]);
        } else if (MODE == 2) {
            // paired Q/K pack: channel pairs (r0,r0+1)->x, (r0+8,r0+9)->y
            float s0 = sc0 * qscale, t0 = tt0 * qscale;
            float s1 = sc1 * qscale, t1 = tt1 * qscale;
            int gp = (r0 >> 5) * 8 + 4 * ((r0 >> 4) & 1) + (g >> 1);
#pragma unroll
            for (int nf = 0; nf < 4; nf++) {
                float v0 = c[mf][nf][0] * s0 + t0;
                float v1 = c[mf][nf][1] * s0 + t0;
                float v2 = c[mf][nf][2] * s1 + t1;
                float v3 = c[mf][nf][3] * s1 + t1;
                float n0v = __shfl_down_sync(0xffffffffu, v0, 4);
                float n1v = __shfl_down_sync(0xffffffffu, v1, 4);
                float n2v = __shfl_down_sync(0xffffffffu, v2, 4);
                float n3v = __shfl_down_sync(0xffffffffu, v3, 4);
                if ((lane & 4) == 0) {
                    int nn = n0 + nw + nf * 8 + 2 * q;
                    long basep = (long)gp * NTOK + nn;
                    uint32_t hx, lx, hy, ly;
                    splitpack(v0, n0v, hx, lx);
                    splitpack(v2, n2v, hy, ly);
                    QHo[basep] = make_uint2(hx, hy);
                    QLo[basep] = make_uint2(lx, ly);
                    splitpack(v1, n1v, hx, lx);
                    splitpack(v3, n3v, hy, ly);
                    QHo[basep + 1] = make_uint2(hx, hy);
                    QLo[basep + 1] = make_uint2(lx, ly);
                }
            }
        } else {
#pragma unroll
            for (int nf = 0; nf < 4; nf++) {
                int nn = n0 + nw + nf * 8 + 2 * q;
                float2 v0, v1;
                v0.x = c[mf][nf][0] * sc0 + tt0;
                v0.y = c[mf][nf][1] * sc0 + tt0;
                v1.x = c[mf][nf][2] * sc1 + tt1;
                v1.y = c[mf][nf][3] * sc1 + tt1;
                *(float2*)(Yb + (long)r0 * NTOK + nn) = v0;
                *(float2*)(Yb + (long)r1 * NTOK + nn) = v1;
            }
        }
    }
}

__global__ __launch_bounds__(256, 2) void gemm_qkv_tc(
    const float* __restrict__ bnq, const float* __restrict__ bnk,
    const float* __restrict__ bnv)
{
    extern __shared__ uint32_t smu[];
    const int y = blockIdx.y, b = blockIdx.z;
    const uint2* XH = g_xh2 + (long)b * 96 * NTOK;
    const uint2* XL = g_xl2 + (long)b * 96 * NTOK;
    if (y < 2) {
        gemm16_body<2>(g_wqh, g_wql, XH, XL, bnq, nullptr, nullptr,
                       g_qp2h + (long)b * 64 * NTOK, g_qp2l + (long)b * 64 * NTOK,
                       5.656854249492380f,
                       NHKD, 192, y * 128, blockIdx.x * 128, smu);
    } else if (y < 4) {
        gemm16_body<2>(g_wkh, g_wkl, XH, XL, bnk, nullptr, nullptr,
                       g_kp2h + (long)b * 64 * NTOK, g_kp2l + (long)b * 64 * NTOK,
                       1.0f,
                       NHKD, 192, (y - 2) * 128, blockIdx.x * 128, smu);
    } else {
        gemm16_body<1>(g_wvh, g_wvl, XH, XL, bnv, nullptr,
                       g_vp + (long)b * 1024 * 512, nullptr, nullptr, 1.0f,
                       DHV, 192, (y - 4) * 128, blockIdx.x * 128, smu);
    }
}

__global__ __launch_bounds__(256, 2) void gemm_proj_tc(
    const float* __restrict__ bnp, float* __restrict__ out)
{
    extern __shared__ uint32_t smu[];
    const int b = blockIdx.z;
    gemm16_body<0>(g_wph, g_wpl,
                   g_xx2h + (long)b * 256 * NTOK, g_xx2l + (long)b * 256 * NTOK,
                   bnp, out + (long)b * DIM * NTOK, nullptr, nullptr, nullptr,
                   1.0f, DIM, 512, blockIdx.y * 128, blockIdx.x * 128, smu);
}

// ---------------- FA2 attention, cp.async rotating prefetch -----------------
#define A_KH 0        // uint2 [8][132]
#define A_KL 2112
#define A_V0 4224     // u32 [128][36]
#define A_V1 8832
#define A_P  13440    // u32 [64][76]
#define A_MP 18304
#define A_SP 18432
#define A_MR 18560
#define A_LR 18688
#define ATTN_SMEM_U32 18752   // 75008 B

__global__ __launch_bounds__(256, 2) void attn_fa()
{
    extern __shared__ float sm[];
    uint32_t* smu = (uint32_t*)sm;
    uint2* smKH = (uint2*)(smu + A_KH);
    uint2* smKL = (uint2*)(smu + A_KL);
    const int t = threadIdx.x, lane = t & 31, w = t >> 5;
    const int mi = w >> 1, ni = w & 1;
    const int g = lane >> 2, q = lane & 3;
    const int q0 = blockIdx.x * 64;
    const int b = blockIdx.y >> 3, h = blockIdx.y & 7;
    const float L2E = 1.44269504088896f;

    const uint2* qp2h = g_qp2h + ((long)b * 64 + h * 8) * NTOK + q0;
    const uint2* qp2l = g_qp2l + ((long)b * 64 + h * 8) * NTOK + q0;
    const uint2* kp2h = g_kp2h + ((long)b * 64 + h * 8) * NTOK;
    const uint2* kp2l = g_kp2l + ((long)b * 64 + h * 8) * NTOK;
    const uint32_t* vpk = g_vp + ((long)b * 1024 + h * 128) * 512;

    const int pr = t >> 5, cq = t & 31;
    const int vd = t >> 1, hv = t & 1;

    if (t < 64) { sm[A_MR + t] = -1e30f; sm[A_MR + 64 + t] = -1e30f; sm[A_LR + t] = 0.f; }

    {
        long srow = (long)pr * NTOK;
#pragma unroll
        for (int i = 0; i < 2; i++) {
            int c2 = (cq + 32 * i) * 2;
            cpa16(smu + A_KH + (pr * 132 + c2) * 2, kp2h + srow + c2);
            cpa16(smu + A_KL + (pr * 132 + c2) * 2, kp2l + srow + c2);
        }
        const uint32_t* sv = vpk + (long)vd * 512 + hv * 16;
#pragma unroll
        for (int r = 0; r < 4; r++)
            cpa16(smu + A_V0 + vd * 36 + hv * 16 + r * 4, sv + r * 4);
        CP_COMMIT();
    }

    const int r0 = mi * 16 + g;
    uint32_t qh[2][4], ql[2][4];
#pragma unroll
    for (int s = 0; s < 2; s++) {
        long pi = (long)(4 * s + q) * NTOK;
        uint2 h0 = qp2h[pi + r0],  h1 = qp2h[pi + r0 + 8];
        uint2 l0 = qp2l[pi + r0],  l1 = qp2l[pi + r0 + 8];
        qh[s][0] = h0.x; qh[s][1] = h1.x; qh[s][2] = h0.y; qh[s][3] = h1.y;
        ql[s][0] = l0.x; ql[s][1] = l1.x; ql[s][2] = l0.y; ql[s][3] = l1.y;
    }

    float o[8][4];
#pragma unroll
    for (int nf = 0; nf < 8; nf++)
#pragma unroll
        for (int j = 0; j < 4; j++) o[nf][j] = 0.f;

    for (int it = 0; it < 8; it++) {
        CP_WAIT(0);
        __syncthreads();

        float s4[8][4];
#pragma unroll
        for (int nf = 0; nf < 8; nf++)
#pragma unroll
            for (int j = 0; j < 4; j++) s4[nf][j] = 0.f;
#pragma unroll
        for (int s = 0; s < 2; s++) {
#pragma unroll
            for (int nf = 0; nf < 8; nf++) {
                int col = ni * 64 + nf * 8 + g;
                uint2 bh = smKH[(4 * s + q) * 132 + col];
                uint2 bl = smKL[(4 * s + q) * 132 + col];
                mma16(s4[nf], qh[s], bh.x, bh.y);
                mma16(s4[nf], qh[s], bl.x, bl.y);
                mma16(s4[nf], ql[s], bh.x, bh.y);
            }
        }

        {
            float m0 = fmaxf(s4[0][0], s4[0][1]);
            float m1 = fmaxf(s4[0][2], s4[0][3]);
#pragma unroll
            for (int nf = 1; nf < 8; nf++) {
                m0 = fmaxf(m0, fmaxf(s4[nf][0], s4[nf][1]));
                m1 = fmaxf(m1, fmaxf(s4[nf][2], s4[nf][3]));
            }
            m0 = fmaxf(m0, __shfl_xor_sync(0xffffffffu, m0, 1));
            m0 = fmaxf(m0, __shfl_xor_sync(0xffffffffu, m0, 2));
            m1 = fmaxf(m1, __shfl_xor_sync(0xffffffffu, m1, 1));
            m1 = fmaxf(m1, __shfl_xor_sync(0xffffffffu, m1, 2));
            if (q == 0) {
                sm[A_MP + ni * 64 + r0] = m0;
                sm[A_MP + ni * 64 + r0 + 8] = m1;
            }
        }
        __syncthreads();

        {
            if (it < 7) {
                long srow = (long)pr * NTOK + (it + 1) * 128;
#pragma unroll
                for (int i = 0; i < 2; i++) {
                    int c2 = (cq + 32 * i) * 2;
                    cpa16(smu + A_KH + (pr * 132 + c2) * 2, kp2h + srow + c2);
                    cpa16(smu + A_KL + (pr * 132 + c2) * 2, kp2l + srow + c2);
                }
            }
            const uint32_t* sv = vpk + (long)vd * 512 + it * 64 + 32 + hv * 16;
#pragma unroll
            for (int r = 0; r < 4; r++)
                cpa16(smu + A_V1 + vd * 36 + hv * 16 + r * 4, sv + r * 4);
            CP_COMMIT();
        }

        {
            float moA = sm[A_MR + (it & 1) * 64 + r0];
            float moB = sm[A_MR + (it & 1) * 64 + r0 + 8];
            float mn0 = fmaxf(moA, fmaxf(sm[A_MP + r0], sm[A_MP + 64 + r0]));
            float mn1 = fmaxf(moB, fmaxf(sm[A_MP + r0 + 8], sm[A_MP + 64 + r0 + 8]));
            if (ni == 0 && q == 0) {
                sm[A_MR + ((it + 1) & 1) * 64 + r0] = mn0;
                sm[A_MR + ((it + 1) & 1) * 64 + r0 + 8] = mn1;
            }
            float al0 = fexp2((moA - mn0) * L2E);
            float al1 = fexp2((moB - mn1) * L2E);
            float c0 = -mn0 * L2E, c1 = -mn1 * L2E;
            float rs0 = 0.f, rs1 = 0.f;
            uint32_t p0v[8], p1v[8];
#pragma unroll
            for (int nf = 0; nf < 8; nf++) {
                float e00 = fexp2p(fmaf(s4[nf][0], L2E, c0));
                float e01 = fexp2p(fmaf(s4[nf][1], L2E, c0));
                float e10 = fexp2p(fmaf(s4[nf][2], L2E, c1));
                float e11 = fexp2p(fmaf(s4[nf][3], L2E, c1));
                rs0 += e00 + e01; rs1 += e10 + e11;
                p0v[nf] = pack2(e00, e01);
                p1v[nf] = pack2(e10, e11);
            }
            {
                uint32_t base = A_P + r0 * 76 + ni * 32 + q * 8;
                *(uint4*)(smu + base)     = make_uint4(p0v[0], p0v[1], p0v[2], p0v[3]);
                *(uint4*)(smu + base + 4) = make_uint4(p0v[4], p0v[5], p0v[6], p0v[7]);
                uint32_t base1 = A_P + (r0 + 8) * 76 + ni * 32 + q * 8;
                *(uint4*)(smu + base1)     = make_uint4(p1v[0], p1v[1], p1v[2], p1v[3]);
                *(uint4*)(smu + base1 + 4) = make_uint4(p1v[4], p1v[5], p1v[6], p1v[7]);
            }
            rs0 += __shfl_xor_sync(0xffffffffu, rs0, 1);
            rs0 += __shfl_xor_sync(0xffffffffu, rs0, 2);
            rs1 += __shfl_xor_sync(0xffffffffu, rs1, 1);
            rs1 += __shfl_xor_sync(0xffffffffu, rs1, 2);
            if (q == 0) {
                sm[A_SP + ni * 64 + r0] = rs0;
                sm[A_SP + ni * 64 + r0 + 8] = rs1;
            }
#pragma unroll
            for (int nf = 0; nf < 8; nf++) {
                o[nf][0] *= al0; o[nf][1] *= al0;
                o[nf][2] *= al1; o[nf][3] *= al1;
            }
        }
        __syncthreads();

        if (t < 64) {
            float mo = sm[A_MR + (it & 1) * 64 + t];
            float mn = sm[A_MR + ((it + 1) & 1) * 64 + t];
            sm[A_LR + t] = sm[A_LR + t] * fexp2((mo - mn) * L2E)
                         + sm[A_SP + t] + sm[A_SP + 64 + t];
        }

        {
            uint4 pa0 = *(const uint4*)(smu + A_P + r0 * 76 + q * 8);
            uint4 pa1 = *(const uint4*)(smu + A_P + r0 * 76 + q * 8 + 4);
            uint4 pb0 = *(const uint4*)(smu + A_P + (r0 + 8) * 76 + q * 8);
            uint4 pb1 = *(const uint4*)(smu + A_P + (r0 + 8) * 76 + q * 8 + 4);
            uint32_t pa[8] = {pa0.x, pa0.y, pa0.z, pa0.w, pa1.x, pa1.y, pa1.z, pa1.w};
            uint32_t pb[8] = {pb0.x, pb0.y, pb0.z, pb0.w, pb1.x, pb1.y, pb1.z, pb1.w};
            uint32_t as_[4][4];
#pragma unroll
            for (int s = 0; s < 4; s++) {
                as_[s][0] = pa[2 * s];     as_[s][1] = pb[2 * s];
                as_[s][2] = pa[2 * s + 1]; as_[s][3] = pb[2 * s + 1];
            }
#pragma unroll
            for (int nf = 0; nf < 8; nf++) {
                int d = ni * 64 + nf * 8 + g;
                uint4 v0 = *(const uint4*)(smu + A_V0 + d * 36 + q * 8);
                uint4 v1 = *(const uint4*)(smu + A_V0 + d * 36 + q * 8 + 4);
                uint32_t vv[8] = {v0.x, v0.y, v0.z, v0.w, v1.x, v1.y, v1.z, v1.w};
#pragma unroll
                for (int s = 0; s < 4; s++)
                    mma16(o[nf], as_[s], vv[2 * s], vv[2 * s + 1]);
            }
        }

        CP_WAIT(0);
        __syncthreads();

        if (it < 7) {
            const uint32_t* sv = vpk + (long)vd * 512 + (it + 1) * 64 + hv * 16;
#pragma unroll
            for (int r = 0; r < 4; r++)
                cpa16(smu + A_V0 + vd * 36 + hv * 16 + r * 4, sv + r * 4);
            CP_COMMIT();
        }

        {
            uint4 pa0 = *(const uint4*)(smu + A_P + r0 * 76 + 32 + q * 8);
            uint4 pa1 = *(const uint4*)(smu + A_P + r0 * 76 + 32 + q * 8 + 4);
            uint4 pb0 = *(const uint4*)(smu + A_P + (r0 + 8) * 76 + 32 + q * 8);
            uint4 pb1 = *(const uint4*)(smu + A_P + (r0 + 8) * 76 + 32 + q * 8 + 4);
            uint32_t pa[8] = {pa0.x, pa0.y, pa0.z, pa0.w, pa1.x, pa1.y, pa1.z, pa1.w};
            uint32_t pb[8] = {pb0.x, pb0.y, pb0.z, pb0.w, pb1.x, pb1.y, pb1.z, pb1.w};
            uint32_t as_[4][4];
#pragma unroll
            for (int s = 0; s < 4; s++) {
                as_[s][0] = pa[2 * s];     as_[s][1] = pb[2 * s];
                as_[s][2] = pa[2 * s + 1]; as_[s][3] = pb[2 * s + 1];
            }
#pragma unroll
            for (int nf = 0; nf < 8; nf++) {
                int d = ni * 64 + nf * 8 + g;
                uint4 v0 = *(const uint4*)(smu + A_V1 + d * 36 + q * 8);
                uint4 v1 = *(const uint4*)(smu + A_V1 + d * 36 + q * 8 + 4);
                uint32_t vv[8] = {v0.x, v0.y, v0.z, v0.w, v1.x, v1.y, v1.z, v1.w};
#pragma unroll
                for (int s = 0; s < 4; s++)
                    mma16(o[nf], as_[s], vv[2 * s], vv[2 * s + 1]);
            }
        }
    }

    __syncthreads();
    {
        float inv0 = 1.0f / sm[A_LR + r0];
        float inv1 = 1.0f / sm[A_LR + r0 + 8];
#pragma unroll
        for (int nf = 0; nf < 8; nf += 2) {
            int gpair = (h * 4 + ni * 2 + (nf >> 2)) * 8 + 4 * ((nf >> 1) & 1) + q;
            long base = ((long)b * 256 + gpair) * NTOK + q0;
            uint32_t hA0, lA0, hB0, lB0;
            uint32_t hA1, lA1, hB1, lB1;
            splitpack(o[nf][0] * inv0,     o[nf][1] * inv0,     hA0, lA0);
            splitpack(o[nf][2] * inv1,     o[nf][3] * inv1,     hB0, lB0);
            splitpack(o[nf + 1][0] * inv0, o[nf + 1][1] * inv0, hA1, lA1);
            splitpack(o[nf + 1][2] * inv1, o[nf + 1][3] * inv1, hB1, lB1);
            g_xx2h[base + r0]     = make_uint2(hA0, hA1);
            g_xx2l[base + r0]     = make_uint2(lA0, lA1);
            g_xx2h[base + r0 + 8] = make_uint2(hB0, hB1);
            g_xx2l[base + r0 + 8] = make_uint2(lB0, lB1);
        }
    }
}

// ---------------------------------------------------------------------------
extern "C" void kernel_launch(void* const* d_in, const int* in_sizes, int n_in,
                              void* d_out, int out_size)
{
    const float* x   = (const float*)d_in[0];
    const float* wq  = (const float*)d_in[1];
    const float* bnq = (const float*)d_in[2];
    const float* wk  = (const float*)d_in[3];
    const float* bnk = (const float*)d_in[4];
    const float* wv  = (const float*)d_in[5];
    const float* bnv = (const float*)d_in[6];
    const float* wp  = (const float*)d_in[7];
    const float* bnp = (const float*)d_in[8];
    float* out = (float*)d_out;

    uint32_t *wqh, *wql, *wkh, *wkl, *wvh, *wvl, *wph, *wpl;
    uint2 *xh2, *xl2;
    cudaGetSymbolAddress((void**)&wqh, g_wqh);
    cudaGetSymbolAddress((void**)&wql, g_wql);
    cudaGetSymbolAddress((void**)&wkh, g_wkh);
    cudaGetSymbolAddress((void**)&wkl, g_wkl);
    cudaGetSymbolAddress((void**)&wvh, g_wvh);
    cudaGetSymbolAddress((void**)&wvl, g_wvl);
    cudaGetSymbolAddress((void**)&wph, g_wph);
    cudaGetSymbolAddress((void**)&wpl, g_wpl);
    cudaGetSymbolAddress((void**)&xh2, g_xh2);
    cudaGetSymbolAddress((void**)&xl2, g_xl2);

    const int smem_attn = ATTN_SMEM_U32 * 4;   // 75008 B
    cudaFuncSetAttribute(attn_fa, cudaFuncAttributeMaxDynamicSharedMemorySize,
                         smem_attn);
    cudaFuncSetAttribute(gemm_qkv_tc, cudaFuncAttributeMaxDynamicSharedMemorySize,
                         GEMM_SMEM_BYTES);
    cudaFuncSetAttribute(gemm_proj_tc, cudaFuncAttributeMaxDynamicSharedMemorySize,
                         GEMM_SMEM_BYTES);
    dim3 blk(256);

    pack_w<<<192, blk>>>(wq, wqh, wql, NHKD, 192);
    pack_w<<<192, blk>>>(wk, wkh, wkl, NHKD, 192);
    pack_w<<<768, blk>>>(wv, wvh, wvl, DHV,  192);
    pack_w<<<768, blk>>>(wp, wph, wpl, DIM,  512);
    pack_x<<<dim3(384, BB), blk>>>(x, xh2, xl2);

    gemm_qkv_tc<<<dim3(8, 12, BB), blk, GEMM_SMEM_BYTES>>>(bnq, bnk, bnv);
    attn_fa<<<dim3(NTOK / 64, BB * NH), blk, smem_attn>>>();
    gemm_proj_tc<<<dim3(8, 3, BB), blk, GEMM_SMEM_BYTES>>>(bnp, out);
}